// round 1
// baseline (speedup 1.0000x reference)
#include <cuda_runtime.h>
#include <cstddef>

// ---------------------------------------------------------------------------
// MultiModalClassifier: B=8192, D=1024, H=4 (hd=256), C=4
//
// Key algebraic simplifications:
//  * self-attention has 1 key -> softmax == 1 -> self_out = (X @ Wv_s^T + bv_s) @ Wo_s^T + bo_s
//  * cross keys: K_ij = Kc_i - Kc_j + bk_c with Kc = X @ Wk_c^T (no bias),
//    likewise V_ij = Vc_i - Vc_j + bv_c.
//  * all 4 inputs stacked -> 6 big GEMMs (M=32768, N=K=1024) + combine + logits.
// ---------------------------------------------------------------------------

#define NB 8192
#define DD 1024
#define MTOT (4 * NB)            // 32768 stacked rows
#define HD 256                   // head dim
#define NH 4

// Static scratch (allocation-free rule): 6 x 128 MB
__device__ float g_X  [(size_t)MTOT * DD];
__device__ float g_Q  [(size_t)MTOT * DD];
__device__ float g_Kc [(size_t)MTOT * DD];
__device__ float g_Vc [(size_t)MTOT * DD];
__device__ float g_Vs [(size_t)MTOT * DD];
__device__ float g_ctx[(size_t)MTOT * DD];

// ---------------------------------------------------------------------------
// SGEMM (NT): C[M,N] = A[M,K] @ W[N,K]^T (+ A2 @ W2^T) + bias (+ bias2)
// 128x128 block tile, 8x8 per thread (split 2x2 of 4x4), BK=8, 256 threads.
// ---------------------------------------------------------------------------
#define BM 128
#define BN 128
#define BK 8

__global__ __launch_bounds__(256, 2) void sgemm_nt(
    const float* __restrict__ A,  const float* __restrict__ W,  const float* __restrict__ bias,
    const float* __restrict__ A2, const float* __restrict__ W2, const float* __restrict__ bias2,
    float* __restrict__ C, int M, int N, int K)
{
    __shared__ float As[BK][BM];
    __shared__ float Bs[BK][BN];

    const int tid  = threadIdx.x;
    const int brow = blockIdx.y * BM;
    const int bcol = blockIdx.x * BN;

    const int lrow = tid >> 1;        // 0..127
    const int lk4  = (tid & 1) * 4;   // 0 or 4

    const int tx = tid & 15;          // 0..15
    const int ty = tid >> 4;          // 0..15

    float acc[8][8];
    #pragma unroll
    for (int i = 0; i < 8; i++)
        #pragma unroll
        for (int j = 0; j < 8; j++) acc[i][j] = 0.f;

    const int npass = (A2 != nullptr) ? 2 : 1;
    for (int pass = 0; pass < npass; ++pass) {
        const float* Ap = pass ? A2 : A;
        const float* Wp = pass ? W2 : W;
        for (int kt = 0; kt < K; kt += BK) {
            float4 av = *(const float4*)&Ap[(size_t)(brow + lrow) * K + kt + lk4];
            float4 bv = *(const float4*)&Wp[(size_t)(bcol + lrow) * K + kt + lk4];
            __syncthreads();
            As[lk4 + 0][lrow] = av.x; As[lk4 + 1][lrow] = av.y;
            As[lk4 + 2][lrow] = av.z; As[lk4 + 3][lrow] = av.w;
            Bs[lk4 + 0][lrow] = bv.x; Bs[lk4 + 1][lrow] = bv.y;
            Bs[lk4 + 2][lrow] = bv.z; Bs[lk4 + 3][lrow] = bv.w;
            __syncthreads();
            #pragma unroll
            for (int k = 0; k < BK; k++) {
                float a[8], b[8];
                *(float4*)&a[0] = *(const float4*)&As[k][ty * 4];
                *(float4*)&a[4] = *(const float4*)&As[k][64 + ty * 4];
                *(float4*)&b[0] = *(const float4*)&Bs[k][tx * 4];
                *(float4*)&b[4] = *(const float4*)&Bs[k][64 + tx * 4];
                #pragma unroll
                for (int i = 0; i < 8; i++)
                    #pragma unroll
                    for (int j = 0; j < 8; j++)
                        acc[i][j] = fmaf(a[i], b[j], acc[i][j]);
            }
        }
    }

    // epilogue: bias + store
    float bsum[8];
    #pragma unroll
    for (int j = 0; j < 8; j++) {
        int col = bcol + ((j < 4) ? (tx * 4 + j) : (64 + tx * 4 + (j - 4)));
        float v = 0.f;
        if (bias)  v += bias[col];
        if (bias2) v += bias2[col];
        bsum[j] = v;
    }
    #pragma unroll
    for (int i = 0; i < 8; i++) {
        int row = brow + ((i < 4) ? (ty * 4 + i) : (64 + ty * 4 + (i - 4)));
        float4 o0, o1;
        o0.x = acc[i][0] + bsum[0]; o0.y = acc[i][1] + bsum[1];
        o0.z = acc[i][2] + bsum[2]; o0.w = acc[i][3] + bsum[3];
        o1.x = acc[i][4] + bsum[4]; o1.y = acc[i][5] + bsum[5];
        o1.z = acc[i][6] + bsum[6]; o1.w = acc[i][7] + bsum[7];
        *(float4*)&C[(size_t)row * N + bcol + tx * 4]      = o0;
        *(float4*)&C[(size_t)row * N + bcol + 64 + tx * 4] = o1;
    }
}

// ---------------------------------------------------------------------------
// Attention combine: per sample b (8192 blocks), 4 warps = 4 heads.
// scores s_ij = dot(Q_i, Kc_i - Kc_j + bk_c)/16; softmax over 3 j != i;
// ctx_i = Vc_i + bv_c - sum_j a_ij Vc_j
// ---------------------------------------------------------------------------
__device__ __forceinline__ float wsum(float v) {
    #pragma unroll
    for (int o = 16; o; o >>= 1) v += __shfl_xor_sync(0xffffffffu, v, o);
    return v;
}

__global__ __launch_bounds__(128) void combine_kernel(
    const float* __restrict__ Q, const float* __restrict__ Kc,
    const float* __restrict__ Vc,
    const float* __restrict__ bk, const float* __restrict__ bv,
    float* __restrict__ ctx)
{
    const int b    = blockIdx.x;            // 0..8191
    const int h    = threadIdx.x >> 5;      // head = warp
    const int lane = threadIdx.x & 31;
    const int base_d = h * HD + lane;       // element indices base_d + e*32

    float q[4][8], kc[4][8], vc[4][8];
    #pragma unroll
    for (int i = 0; i < 4; i++) {
        size_t row = (size_t)(i * NB + b) * DD + base_d;
        #pragma unroll
        for (int e = 0; e < 8; e++) {
            q [i][e] = Q [row + e * 32];
            kc[i][e] = Kc[row + e * 32];
            vc[i][e] = Vc[row + e * 32];
        }
    }
    float bke[8], bve[8];
    #pragma unroll
    for (int e = 0; e < 8; e++) {
        bke[e] = bk[base_d + e * 32];
        bve[e] = bv[base_d + e * 32];
    }

    float a[4][4];
    #pragma unroll
    for (int i = 0; i < 4; i++) {
        float s[4];
        #pragma unroll
        for (int j = 0; j < 4; j++) {
            float p = 0.f;
            #pragma unroll
            for (int e = 0; e < 8; e++)
                p = fmaf(q[i][e], kc[i][e] - kc[j][e] + bke[e], p);
            s[j] = wsum(p) * (1.f / 16.f);   // /sqrt(256)
        }
        // softmax over j != i
        float m = -1e30f;
        #pragma unroll
        for (int j = 0; j < 4; j++) if (j != i && s[j] > m) m = s[j];
        float den = 0.f;
        #pragma unroll
        for (int j = 0; j < 4; j++) {
            float ex = (j == i) ? 0.f : __expf(s[j] - m);
            a[i][j] = ex; den += ex;
        }
        float inv = 1.f / den;
        #pragma unroll
        for (int j = 0; j < 4; j++) a[i][j] *= inv;
    }

    #pragma unroll
    for (int i = 0; i < 4; i++) {
        size_t row = (size_t)(i * NB + b) * DD + base_d;
        #pragma unroll
        for (int e = 0; e < 8; e++) {
            float c = vc[i][e] + bve[e];
            #pragma unroll
            for (int j = 0; j < 4; j++)
                c = fmaf(-a[i][j], vc[j][e], c);
            ctx[row + e * 32] = c;
        }
    }
}

// ---------------------------------------------------------------------------
// Logits: one warp per row, 4 outputs each. D is the already-written d_out.
// ---------------------------------------------------------------------------
__global__ __launch_bounds__(256) void logits_kernel(
    const float* __restrict__ D, const float* __restrict__ Wc,
    const float* __restrict__ bc, float* __restrict__ out)
{
    const int warp = (blockIdx.x * blockDim.x + threadIdx.x) >> 5;
    const int lane = threadIdx.x & 31;
    if (warp >= MTOT) return;
    const float* drow = D + (size_t)warp * DD;
    float s0 = 0.f, s1 = 0.f, s2 = 0.f, s3 = 0.f;
    for (int k = lane; k < DD; k += 32) {
        float d = drow[k];
        s0 = fmaf(d, Wc[k],            s0);
        s1 = fmaf(d, Wc[DD + k],       s1);
        s2 = fmaf(d, Wc[2 * DD + k],   s2);
        s3 = fmaf(d, Wc[3 * DD + k],   s3);
    }
    s0 = wsum(s0); s1 = wsum(s1); s2 = wsum(s2); s3 = wsum(s3);
    if (lane == 0) {
        out[(size_t)warp * 4 + 0] = s0 + bc[0];
        out[(size_t)warp * 4 + 1] = s1 + bc[1];
        out[(size_t)warp * 4 + 2] = s2 + bc[2];
        out[(size_t)warp * 4 + 3] = s3 + bc[3];
    }
}

// ---------------------------------------------------------------------------
extern "C" void kernel_launch(void* const* d_in, const int* in_sizes, int n_in,
                              void* d_out, int out_size)
{
    const float* X[4] = { (const float*)d_in[0], (const float*)d_in[1],
                          (const float*)d_in[2], (const float*)d_in[3] };
    const float* Wq   = (const float*)d_in[4];
    const float* bq   = (const float*)d_in[5];
    // Wk_s (6), bk_s (7) are mathematically unused (softmax over 1 key == 1)
    const float* Wv_s = (const float*)d_in[8];
    const float* bv_s = (const float*)d_in[9];
    const float* Wo_s = (const float*)d_in[10];
    const float* bo_s = (const float*)d_in[11];
    const float* Wk_c = (const float*)d_in[12];
    const float* bk_c = (const float*)d_in[13];
    const float* Wv_c = (const float*)d_in[14];
    const float* bv_c = (const float*)d_in[15];
    const float* Wo_c = (const float*)d_in[16];
    const float* bo_c = (const float*)d_in[17];
    const float* Wc   = (const float*)d_in[18];
    const float* bc   = (const float*)d_in[19];

    float* out = (float*)d_out;
    float* logits = out + (size_t)MTOT * DD;

    float *gX, *gQ, *gKc, *gVc, *gVs, *gCtx;
    cudaGetSymbolAddress((void**)&gX,   g_X);
    cudaGetSymbolAddress((void**)&gQ,   g_Q);
    cudaGetSymbolAddress((void**)&gKc,  g_Kc);
    cudaGetSymbolAddress((void**)&gVc,  g_Vc);
    cudaGetSymbolAddress((void**)&gVs,  g_Vs);
    cudaGetSymbolAddress((void**)&gCtx, g_ctx);

    // stack inputs
    for (int i = 0; i < 4; i++)
        cudaMemcpyAsync(gX + (size_t)i * NB * DD, X[i],
                        (size_t)NB * DD * sizeof(float),
                        cudaMemcpyDeviceToDevice, 0);

    dim3 grid(DD / BN, MTOT / BM);   // (8, 256)

    // projections (Kc, Vc biases handled in combine since they must survive the key difference)
    sgemm_nt<<<grid, 256>>>(gX, Wq,   bq,      nullptr, nullptr, nullptr, gQ,  MTOT, DD, DD);
    sgemm_nt<<<grid, 256>>>(gX, Wk_c, nullptr, nullptr, nullptr, nullptr, gKc, MTOT, DD, DD);
    sgemm_nt<<<grid, 256>>>(gX, Wv_c, nullptr, nullptr, nullptr, nullptr, gVc, MTOT, DD, DD);
    sgemm_nt<<<grid, 256>>>(gX, Wv_s, bv_s,    nullptr, nullptr, nullptr, gVs, MTOT, DD, DD);

    // attention combine
    combine_kernel<<<NB, 128>>>(gQ, gKc, gVc, bk_c, bv_c, gCtx);

    // d = Vs @ Wo_s^T + ctx @ Wo_c^T + (bo_s + bo_c), written straight into d_out
    sgemm_nt<<<grid, 256>>>(gVs, Wo_s, bo_s, gCtx, Wo_c, bo_c, out, MTOT, DD, DD);

    // logits = d @ Wc^T + bc
    logits_kernel<<<(MTOT * 32 + 255) / 256, 256>>>(out, Wc, bc, logits);
}

// round 4
// speedup vs baseline: 2.0137x; 2.0137x over previous
#include <cuda_runtime.h>
#include <cuda_bf16.h>
#include <cstdint>
#include <cstddef>

// ---------------------------------------------------------------------------
// MultiModalClassifier on GB300 via mma.sync bf16 (baseline PTX; tcgen05 is
// rejected by the harness's compute_103 PTX stage).
//   B=8192, D=1024, H=4 (hd=256), C=4, M=4*B=32768
// Algebra (validated R1, rel_err 1.1e-6 fp32):
//   self_out = (X@Wv_s^T+bv_s)@Wo_s^T+bo_s      (softmax over 1 key == 1)
//   cross keys/values factor per-input: Kc_i - Kc_j + bk_c etc.
// bf16x2 split: a*b ~ ah*bh + al*bh + ah*bl (err ~2^-16), folded into
// K-concatenation: A'=[hi|lo|hi], W'=[hi|hi|lo] -> plain GEMM, K tripled.
// R3 bug: B fragment used ldmatrix.trans; K-contiguous B needs NON-trans.
// ---------------------------------------------------------------------------

#define NB 8192
#define DD 1024
#define MTOT 32768
#define HD 256

#define K1 3072          // 3*1024
#define N1 4096          // Q|Kc|Vc|Vs fused
#define K2 6144          // 3*1024 * 2 inputs (Vs, ctx)

// ------------------------------ scratch -----------------------------------
__device__ __nv_bfloat16 g_Xs[(size_t)MTOT * K1];   // 192 MB
__device__ __nv_bfloat16 g_W1[(size_t)N1 * K1];     // 24 MB
__device__ float         g_C1[(size_t)MTOT * N1];   // 512 MB
__device__ float         g_ctx[(size_t)MTOT * DD];  // 128 MB
__device__ __nv_bfloat16 g_A2[(size_t)MTOT * K2];   // 384 MB
__device__ __nv_bfloat16 g_W2[(size_t)DD * K2];     // 12 MB
__device__ float         g_b1[N1];
__device__ float         g_b2[DD];

// --------------------------- PTX helpers -----------------------------------
__device__ __forceinline__ uint32_t smem_u32(const void* p) {
    uint32_t a;
    asm("{ .reg .u64 t; cvta.to.shared.u64 t, %1; cvt.u32.u64 %0, t; }"
        : "=r"(a) : "l"(p));
    return a;
}

#define CP_ASYNC16(dst, src) \
    asm volatile("cp.async.cg.shared.global [%0], [%1], 16;" :: "r"(dst), "l"(src))
#define CP_COMMIT() asm volatile("cp.async.commit_group;" ::: "memory")
#define CP_WAIT(n)  asm volatile("cp.async.wait_group %0;" :: "n"(n) : "memory")

#define LDMATRIX_X4(r0, r1, r2, r3, addr)                                     \
    asm volatile("ldmatrix.sync.aligned.m8n8.x4.shared.b16 {%0,%1,%2,%3}, [%4];" \
                 : "=r"(r0), "=r"(r1), "=r"(r2), "=r"(r3) : "r"(addr))
// NON-trans x2: K-contiguous B rows (n-major rows, k columns) already give the
// mma.b fragment layout (n = t/4, k = (t%4)*2+e).
#define LDMATRIX_X2(r0, r1, addr)                                             \
    asm volatile("ldmatrix.sync.aligned.m8n8.x2.shared.b16 {%0,%1}, [%2];"    \
                 : "=r"(r0), "=r"(r1) : "r"(addr))

#define MMA16816(d0, d1, d2, d3, a0, a1, a2, a3, b0, b1)                      \
    asm volatile("mma.sync.aligned.m16n8k16.row.col.f32.bf16.bf16.f32 "       \
                 "{%0,%1,%2,%3}, {%4,%5,%6,%7}, {%8,%9}, {%0,%1,%2,%3};"      \
                 : "+f"(d0), "+f"(d1), "+f"(d2), "+f"(d3)                     \
                 : "r"(a0), "r"(a1), "r"(a2), "r"(a3), "r"(b0), "r"(b1))

// --------------------------- GEMM kernel -----------------------------------
// C[M,N] = A[M,K](bf16,K-major) @ B[N,K](bf16,K-major)^T + bias, fp32 out.
// Tile 128x128, BK=32 (64B rows), 4-stage cp.async pipeline, 8 warps (2x4),
// warp tile 64x32 via mma.sync m16n8k16. xor swizzle -> conflict-free.
#define STAGES 4
#define STAGE_BYTES 16384           // A 8KB + B 8KB
#define GEMM_SMEM (STAGES * STAGE_BYTES)

__device__ __forceinline__ void gemm_load_stage(
    const __nv_bfloat16* __restrict__ A, const __nv_bfloat16* __restrict__ B,
    int K, int brow, int bcol, int kb, uint32_t st, int tid)
{
    const int row   = tid >> 1;          // 0..127
    const int cpair = (tid & 1) * 2;     // chunk c16 = cpair, cpair+1
    const int swz   = (row >> 1) & 3;
    const uint32_t arow = st + row * 64;
    const uint32_t brow_s = st + 8192 + row * 64;
    const __nv_bfloat16* ga = A + (size_t)(brow + row) * K + kb * 32 + cpair * 8;
    const __nv_bfloat16* gb = B + (size_t)(bcol + row) * K + kb * 32 + cpair * 8;
    CP_ASYNC16(arow   + ((cpair       ^ swz) * 16), ga);
    CP_ASYNC16(arow   + (((cpair + 1) ^ swz) * 16), ga + 8);
    CP_ASYNC16(brow_s + ((cpair       ^ swz) * 16), gb);
    CP_ASYNC16(brow_s + (((cpair + 1) ^ swz) * 16), gb + 8);
}

__global__ __launch_bounds__(256, 2)
void gemm_bf16_mma(const __nv_bfloat16* __restrict__ A,
                   const __nv_bfloat16* __restrict__ B,
                   const float* __restrict__ bias,
                   float* __restrict__ C, int M, int N, int K)
{
    extern __shared__ __align__(1024) char smem[];
    const uint32_t sbase = smem_u32(smem);
    const int tid  = threadIdx.x;
    const int wid  = tid >> 5, lane = tid & 31;
    const int wm   = wid >> 2, wn = wid & 3;    // 2 x 4 warps
    const int brow = blockIdx.y * 128, bcol = blockIdx.x * 128;
    const int NKB  = K >> 5;

    float acc[4][4][4];
    #pragma unroll
    for (int i = 0; i < 4; i++)
        #pragma unroll
        for (int j = 0; j < 4; j++)
            #pragma unroll
            for (int k = 0; k < 4; k++) acc[i][j][k] = 0.f;

    // prologue: fill 3 stages
    #pragma unroll
    for (int s = 0; s < 3; s++) {
        gemm_load_stage(A, B, K, brow, bcol, s, sbase + s * STAGE_BYTES, tid);
        CP_COMMIT();
    }

    // per-thread ldmatrix row components (loop-invariant)
    int a_row[4], a_swz[4];
    #pragma unroll
    for (int mt = 0; mt < 4; mt++) {
        int r = wm * 64 + mt * 16 + (lane & 15);
        a_row[mt] = r * 64;
        a_swz[mt] = (r >> 1) & 3;
    }
    int b_row[4], b_swz[4];
    #pragma unroll
    for (int nt = 0; nt < 4; nt++) {
        int r = wn * 32 + nt * 8 + (lane & 7);
        b_row[nt] = r * 64;
        b_swz[nt] = (r >> 1) & 3;
    }
    const int a_hi = lane >> 4;          // 0/1
    const int b_hi = (lane >> 3) & 1;    // 0/1

    for (int kb = 0; kb < NKB; kb++) {
        CP_WAIT(2);
        __syncthreads();
        if (kb + 3 < NKB)
            gemm_load_stage(A, B, K, brow, bcol, kb + 3,
                            sbase + ((kb + 3) & 3) * STAGE_BYTES, tid);
        CP_COMMIT();

        const uint32_t sA = sbase + (kb & 3) * STAGE_BYTES;
        const uint32_t sB = sA + 8192;

        #pragma unroll
        for (int kstep = 0; kstep < 2; kstep++) {
            uint32_t af[4][4], bf[4][2];
            #pragma unroll
            for (int mt = 0; mt < 4; mt++) {
                int cc = (kstep * 2 + a_hi) ^ a_swz[mt];
                LDMATRIX_X4(af[mt][0], af[mt][1], af[mt][2], af[mt][3],
                            sA + a_row[mt] + cc * 16);
            }
            #pragma unroll
            for (int nt = 0; nt < 4; nt++) {
                int cc = (kstep * 2 + b_hi) ^ b_swz[nt];
                LDMATRIX_X2(bf[nt][0], bf[nt][1], sB + b_row[nt] + cc * 16);
            }
            #pragma unroll
            for (int mt = 0; mt < 4; mt++)
                #pragma unroll
                for (int nt = 0; nt < 4; nt++)
                    MMA16816(acc[mt][nt][0], acc[mt][nt][1],
                             acc[mt][nt][2], acc[mt][nt][3],
                             af[mt][0], af[mt][1], af[mt][2], af[mt][3],
                             bf[nt][0], bf[nt][1]);
        }
        __syncthreads();
    }

    // epilogue: direct gmem write + bias
    #pragma unroll
    for (int mt = 0; mt < 4; mt++) {
        const int r0 = brow + wm * 64 + mt * 16 + (lane >> 2);
        #pragma unroll
        for (int nt = 0; nt < 4; nt++) {
            const int c0 = bcol + wn * 32 + nt * 8 + (lane & 3) * 2;
            const float bx = bias[c0], by = bias[c0 + 1];
            float2 v0 = { acc[mt][nt][0] + bx, acc[mt][nt][1] + by };
            float2 v1 = { acc[mt][nt][2] + bx, acc[mt][nt][3] + by };
            *(float2*)&C[(size_t)r0 * N + c0]       = v0;
            *(float2*)&C[(size_t)(r0 + 8) * N + c0] = v1;
        }
    }
}

// --------------------------- split kernels ---------------------------------
__device__ __forceinline__ void split1(float a, __nv_bfloat16& h, __nv_bfloat16& l) {
    h = __float2bfloat16(a);
    l = __float2bfloat16(a - __bfloat162float(h));
}

// Xs[r, 3072] = [hi(X[r]) | lo | hi], r = i*NB + b
__global__ __launch_bounds__(256) void split_X_kernel(
    const float* __restrict__ X1, const float* __restrict__ X2,
    const float* __restrict__ X3, const float* __restrict__ X4,
    __nv_bfloat16* __restrict__ Xs)
{
    size_t idx = (size_t)blockIdx.x * blockDim.x + threadIdx.x;  // one float4
    size_t r = idx >> 8;
    int c4 = (int)(idx & 255) * 4;
    const float* src = (r < NB) ? X1 : (r < 2 * NB) ? X2 : (r < 3 * NB) ? X3 : X4;
    float4 v = *(const float4*)&src[(r & (NB - 1)) * DD + c4];
    __nv_bfloat16 h[4], l[4];
    split1(v.x, h[0], l[0]); split1(v.y, h[1], l[1]);
    split1(v.z, h[2], l[2]); split1(v.w, h[3], l[3]);
    __nv_bfloat16* row = Xs + r * K1;
    *(uint2*)&row[c4]        = *(uint2*)h;
    *(uint2*)&row[DD + c4]   = *(uint2*)l;
    *(uint2*)&row[2*DD + c4] = *(uint2*)h;
}

// W1[n, 3072] = [hi | hi | lo], n -> {Wq, Wk_c, Wv_c, Wv_s}
__global__ __launch_bounds__(256) void split_W1_kernel(
    const float* __restrict__ Wq, const float* __restrict__ Wkc,
    const float* __restrict__ Wvc, const float* __restrict__ Wvs,
    __nv_bfloat16* __restrict__ W1)
{
    size_t idx = (size_t)blockIdx.x * blockDim.x + threadIdx.x;
    size_t n = idx >> 8;
    int c4 = (int)(idx & 255) * 4;
    const float* src = (n < 1024) ? Wq : (n < 2048) ? Wkc : (n < 3072) ? Wvc : Wvs;
    float4 v = *(const float4*)&src[(n & 1023) * DD + c4];
    __nv_bfloat16 h[4], l[4];
    split1(v.x, h[0], l[0]); split1(v.y, h[1], l[1]);
    split1(v.z, h[2], l[2]); split1(v.w, h[3], l[3]);
    __nv_bfloat16* row = W1 + n * K1;
    *(uint2*)&row[c4]        = *(uint2*)h;
    *(uint2*)&row[DD + c4]   = *(uint2*)h;
    *(uint2*)&row[2*DD + c4] = *(uint2*)l;
}

// W2[n, 6144] = [Wo_s: hi|hi|lo | Wo_c: hi|hi|lo]
__global__ __launch_bounds__(256) void split_W2_kernel(
    const float* __restrict__ Wos, const float* __restrict__ Woc,
    __nv_bfloat16* __restrict__ W2)
{
    size_t idx = (size_t)blockIdx.x * blockDim.x + threadIdx.x;
    int sel = (int)(idx >> 18);               // 1024*256 f4 per source
    size_t rem = idx & ((1 << 18) - 1);
    size_t n = rem >> 8;
    int c4 = (int)(rem & 255) * 4;
    const float* src = sel ? Woc : Wos;
    float4 v = *(const float4*)&src[n * DD + c4];
    __nv_bfloat16 h[4], l[4];
    split1(v.x, h[0], l[0]); split1(v.y, h[1], l[1]);
    split1(v.z, h[2], l[2]); split1(v.w, h[3], l[3]);
    __nv_bfloat16* row = W2 + n * K2 + sel * K1;
    *(uint2*)&row[c4]        = *(uint2*)h;
    *(uint2*)&row[DD + c4]   = *(uint2*)h;
    *(uint2*)&row[2*DD + c4] = *(uint2*)l;
}

// A2[r, 6144] = [Vs: hi|lo|hi | ctx: hi|lo|hi];  Vs = C1[:, 3072:4096]
__global__ __launch_bounds__(256) void split_AV_kernel(
    const float* __restrict__ C1, const float* __restrict__ ctx,
    __nv_bfloat16* __restrict__ A2)
{
    size_t idx = (size_t)blockIdx.x * blockDim.x + threadIdx.x;
    int sel = (int)(idx >> 23);               // 32768*256 f4 per source
    size_t rem = idx & ((1u << 23) - 1);
    size_t r = rem >> 8;
    int c4 = (int)(rem & 255) * 4;
    float4 v = sel ? *(const float4*)&ctx[r * DD + c4]
                   : *(const float4*)&C1[r * N1 + 3072 + c4];
    __nv_bfloat16 h[4], l[4];
    split1(v.x, h[0], l[0]); split1(v.y, h[1], l[1]);
    split1(v.z, h[2], l[2]); split1(v.w, h[3], l[3]);
    __nv_bfloat16* row = A2 + r * K2 + sel * K1;
    *(uint2*)&row[c4]        = *(uint2*)h;
    *(uint2*)&row[DD + c4]   = *(uint2*)l;
    *(uint2*)&row[2*DD + c4] = *(uint2*)h;
}

__global__ void bias_build_kernel(
    const float* __restrict__ bq, const float* __restrict__ bvs,
    const float* __restrict__ bos, const float* __restrict__ boc,
    float* __restrict__ b1, float* __restrict__ b2)
{
    int i = blockIdx.x * blockDim.x + threadIdx.x;
    if (i < 1024) {
        b1[i] = bq[i]; b1[1024 + i] = 0.f; b1[2048 + i] = 0.f; b1[3072 + i] = bvs[i];
        b2[i] = bos[i] + boc[i];
    }
}

// --------------------------- combine ---------------------------------------
__device__ __forceinline__ float wsum(float v) {
    #pragma unroll
    for (int o = 16; o; o >>= 1) v += __shfl_xor_sync(0xffffffffu, v, o);
    return v;
}

__global__ __launch_bounds__(128) void combine_kernel(
    const float* __restrict__ C1,
    const float* __restrict__ bk, const float* __restrict__ bv,
    float* __restrict__ ctx)
{
    const int b    = blockIdx.x;
    const int h    = threadIdx.x >> 5;
    const int lane = threadIdx.x & 31;
    const int base_d = h * HD + lane;

    float q[4][8], kc[4][8], vc[4][8];
    #pragma unroll
    for (int i = 0; i < 4; i++) {
        size_t row = (size_t)(i * NB + b) * N1 + base_d;
        #pragma unroll
        for (int e = 0; e < 8; e++) {
            q [i][e] = C1[row + e * 32];
            kc[i][e] = C1[row + 1024 + e * 32];
            vc[i][e] = C1[row + 2048 + e * 32];
        }
    }
    float bke[8], bve[8];
    #pragma unroll
    for (int e = 0; e < 8; e++) {
        bke[e] = bk[base_d + e * 32];
        bve[e] = bv[base_d + e * 32];
    }

    float a[4][4];
    #pragma unroll
    for (int i = 0; i < 4; i++) {
        float s[4];
        #pragma unroll
        for (int j = 0; j < 4; j++) {
            float p = 0.f;
            #pragma unroll
            for (int e = 0; e < 8; e++)
                p = fmaf(q[i][e], kc[i][e] - kc[j][e] + bke[e], p);
            s[j] = wsum(p) * (1.f / 16.f);
        }
        float m = -1e30f;
        #pragma unroll
        for (int j = 0; j < 4; j++) if (j != i && s[j] > m) m = s[j];
        float den = 0.f;
        #pragma unroll
        for (int j = 0; j < 4; j++) {
            float ex = (j == i) ? 0.f : __expf(s[j] - m);
            a[i][j] = ex; den += ex;
        }
        float inv = 1.f / den;
        #pragma unroll
        for (int j = 0; j < 4; j++) a[i][j] *= inv;
    }

    #pragma unroll
    for (int i = 0; i < 4; i++) {
        size_t row = (size_t)(i * NB + b) * DD + base_d;
        #pragma unroll
        for (int e = 0; e < 8; e++) {
            float c = vc[i][e] + bve[e];
            #pragma unroll
            for (int j = 0; j < 4; j++)
                c = fmaf(-a[i][j], vc[j][e], c);
            ctx[row + e * 32] = c;
        }
    }
}

// --------------------------- logits ----------------------------------------
__global__ __launch_bounds__(256) void logits_kernel(
    const float* __restrict__ D, const float* __restrict__ Wc,
    const float* __restrict__ bc, float* __restrict__ out)
{
    const int warp = (blockIdx.x * blockDim.x + threadIdx.x) >> 5;
    const int lane = threadIdx.x & 31;
    if (warp >= MTOT) return;
    const float* drow = D + (size_t)warp * DD;
    float s0 = 0.f, s1 = 0.f, s2 = 0.f, s3 = 0.f;
    for (int k = lane; k < DD; k += 32) {
        float d = drow[k];
        s0 = fmaf(d, Wc[k],          s0);
        s1 = fmaf(d, Wc[DD + k],     s1);
        s2 = fmaf(d, Wc[2 * DD + k], s2);
        s3 = fmaf(d, Wc[3 * DD + k], s3);
    }
    s0 = wsum(s0); s1 = wsum(s1); s2 = wsum(s2); s3 = wsum(s3);
    if (lane == 0) {
        out[(size_t)warp * 4 + 0] = s0 + bc[0];
        out[(size_t)warp * 4 + 1] = s1 + bc[1];
        out[(size_t)warp * 4 + 2] = s2 + bc[2];
        out[(size_t)warp * 4 + 3] = s3 + bc[3];
    }
}

// ---------------------------------------------------------------------------
extern "C" void kernel_launch(void* const* d_in, const int* in_sizes, int n_in,
                              void* d_out, int out_size)
{
    const float* X1   = (const float*)d_in[0];
    const float* X2   = (const float*)d_in[1];
    const float* X3   = (const float*)d_in[2];
    const float* X4   = (const float*)d_in[3];
    const float* Wq   = (const float*)d_in[4];
    const float* bq   = (const float*)d_in[5];
    const float* Wv_s = (const float*)d_in[8];
    const float* bv_s = (const float*)d_in[9];
    const float* Wo_s = (const float*)d_in[10];
    const float* bo_s = (const float*)d_in[11];
    const float* Wk_c = (const float*)d_in[12];
    const float* bk_c = (const float*)d_in[13];
    const float* Wv_c = (const float*)d_in[14];
    const float* bv_c = (const float*)d_in[15];
    const float* Wo_c = (const float*)d_in[16];
    const float* bo_c = (const float*)d_in[17];
    const float* Wc   = (const float*)d_in[18];
    const float* bc   = (const float*)d_in[19];

    float* out    = (float*)d_out;
    float* logits = out + (size_t)MTOT * DD;

    __nv_bfloat16 *gXs, *gW1, *gA2, *gW2;
    float *gC1, *gCtx, *gb1, *gb2;
    cudaGetSymbolAddress((void**)&gXs,  g_Xs);
    cudaGetSymbolAddress((void**)&gW1,  g_W1);
    cudaGetSymbolAddress((void**)&gC1,  g_C1);
    cudaGetSymbolAddress((void**)&gCtx, g_ctx);
    cudaGetSymbolAddress((void**)&gA2,  g_A2);
    cudaGetSymbolAddress((void**)&gW2,  g_W2);
    cudaGetSymbolAddress((void**)&gb1,  g_b1);
    cudaGetSymbolAddress((void**)&gb2,  g_b2);

    cudaFuncSetAttribute(gemm_bf16_mma,
                         cudaFuncAttributeMaxDynamicSharedMemorySize, GEMM_SMEM);

    // prep: bf16 splits + bias vectors
    split_X_kernel <<<(MTOT * 256) / 256, 256>>>(X1, X2, X3, X4, gXs);
    split_W1_kernel<<<(N1 * 256) / 256, 256>>>(Wq, Wk_c, Wv_c, Wv_s, gW1);
    split_W2_kernel<<<(2 * 1024 * 256) / 256, 256>>>(Wo_s, Wo_c, gW2);
    bias_build_kernel<<<4, 256>>>(bq, bv_s, bo_s, bo_c, gb1, gb2);

    // fused projection GEMM: C1[32768,4096] = Xs @ W1^T + b1
    {
        dim3 grid(N1 / 128, MTOT / 128);
        gemm_bf16_mma<<<grid, 256, GEMM_SMEM>>>(gXs, gW1, gb1, gC1, MTOT, N1, K1);
    }

    // attention combine -> ctx (fp32)
    combine_kernel<<<NB, 128>>>(gC1, bk_c, bv_c, gCtx);

    // build A2 = [Vs split | ctx split]
    split_AV_kernel<<<(2 * MTOT * 256) / 256, 256>>>(gC1, gCtx, gA2);

    // output GEMM straight into d_out: D = A2 @ W2^T + b2
    {
        dim3 grid(DD / 128, MTOT / 128);
        gemm_bf16_mma<<<grid, 256, GEMM_SMEM>>>(gA2, gW2, gb2, out, MTOT, DD, K2);
    }

    // logits
    logits_kernel<<<(MTOT * 32 + 255) / 256, 256>>>(out, Wc, bc, logits);
}

// round 5
// speedup vs baseline: 3.2023x; 1.5902x over previous
#include <cuda_runtime.h>
#include <cuda_bf16.h>
#include <cstdint>
#include <cstddef>

// ---------------------------------------------------------------------------
// MultiModalClassifier, GB300, mma.sync bf16 3-term split GEMMs.
//   B=8192, D=1024, H=4 (hd=256), C=4, M=32768
// Algebra:
//   self_out = X@(Wo_s@Wv_s)^T + (Wo_s@bv_s + bo_s)   [1-key softmax == 1]
//   cross: K_ij = Kc_i - Kc_j + bk_c, V_ij = Vc_i - Vc_j + bv_c
//   d = S + ctx@Wo_c^T + bo_c, ctx from 4x4 head-wise softmax combine.
// bf16 split a=ah+al: a*b ~ ah*bh + al*bh + ah*bl, folded as K-concat:
//   A' = [hi|lo|hi], W' = [hi|hi|lo]  (one GEMM, K=3072).
// ---------------------------------------------------------------------------

#define NB 8192
#define DD 1024
#define MTOT 32768
#define HD 256
#define K1 3072
#define N1 4096          // Q | Kc | Vc | S

// ------------------------------ scratch ------------------------------------
__device__ __nv_bfloat16 g_Xs  [(size_t)MTOT * K1];   // 192 MB
__device__ __nv_bfloat16 g_W1  [(size_t)N1 * K1];     // 24 MB
__device__ float         g_C1  [(size_t)MTOT * N1];   // 512 MB
__device__ __nv_bfloat16 g_A2  [(size_t)MTOT * K1];   // 192 MB (ctx split)
__device__ __nv_bfloat16 g_WocS[(size_t)DD * K1];     // 6 MB
__device__ __nv_bfloat16 g_WosS[(size_t)DD * K1];     // 6 MB
__device__ __nv_bfloat16 g_WvsT[(size_t)DD * K1];     // 6 MB
__device__ float         g_Weff[(size_t)DD * DD];     // 4 MB
__device__ float         g_b1[N1];
__device__ float         g_zero[DD];                   // never written: zeros

// --------------------------- PTX helpers -----------------------------------
__device__ __forceinline__ uint32_t smem_u32(const void* p) {
    uint32_t a;
    asm("{ .reg .u64 t; cvta.to.shared.u64 t, %1; cvt.u32.u64 %0, t; }"
        : "=r"(a) : "l"(p));
    return a;
}

#define CP_ASYNC16(dst, src) \
    asm volatile("cp.async.cg.shared.global [%0], [%1], 16;" :: "r"(dst), "l"(src))
#define CP_COMMIT() asm volatile("cp.async.commit_group;" ::: "memory")
#define CP_WAIT(n)  asm volatile("cp.async.wait_group %0;" :: "n"(n) : "memory")

#define LDMATRIX_X4(r0, r1, r2, r3, addr)                                     \
    asm volatile("ldmatrix.sync.aligned.m8n8.x4.shared.b16 {%0,%1,%2,%3}, [%4];" \
                 : "=r"(r0), "=r"(r1), "=r"(r2), "=r"(r3) : "r"(addr))

#define MMA16816(d0, d1, d2, d3, a0, a1, a2, a3, b0, b1)                      \
    asm volatile("mma.sync.aligned.m16n8k16.row.col.f32.bf16.bf16.f32 "       \
                 "{%0,%1,%2,%3}, {%4,%5,%6,%7}, {%8,%9}, {%0,%1,%2,%3};"      \
                 : "+f"(d0), "+f"(d1), "+f"(d2), "+f"(d3)                     \
                 : "r"(a0), "r"(a1), "r"(a2), "r"(a3), "r"(b0), "r"(b1))

// --------------------------- GEMM kernel -----------------------------------
// C[M,N] = A[M,K] @ B[N,K]^T + bias (+ add), bf16 in / fp32 out.
// CTA tile 128x256, BK=64 (128B rows, full SW128 swizzle), 4-stage cp.async,
// 8 warps (2x4), warp tile 64x64, B frags via x4 (two n-tiles per ldmatrix).
#define STAGES 4
#define STAGE_BYTES 49152          // A 16KB + B 32KB
#define GEMM_SMEM (STAGES * STAGE_BYTES)

__device__ __forceinline__ void load_stage(
    const __nv_bfloat16* __restrict__ A, const __nv_bfloat16* __restrict__ B,
    int K, int brow, int bcol, int kb, uint32_t st, int tid)
{
    #pragma unroll
    for (int i = 0; i < 12; i++) {
        int id = tid + 256 * i;
        if (id < 1024) {                       // A: 128 rows x 8 chunks
            int row = id >> 3, c = id & 7;
            const __nv_bfloat16* g = A + (size_t)(brow + row) * K + kb * 64 + c * 8;
            CP_ASYNC16(st + row * 128 + ((c ^ (row & 7)) * 16), g);
        } else {                               // B: 256 rows x 8 chunks
            int idb = id - 1024;
            int row = idb >> 3, c = idb & 7;
            const __nv_bfloat16* g = B + (size_t)(bcol + row) * K + kb * 64 + c * 8;
            CP_ASYNC16(st + 16384 + row * 128 + ((c ^ (row & 7)) * 16), g);
        }
    }
}

__global__ __launch_bounds__(256, 1)
void gemm_bf16_mma(const __nv_bfloat16* __restrict__ A,
                   const __nv_bfloat16* __restrict__ B,
                   const float* __restrict__ bias,
                   const float* __restrict__ add, int add_ld,
                   float* __restrict__ C, int M, int N, int K)
{
    extern __shared__ __align__(1024) char smem[];
    const uint32_t sbase = smem_u32(smem);
    const int tid  = threadIdx.x;
    const int wid  = tid >> 5, lane = tid & 31;
    const int wm   = wid >> 2, wn = wid & 3;     // 2 x 4 warps
    const int brow = blockIdx.y * 128, bcol = blockIdx.x * 256;
    const int NKB  = K >> 6;

    float acc[4][8][4];
    #pragma unroll
    for (int i = 0; i < 4; i++)
        #pragma unroll
        for (int j = 0; j < 8; j++)
            #pragma unroll
            for (int k = 0; k < 4; k++) acc[i][j][k] = 0.f;

    load_stage(A, B, K, brow, bcol, 0, sbase, tid);                  CP_COMMIT();
    load_stage(A, B, K, brow, bcol, 1, sbase + STAGE_BYTES, tid);    CP_COMMIT();
    load_stage(A, B, K, brow, bcol, 2, sbase + 2 * STAGE_BYTES, tid);CP_COMMIT();

    // loop-invariant ldmatrix addressing
    int a_off[4], a_sw[4];
    #pragma unroll
    for (int mt = 0; mt < 4; mt++) {
        int r = wm * 64 + mt * 16 + (lane & 15);
        a_off[mt] = r * 128; a_sw[mt] = r & 7;
    }
    const int a_kh = lane >> 4;                  // k-half select (A)
    int b_off[4], b_sw[4];
    #pragma unroll
    for (int np = 0; np < 4; np++) {
        int r = wn * 64 + np * 16 + ((lane >> 4) & 1) * 8 + (lane & 7);
        b_off[np] = r * 128; b_sw[np] = r & 7;
    }
    const int b_kh = (lane >> 3) & 1;            // k-half select (B)

    for (int kb = 0; kb < NKB; kb++) {
        if (kb < NKB - 2)       CP_WAIT(2);
        else if (kb == NKB - 2) CP_WAIT(1);
        else                    CP_WAIT(0);
        __syncthreads();
        if (kb + 3 < NKB) {
            load_stage(A, B, K, brow, bcol, kb + 3,
                       sbase + ((kb + 3) & 3) * STAGE_BYTES, tid);
            CP_COMMIT();
        }
        const uint32_t sA = sbase + (kb & 3) * STAGE_BYTES;
        const uint32_t sB = sA + 16384;

        #pragma unroll
        for (int ks = 0; ks < 4; ks++) {
            uint32_t af[4][4], bf[4][4];
            #pragma unroll
            for (int mt = 0; mt < 4; mt++) {
                int cc = ks * 2 + a_kh;
                LDMATRIX_X4(af[mt][0], af[mt][1], af[mt][2], af[mt][3],
                            sA + a_off[mt] + ((cc ^ a_sw[mt]) * 16));
            }
            #pragma unroll
            for (int np = 0; np < 4; np++) {
                int cc = ks * 2 + b_kh;
                LDMATRIX_X4(bf[np][0], bf[np][1], bf[np][2], bf[np][3],
                            sB + b_off[np] + ((cc ^ b_sw[np]) * 16));
            }
            #pragma unroll
            for (int mt = 0; mt < 4; mt++)
                #pragma unroll
                for (int nt = 0; nt < 8; nt++)
                    MMA16816(acc[mt][nt][0], acc[mt][nt][1],
                             acc[mt][nt][2], acc[mt][nt][3],
                             af[mt][0], af[mt][1], af[mt][2], af[mt][3],
                             bf[nt >> 1][(nt & 1) * 2],
                             bf[nt >> 1][(nt & 1) * 2 + 1]);
        }
    }

    // epilogue: bias (+ optional fp32 addend) + store
    #pragma unroll
    for (int mt = 0; mt < 4; mt++) {
        const int r0 = brow + wm * 64 + mt * 16 + (lane >> 2);
        #pragma unroll
        for (int nt = 0; nt < 8; nt++) {
            const int c0 = bcol + wn * 64 + nt * 8 + (lane & 3) * 2;
            const float bx = bias[c0], by = bias[c0 + 1];
            float a0 = acc[mt][nt][0] + bx, a1 = acc[mt][nt][1] + by;
            float a2 = acc[mt][nt][2] + bx, a3 = acc[mt][nt][3] + by;
            if (add) {
                a0 += add[(size_t)r0 * add_ld + c0];
                a1 += add[(size_t)r0 * add_ld + c0 + 1];
                a2 += add[(size_t)(r0 + 8) * add_ld + c0];
                a3 += add[(size_t)(r0 + 8) * add_ld + c0 + 1];
            }
            float2 v0 = { a0, a1 }, v1 = { a2, a3 };
            *(float2*)&C[(size_t)r0 * N + c0]       = v0;
            *(float2*)&C[(size_t)(r0 + 8) * N + c0] = v1;
        }
    }
}

// --------------------------- split kernels ---------------------------------
__device__ __forceinline__ void split1(float a, __nv_bfloat16& h, __nv_bfloat16& l) {
    h = __float2bfloat16(a);
    l = __float2bfloat16(a - __bfloat162float(h));
}

// A-operand layout [hi|lo|hi]
__global__ __launch_bounds__(256) void split_Ahl(
    const float* __restrict__ src, __nv_bfloat16* __restrict__ dst)
{
    size_t idx = (size_t)blockIdx.x * blockDim.x + threadIdx.x;
    size_t n = idx >> 8;
    int c4 = (int)(idx & 255) * 4;
    float4 v = *(const float4*)&src[n * DD + c4];
    __nv_bfloat16 h[4], l[4];
    split1(v.x, h[0], l[0]); split1(v.y, h[1], l[1]);
    split1(v.z, h[2], l[2]); split1(v.w, h[3], l[3]);
    __nv_bfloat16* row = dst + n * K1;
    *(uint2*)&row[c4]          = *(uint2*)h;
    *(uint2*)&row[DD + c4]     = *(uint2*)l;
    *(uint2*)&row[2 * DD + c4] = *(uint2*)h;
}

// B-operand layout [hi|hi|lo]
__global__ __launch_bounds__(256) void split_Bhl(
    const float* __restrict__ src, __nv_bfloat16* __restrict__ dst)
{
    size_t idx = (size_t)blockIdx.x * blockDim.x + threadIdx.x;
    size_t n = idx >> 8;
    int c4 = (int)(idx & 255) * 4;
    float4 v = *(const float4*)&src[n * DD + c4];
    __nv_bfloat16 h[4], l[4];
    split1(v.x, h[0], l[0]); split1(v.y, h[1], l[1]);
    split1(v.z, h[2], l[2]); split1(v.w, h[3], l[3]);
    __nv_bfloat16* row = dst + n * K1;
    *(uint2*)&row[c4]          = *(uint2*)h;
    *(uint2*)&row[DD + c4]     = *(uint2*)h;
    *(uint2*)&row[2 * DD + c4] = *(uint2*)l;
}

// WvsT[i,m] = Wvs[m,i], B layout [hi|hi|lo]
__global__ __launch_bounds__(256) void transpose_split_B(
    const float* __restrict__ Wvs, __nv_bfloat16* __restrict__ dst)
{
    size_t idx = (size_t)blockIdx.x * blockDim.x + threadIdx.x;
    int m = (int)(idx >> 10);
    int i = (int)(idx & 1023);
    float v = Wvs[(size_t)m * DD + i];
    __nv_bfloat16 h, l; split1(v, h, l);
    __nv_bfloat16* row = dst + (size_t)i * K1;
    row[m] = h; row[DD + m] = h; row[2 * DD + m] = l;
}

// Xs[r,3072] = [hi|lo|hi] of stacked X
__global__ __launch_bounds__(256) void split_X_kernel(
    const float* __restrict__ X1, const float* __restrict__ X2,
    const float* __restrict__ X3, const float* __restrict__ X4,
    __nv_bfloat16* __restrict__ Xs)
{
    size_t idx = (size_t)blockIdx.x * blockDim.x + threadIdx.x;
    size_t r = idx >> 8;
    int c4 = (int)(idx & 255) * 4;
    const float* src = (r < NB) ? X1 : (r < 2 * NB) ? X2 : (r < 3 * NB) ? X3 : X4;
    float4 v = *(const float4*)&src[(r & (NB - 1)) * DD + c4];
    __nv_bfloat16 h[4], l[4];
    split1(v.x, h[0], l[0]); split1(v.y, h[1], l[1]);
    split1(v.z, h[2], l[2]); split1(v.w, h[3], l[3]);
    __nv_bfloat16* row = Xs + r * K1;
    *(uint2*)&row[c4]          = *(uint2*)h;
    *(uint2*)&row[DD + c4]     = *(uint2*)l;
    *(uint2*)&row[2 * DD + c4] = *(uint2*)h;
}

// --------------------------- bias kernels ----------------------------------
__device__ __forceinline__ float wsum(float v) {
    #pragma unroll
    for (int o = 16; o; o >>= 1) v += __shfl_xor_sync(0xffffffffu, v, o);
    return v;
}

__global__ __launch_bounds__(256) void bias_b1_kernel(
    const float* __restrict__ bq, float* __restrict__ b1)
{
    int i = blockIdx.x * blockDim.x + threadIdx.x;
    if (i < DD) { b1[i] = bq[i]; b1[DD + i] = 0.f; b1[2 * DD + i] = 0.f; }
}

// b1[3072+o] = dot(Wos[o,:], bvs) + bos[o]
__global__ __launch_bounds__(256) void bs_eff_kernel(
    const float* __restrict__ Wos, const float* __restrict__ bvs,
    const float* __restrict__ bos, float* __restrict__ b1)
{
    int o = blockIdx.x * 8 + (threadIdx.x >> 5);
    int lane = threadIdx.x & 31;
    float s = 0.f;
    for (int k = lane; k < DD; k += 32)
        s = fmaf(Wos[(size_t)o * DD + k], bvs[k], s);
    s = wsum(s);
    if (lane == 0) b1[3 * DD + o] = s + bos[o];
}

// --------------------------- combine ---------------------------------------
// ctx_i = Vc_i + bv_c - sum_j a_ij Vc_j, written as bf16 split into A2.
__global__ __launch_bounds__(128) void combine_kernel(
    const float* __restrict__ C1,
    const float* __restrict__ bk, const float* __restrict__ bv,
    __nv_bfloat16* __restrict__ A2)
{
    const int b    = blockIdx.x;
    const int h    = threadIdx.x >> 5;
    const int lane = threadIdx.x & 31;
    const int base_d = h * HD + lane;

    float q[4][8], kc[4][8], vc[4][8];
    #pragma unroll
    for (int i = 0; i < 4; i++) {
        size_t row = (size_t)(i * NB + b) * N1 + base_d;
        #pragma unroll
        for (int e = 0; e < 8; e++) {
            q [i][e] = C1[row + e * 32];
            kc[i][e] = C1[row + 1024 + e * 32];
            vc[i][e] = C1[row + 2048 + e * 32];
        }
    }
    float bke[8], bve[8];
    #pragma unroll
    for (int e = 0; e < 8; e++) {
        bke[e] = bk[base_d + e * 32];
        bve[e] = bv[base_d + e * 32];
    }

    float a[4][4];
    #pragma unroll
    for (int i = 0; i < 4; i++) {
        float s[4];
        #pragma unroll
        for (int j = 0; j < 4; j++) {
            float p = 0.f;
            #pragma unroll
            for (int e = 0; e < 8; e++)
                p = fmaf(q[i][e], kc[i][e] - kc[j][e] + bke[e], p);
            s[j] = wsum(p) * (1.f / 16.f);
        }
        float m = -1e30f;
        #pragma unroll
        for (int j = 0; j < 4; j++) if (j != i && s[j] > m) m = s[j];
        float den = 0.f;
        #pragma unroll
        for (int j = 0; j < 4; j++) {
            float ex = (j == i) ? 0.f : __expf(s[j] - m);
            a[i][j] = ex; den += ex;
        }
        float inv = 1.f / den;
        #pragma unroll
        for (int j = 0; j < 4; j++) a[i][j] *= inv;
    }

    #pragma unroll
    for (int i = 0; i < 4; i++) {
        __nv_bfloat16* row = A2 + (size_t)(i * NB + b) * K1;
        #pragma unroll
        for (int e = 0; e < 8; e++) {
            float c = vc[i][e] + bve[e];
            #pragma unroll
            for (int j = 0; j < 4; j++)
                c = fmaf(-a[i][j], vc[j][e], c);
            int col = base_d + e * 32;
            __nv_bfloat16 hh, ll; split1(c, hh, ll);
            row[col] = hh; row[DD + col] = ll; row[2 * DD + col] = hh;
        }
    }
}

// --------------------------- logits ----------------------------------------
__global__ __launch_bounds__(256) void logits_kernel(
    const float* __restrict__ D, const float* __restrict__ Wc,
    const float* __restrict__ bc, float* __restrict__ out)
{
    const int warp = (blockIdx.x * blockDim.x + threadIdx.x) >> 5;
    const int lane = threadIdx.x & 31;
    if (warp >= MTOT) return;
    const float* drow = D + (size_t)warp * DD;
    float s0 = 0.f, s1 = 0.f, s2 = 0.f, s3 = 0.f;
    for (int k = lane; k < DD; k += 32) {
        float d = drow[k];
        s0 = fmaf(d, Wc[k],          s0);
        s1 = fmaf(d, Wc[DD + k],     s1);
        s2 = fmaf(d, Wc[2 * DD + k], s2);
        s3 = fmaf(d, Wc[3 * DD + k], s3);
    }
    s0 = wsum(s0); s1 = wsum(s1); s2 = wsum(s2); s3 = wsum(s3);
    if (lane == 0) {
        out[(size_t)warp * 4 + 0] = s0 + bc[0];
        out[(size_t)warp * 4 + 1] = s1 + bc[1];
        out[(size_t)warp * 4 + 2] = s2 + bc[2];
        out[(size_t)warp * 4 + 3] = s3 + bc[3];
    }
}

// ---------------------------------------------------------------------------
extern "C" void kernel_launch(void* const* d_in, const int* in_sizes, int n_in,
                              void* d_out, int out_size)
{
    const float* X1   = (const float*)d_in[0];
    const float* X2   = (const float*)d_in[1];
    const float* X3   = (const float*)d_in[2];
    const float* X4   = (const float*)d_in[3];
    const float* Wq   = (const float*)d_in[4];
    const float* bq   = (const float*)d_in[5];
    const float* Wv_s = (const float*)d_in[8];
    const float* bv_s = (const float*)d_in[9];
    const float* Wo_s = (const float*)d_in[10];
    const float* bo_s = (const float*)d_in[11];
    const float* Wk_c = (const float*)d_in[12];
    const float* bk_c = (const float*)d_in[13];
    const float* Wv_c = (const float*)d_in[14];
    const float* bv_c = (const float*)d_in[15];
    const float* Wo_c = (const float*)d_in[16];
    const float* bo_c = (const float*)d_in[17];
    const float* Wc   = (const float*)d_in[18];
    const float* bc   = (const float*)d_in[19];

    float* out    = (float*)d_out;
    float* logits = out + (size_t)MTOT * DD;

    __nv_bfloat16 *gXs, *gW1, *gA2, *gWocS, *gWosS, *gWvsT;
    float *gC1, *gWeff, *gb1, *gzero;
    cudaGetSymbolAddress((void**)&gXs,   g_Xs);
    cudaGetSymbolAddress((void**)&gW1,   g_W1);
    cudaGetSymbolAddress((void**)&gC1,   g_C1);
    cudaGetSymbolAddress((void**)&gA2,   g_A2);
    cudaGetSymbolAddress((void**)&gWocS, g_WocS);
    cudaGetSymbolAddress((void**)&gWosS, g_WosS);
    cudaGetSymbolAddress((void**)&gWvsT, g_WvsT);
    cudaGetSymbolAddress((void**)&gWeff, g_Weff);
    cudaGetSymbolAddress((void**)&gb1,   g_b1);
    cudaGetSymbolAddress((void**)&gzero, g_zero);

    cudaFuncSetAttribute(gemm_bf16_mma,
                         cudaFuncAttributeMaxDynamicSharedMemorySize, GEMM_SMEM);

    // prep: splits + weight-space fold of the self path
    split_X_kernel<<<MTOT, 256>>>(X1, X2, X3, X4, gXs);
    split_Bhl<<<1024, 256>>>(Wq,   gW1);
    split_Bhl<<<1024, 256>>>(Wk_c, gW1 + (size_t)1024 * K1);
    split_Bhl<<<1024, 256>>>(Wv_c, gW1 + (size_t)2048 * K1);
    split_Bhl<<<1024, 256>>>(Wo_c, gWocS);
    split_Ahl<<<1024, 256>>>(Wo_s, gWosS);
    transpose_split_B<<<4096, 256>>>(Wv_s, gWvsT);

    // Weff[o,i] = sum_m Wos[o,m] * Wvs[m,i]   (tiny split GEMM, K=3072)
    gemm_bf16_mma<<<dim3(4, 8), 256, GEMM_SMEM>>>(
        gWosS, gWvsT, gzero, nullptr, 0, gWeff, 1024, 1024, K1);
    split_Bhl<<<1024, 256>>>(gWeff, gW1 + (size_t)3072 * K1);

    bias_b1_kernel<<<4, 256>>>(bq, gb1);
    bs_eff_kernel<<<128, 256>>>(Wo_s, bv_s, bo_s, gb1);

    // GEMM1: C1[32768,4096] = Xs @ W1^T + b1   (Q | Kc | Vc | S)
    gemm_bf16_mma<<<dim3(N1 / 256, MTOT / 128), 256, GEMM_SMEM>>>(
        gXs, gW1, gb1, nullptr, 0, gC1, MTOT, N1, K1);

    // attention combine -> ctx bf16 split straight into A2
    combine_kernel<<<NB, 128>>>(gC1, bk_c, bv_c, gA2);

    // GEMM2: d = ctx @ Wo_c^T + bo_c + S   (S = C1 cols 3072..4095)
    gemm_bf16_mma<<<dim3(DD / 256, MTOT / 128), 256, GEMM_SMEM>>>(
        gA2, gWocS, bo_c, gC1 + 3072, N1, out, MTOT, DD, K1);

    // logits = d @ Wc^T + bc
    logits_kernel<<<MTOT / 8, 256>>>(out, Wc, bc, logits);
}

// round 6
// speedup vs baseline: 4.0105x; 1.2524x over previous
#include <cuda_runtime.h>
#include <cuda_bf16.h>
#include <cuda_fp16.h>
#include <cstdint>
#include <cstddef>

// ---------------------------------------------------------------------------
// MultiModalClassifier, GB300, mma.sync GEMMs with precision tiering.
//   B=8192, D=1024, H=4 (hd=256), C=4, M=32768
// Algebra:
//   self_out = X@(Wo_s@Wv_s)^T + (Wo_s@bv_s + bo_s)   [1-key softmax == 1]
//   cross: K_ij = Kc_i - Kc_j + bk_c, V_ij = Vc_i - Vc_j + bv_c
//   d = S + ctx@Wo_c^T + bo_c
// Precision tiers:
//   Q|Kc (scores only): single fp16, K=1024  (score err ~4e-4 -> out ~2e-4)
//   Vc|S, ctx, Weff   : bf16 3-term split, K=3072 (err ~2^-16)
// ---------------------------------------------------------------------------

#define NB 8192
#define DD 1024
#define MTOT 32768
#define HD 256
#define K1 3072
#define N2 2048

// ------------------------------ scratch ------------------------------------
__device__ __nv_bfloat16 g_Xs  [(size_t)MTOT * K1];   // 192 MB  (bf16 3-seg)
__device__ __half        g_Xh  [(size_t)MTOT * DD];   // 64 MB   (fp16 single)
__device__ __half        g_Wh  [(size_t)N2 * DD];     // 4 MB    (Wq;Wk_c fp16)
__device__ __nv_bfloat16 g_W1b [(size_t)N2 * K1];     // 12 MB   (Wv_c;Weff split)
__device__ float         g_C1a [(size_t)MTOT * N2];   // 256 MB  (Q|Kc)
__device__ float         g_C1b [(size_t)MTOT * N2];   // 256 MB  (Vc|S)
__device__ __nv_bfloat16 g_A2  [(size_t)MTOT * K1];   // 192 MB  (ctx split)
__device__ __nv_bfloat16 g_WocS[(size_t)DD * K1];     // 6 MB
__device__ __nv_bfloat16 g_WosS[(size_t)DD * K1];     // 6 MB
__device__ __nv_bfloat16 g_WvsT[(size_t)DD * K1];     // 6 MB
__device__ float         g_Weff[(size_t)DD * DD];     // 4 MB
__device__ float         g_b1a[N2];
__device__ float         g_b1b[N2];
__device__ float         g_zero[DD];                   // never written: zeros

// --------------------------- PTX helpers -----------------------------------
__device__ __forceinline__ uint32_t smem_u32(const void* p) {
    uint32_t a;
    asm("{ .reg .u64 t; cvta.to.shared.u64 t, %1; cvt.u32.u64 %0, t; }"
        : "=r"(a) : "l"(p));
    return a;
}

#define CP_ASYNC16(dst, src) \
    asm volatile("cp.async.cg.shared.global [%0], [%1], 16;" :: "r"(dst), "l"(src))
#define CP_COMMIT() asm volatile("cp.async.commit_group;" ::: "memory")
#define CP_WAIT(n)  asm volatile("cp.async.wait_group %0;" :: "n"(n) : "memory")

#define LDMATRIX_X4(r0, r1, r2, r3, addr)                                     \
    asm volatile("ldmatrix.sync.aligned.m8n8.x4.shared.b16 {%0,%1,%2,%3}, [%4];" \
                 : "=r"(r0), "=r"(r1), "=r"(r2), "=r"(r3) : "r"(addr))

#define MMA_BF16(d0, d1, d2, d3, a0, a1, a2, a3, b0, b1)                      \
    asm volatile("mma.sync.aligned.m16n8k16.row.col.f32.bf16.bf16.f32 "       \
                 "{%0,%1,%2,%3}, {%4,%5,%6,%7}, {%8,%9}, {%0,%1,%2,%3};"      \
                 : "+f"(d0), "+f"(d1), "+f"(d2), "+f"(d3)                     \
                 : "r"(a0), "r"(a1), "r"(a2), "r"(a3), "r"(b0), "r"(b1))

#define MMA_F16(d0, d1, d2, d3, a0, a1, a2, a3, b0, b1)                       \
    asm volatile("mma.sync.aligned.m16n8k16.row.col.f32.f16.f16.f32 "         \
                 "{%0,%1,%2,%3}, {%4,%5,%6,%7}, {%8,%9}, {%0,%1,%2,%3};"      \
                 : "+f"(d0), "+f"(d1), "+f"(d2), "+f"(d3)                     \
                 : "r"(a0), "r"(a1), "r"(a2), "r"(a3), "r"(b0), "r"(b1))

// --------------------------- GEMM kernel -----------------------------------
// C[M,N] = A[M,K] @ B[N,K]^T + bias (+ add), b16-typed in / fp32 out.
// CTA tile 128x256, BK=64, SW128 swizzle, 4-stage cp.async, 8 warps (2x4),
// warp tile 64x64. F16 selects fp16 mma (same fragments as bf16).
#define STAGES 4
#define STAGE_BYTES 49152          // A 16KB + B 32KB
#define GEMM_SMEM (STAGES * STAGE_BYTES)

__device__ __forceinline__ void load_stage(
    const uint16_t* __restrict__ A, const uint16_t* __restrict__ B,
    int K, int brow, int bcol, int kb, uint32_t st, int tid)
{
    #pragma unroll
    for (int i = 0; i < 12; i++) {
        int id = tid + 256 * i;
        if (id < 1024) {                       // A: 128 rows x 8 chunks
            int row = id >> 3, c = id & 7;
            const uint16_t* g = A + (size_t)(brow + row) * K + kb * 64 + c * 8;
            CP_ASYNC16(st + row * 128 + ((c ^ (row & 7)) * 16), g);
        } else {                               // B: 256 rows x 8 chunks
            int idb = id - 1024;
            int row = idb >> 3, c = idb & 7;
            const uint16_t* g = B + (size_t)(bcol + row) * K + kb * 64 + c * 8;
            CP_ASYNC16(st + 16384 + row * 128 + ((c ^ (row & 7)) * 16), g);
        }
    }
}

template <bool F16>
__global__ __launch_bounds__(256, 1)
void gemm_mma(const uint16_t* __restrict__ A,
              const uint16_t* __restrict__ B,
              const float* __restrict__ bias,
              const float* __restrict__ add, int add_ld,
              float* __restrict__ C, int M, int N, int K)
{
    extern __shared__ __align__(1024) char smem[];
    const uint32_t sbase = smem_u32(smem);
    const int tid  = threadIdx.x;
    const int wid  = tid >> 5, lane = tid & 31;
    const int wm   = wid >> 2, wn = wid & 3;     // 2 x 4 warps
    const int brow = blockIdx.y * 128, bcol = blockIdx.x * 256;
    const int NKB  = K >> 6;

    float acc[4][8][4];
    #pragma unroll
    for (int i = 0; i < 4; i++)
        #pragma unroll
        for (int j = 0; j < 8; j++)
            #pragma unroll
            for (int k = 0; k < 4; k++) acc[i][j][k] = 0.f;

    load_stage(A, B, K, brow, bcol, 0, sbase, tid);                  CP_COMMIT();
    load_stage(A, B, K, brow, bcol, 1, sbase + STAGE_BYTES, tid);    CP_COMMIT();
    load_stage(A, B, K, brow, bcol, 2, sbase + 2 * STAGE_BYTES, tid);CP_COMMIT();

    int a_off[4], a_sw[4];
    #pragma unroll
    for (int mt = 0; mt < 4; mt++) {
        int r = wm * 64 + mt * 16 + (lane & 15);
        a_off[mt] = r * 128; a_sw[mt] = r & 7;
    }
    const int a_kh = lane >> 4;
    int b_off[4], b_sw[4];
    #pragma unroll
    for (int np = 0; np < 4; np++) {
        int r = wn * 64 + np * 16 + ((lane >> 4) & 1) * 8 + (lane & 7);
        b_off[np] = r * 128; b_sw[np] = r & 7;
    }
    const int b_kh = (lane >> 3) & 1;

    for (int kb = 0; kb < NKB; kb++) {
        if (kb < NKB - 2)       CP_WAIT(2);
        else if (kb == NKB - 2) CP_WAIT(1);
        else                    CP_WAIT(0);
        __syncthreads();
        if (kb + 3 < NKB) {
            load_stage(A, B, K, brow, bcol, kb + 3,
                       sbase + ((kb + 3) & 3) * STAGE_BYTES, tid);
            CP_COMMIT();
        }
        const uint32_t sA = sbase + (kb & 3) * STAGE_BYTES;
        const uint32_t sB = sA + 16384;

        #pragma unroll
        for (int ks = 0; ks < 4; ks++) {
            uint32_t af[4][4], bf[4][4];
            #pragma unroll
            for (int mt = 0; mt < 4; mt++) {
                int cc = ks * 2 + a_kh;
                LDMATRIX_X4(af[mt][0], af[mt][1], af[mt][2], af[mt][3],
                            sA + a_off[mt] + ((cc ^ a_sw[mt]) * 16));
            }
            #pragma unroll
            for (int np = 0; np < 4; np++) {
                int cc = ks * 2 + b_kh;
                LDMATRIX_X4(bf[np][0], bf[np][1], bf[np][2], bf[np][3],
                            sB + b_off[np] + ((cc ^ b_sw[np]) * 16));
            }
            #pragma unroll
            for (int mt = 0; mt < 4; mt++)
                #pragma unroll
                for (int nt = 0; nt < 8; nt++) {
                    if (F16)
                        MMA_F16(acc[mt][nt][0], acc[mt][nt][1],
                                acc[mt][nt][2], acc[mt][nt][3],
                                af[mt][0], af[mt][1], af[mt][2], af[mt][3],
                                bf[nt >> 1][(nt & 1) * 2],
                                bf[nt >> 1][(nt & 1) * 2 + 1]);
                    else
                        MMA_BF16(acc[mt][nt][0], acc[mt][nt][1],
                                 acc[mt][nt][2], acc[mt][nt][3],
                                 af[mt][0], af[mt][1], af[mt][2], af[mt][3],
                                 bf[nt >> 1][(nt & 1) * 2],
                                 bf[nt >> 1][(nt & 1) * 2 + 1]);
                }
        }
    }

    #pragma unroll
    for (int mt = 0; mt < 4; mt++) {
        const int r0 = brow + wm * 64 + mt * 16 + (lane >> 2);
        #pragma unroll
        for (int nt = 0; nt < 8; nt++) {
            const int c0 = bcol + wn * 64 + nt * 8 + (lane & 3) * 2;
            const float bx = bias[c0], by = bias[c0 + 1];
            float a0 = acc[mt][nt][0] + bx, a1 = acc[mt][nt][1] + by;
            float a2 = acc[mt][nt][2] + bx, a3 = acc[mt][nt][3] + by;
            if (add) {
                a0 += add[(size_t)r0 * add_ld + c0];
                a1 += add[(size_t)r0 * add_ld + c0 + 1];
                a2 += add[(size_t)(r0 + 8) * add_ld + c0];
                a3 += add[(size_t)(r0 + 8) * add_ld + c0 + 1];
            }
            float2 v0 = { a0, a1 }, v1 = { a2, a3 };
            *(float2*)&C[(size_t)r0 * N + c0]       = v0;
            *(float2*)&C[(size_t)(r0 + 8) * N + c0] = v1;
        }
    }
}

// --------------------------- split kernels ---------------------------------
__device__ __forceinline__ void split1(float a, __nv_bfloat16& h, __nv_bfloat16& l) {
    h = __float2bfloat16(a);
    l = __float2bfloat16(a - __bfloat162float(h));
}

// A-operand layout [hi|lo|hi]
__global__ __launch_bounds__(256) void split_Ahl(
    const float* __restrict__ src, __nv_bfloat16* __restrict__ dst)
{
    size_t idx = (size_t)blockIdx.x * blockDim.x + threadIdx.x;
    size_t n = idx >> 8;
    int c4 = (int)(idx & 255) * 4;
    float4 v = *(const float4*)&src[n * DD + c4];
    __nv_bfloat16 h[4], l[4];
    split1(v.x, h[0], l[0]); split1(v.y, h[1], l[1]);
    split1(v.z, h[2], l[2]); split1(v.w, h[3], l[3]);
    __nv_bfloat16* row = dst + n * K1;
    *(uint2*)&row[c4]          = *(uint2*)h;
    *(uint2*)&row[DD + c4]     = *(uint2*)l;
    *(uint2*)&row[2 * DD + c4] = *(uint2*)h;
}

// B-operand layout [hi|hi|lo]
__global__ __launch_bounds__(256) void split_Bhl(
    const float* __restrict__ src, __nv_bfloat16* __restrict__ dst)
{
    size_t idx = (size_t)blockIdx.x * blockDim.x + threadIdx.x;
    size_t n = idx >> 8;
    int c4 = (int)(idx & 255) * 4;
    float4 v = *(const float4*)&src[n * DD + c4];
    __nv_bfloat16 h[4], l[4];
    split1(v.x, h[0], l[0]); split1(v.y, h[1], l[1]);
    split1(v.z, h[2], l[2]); split1(v.w, h[3], l[3]);
    __nv_bfloat16* row = dst + n * K1;
    *(uint2*)&row[c4]          = *(uint2*)h;
    *(uint2*)&row[DD + c4]     = *(uint2*)h;
    *(uint2*)&row[2 * DD + c4] = *(uint2*)l;
}

// fp32 -> fp16 row copy (1024-col matrices)
__global__ __launch_bounds__(256) void to_half_kernel(
    const float* __restrict__ src, __half* __restrict__ dst)
{
    size_t idx = (size_t)blockIdx.x * blockDim.x + threadIdx.x;
    float4 v = *(const float4*)&src[idx * 4];
    __half h[4] = { __float2half(v.x), __float2half(v.y),
                    __float2half(v.z), __float2half(v.w) };
    *(uint2*)&dst[idx * 4] = *(uint2*)h;
}

// WvsT[i,m] = Wvs[m,i], B layout [hi|hi|lo]
__global__ __launch_bounds__(256) void transpose_split_B(
    const float* __restrict__ Wvs, __nv_bfloat16* __restrict__ dst)
{
    size_t idx = (size_t)blockIdx.x * blockDim.x + threadIdx.x;
    int m = (int)(idx >> 10);
    int i = (int)(idx & 1023);
    float v = Wvs[(size_t)m * DD + i];
    __nv_bfloat16 h, l; split1(v, h, l);
    __nv_bfloat16* row = dst + (size_t)i * K1;
    row[m] = h; row[DD + m] = h; row[2 * DD + m] = l;
}

// Xs = [hi|lo|hi] of stacked X (bf16), Xh = fp16 single
__global__ __launch_bounds__(256) void split_X_kernel(
    const float* __restrict__ X1, const float* __restrict__ X2,
    const float* __restrict__ X3, const float* __restrict__ X4,
    __nv_bfloat16* __restrict__ Xs, __half* __restrict__ Xh)
{
    size_t idx = (size_t)blockIdx.x * blockDim.x + threadIdx.x;
    size_t r = idx >> 8;
    int c4 = (int)(idx & 255) * 4;
    const float* src = (r < NB) ? X1 : (r < 2 * NB) ? X2 : (r < 3 * NB) ? X3 : X4;
    float4 v = *(const float4*)&src[(r & (NB - 1)) * DD + c4];
    __nv_bfloat16 h[4], l[4];
    split1(v.x, h[0], l[0]); split1(v.y, h[1], l[1]);
    split1(v.z, h[2], l[2]); split1(v.w, h[3], l[3]);
    __nv_bfloat16* row = Xs + r * K1;
    *(uint2*)&row[c4]          = *(uint2*)h;
    *(uint2*)&row[DD + c4]     = *(uint2*)l;
    *(uint2*)&row[2 * DD + c4] = *(uint2*)h;
    __half hf[4] = { __float2half(v.x), __float2half(v.y),
                     __float2half(v.z), __float2half(v.w) };
    *(uint2*)&Xh[r * DD + c4] = *(uint2*)hf;
}

// --------------------------- bias kernels ----------------------------------
__device__ __forceinline__ float wsum(float v) {
    #pragma unroll
    for (int o = 16; o; o >>= 1) v += __shfl_xor_sync(0xffffffffu, v, o);
    return v;
}

__global__ __launch_bounds__(256) void bias_init_kernel(
    const float* __restrict__ bq, float* __restrict__ b1a, float* __restrict__ b1b)
{
    int i = blockIdx.x * blockDim.x + threadIdx.x;
    if (i < DD) { b1a[i] = bq[i]; b1a[DD + i] = 0.f; b1b[i] = 0.f; }
}

// b1b[1024+o] = dot(Wos[o,:], bvs) + bos[o]
__global__ __launch_bounds__(256) void bs_eff_kernel(
    const float* __restrict__ Wos, const float* __restrict__ bvs,
    const float* __restrict__ bos, float* __restrict__ b1b)
{
    int o = blockIdx.x * 8 + (threadIdx.x >> 5);
    int lane = threadIdx.x & 31;
    float s = 0.f;
    for (int k = lane; k < DD; k += 32)
        s = fmaf(Wos[(size_t)o * DD + k], bvs[k], s);
    s = wsum(s);
    if (lane == 0) b1b[DD + o] = s + bos[o];
}

// --------------------------- combine ---------------------------------------
// ctx_i = Vc_i + bv_c - sum_j a_ij Vc_j, written as bf16 split into A2.
__global__ __launch_bounds__(128) void combine_kernel(
    const float* __restrict__ C1a,   // Q | Kc  (ld 2048)
    const float* __restrict__ C1b,   // Vc | S  (ld 2048)
    const float* __restrict__ bk, const float* __restrict__ bv,
    __nv_bfloat16* __restrict__ A2)
{
    const int b    = blockIdx.x;
    const int h    = threadIdx.x >> 5;
    const int lane = threadIdx.x & 31;
    const int base_d = h * HD + lane;

    float q[4][8], kc[4][8], vc[4][8];
    #pragma unroll
    for (int i = 0; i < 4; i++) {
        size_t row = (size_t)(i * NB + b) * N2 + base_d;
        #pragma unroll
        for (int e = 0; e < 8; e++) {
            q [i][e] = C1a[row + e * 32];
            kc[i][e] = C1a[row + 1024 + e * 32];
            vc[i][e] = C1b[row + e * 32];
        }
    }
    float bke[8], bve[8];
    #pragma unroll
    for (int e = 0; e < 8; e++) {
        bke[e] = bk[base_d + e * 32];
        bve[e] = bv[base_d + e * 32];
    }

    float a[4][4];
    #pragma unroll
    for (int i = 0; i < 4; i++) {
        float s[4];
        #pragma unroll
        for (int j = 0; j < 4; j++) {
            float p = 0.f;
            #pragma unroll
            for (int e = 0; e < 8; e++)
                p = fmaf(q[i][e], kc[i][e] - kc[j][e] + bke[e], p);
            s[j] = wsum(p) * (1.f / 16.f);
        }
        float m = -1e30f;
        #pragma unroll
        for (int j = 0; j < 4; j++) if (j != i && s[j] > m) m = s[j];
        float den = 0.f;
        #pragma unroll
        for (int j = 0; j < 4; j++) {
            float ex = (j == i) ? 0.f : __expf(s[j] - m);
            a[i][j] = ex; den += ex;
        }
        float inv = 1.f / den;
        #pragma unroll
        for (int j = 0; j < 4; j++) a[i][j] *= inv;
    }

    #pragma unroll
    for (int i = 0; i < 4; i++) {
        __nv_bfloat16* row = A2 + (size_t)(i * NB + b) * K1;
        #pragma unroll
        for (int e = 0; e < 8; e++) {
            float c = vc[i][e] + bve[e];
            #pragma unroll
            for (int j = 0; j < 4; j++)
                c = fmaf(-a[i][j], vc[j][e], c);
            int col = base_d + e * 32;
            __nv_bfloat16 hh, ll; split1(c, hh, ll);
            row[col] = hh; row[DD + col] = ll; row[2 * DD + col] = hh;
        }
    }
}

// --------------------------- logits ----------------------------------------
__global__ __launch_bounds__(256) void logits_kernel(
    const float* __restrict__ D, const float* __restrict__ Wc,
    const float* __restrict__ bc, float* __restrict__ out)
{
    const int warp = (blockIdx.x * blockDim.x + threadIdx.x) >> 5;
    const int lane = threadIdx.x & 31;
    if (warp >= MTOT) return;
    const float* drow = D + (size_t)warp * DD;
    float s0 = 0.f, s1 = 0.f, s2 = 0.f, s3 = 0.f;
    for (int k = lane; k < DD; k += 32) {
        float d = drow[k];
        s0 = fmaf(d, Wc[k],          s0);
        s1 = fmaf(d, Wc[DD + k],     s1);
        s2 = fmaf(d, Wc[2 * DD + k], s2);
        s3 = fmaf(d, Wc[3 * DD + k], s3);
    }
    s0 = wsum(s0); s1 = wsum(s1); s2 = wsum(s2); s3 = wsum(s3);
    if (lane == 0) {
        out[(size_t)warp * 4 + 0] = s0 + bc[0];
        out[(size_t)warp * 4 + 1] = s1 + bc[1];
        out[(size_t)warp * 4 + 2] = s2 + bc[2];
        out[(size_t)warp * 4 + 3] = s3 + bc[3];
    }
}

// ---------------------------------------------------------------------------
extern "C" void kernel_launch(void* const* d_in, const int* in_sizes, int n_in,
                              void* d_out, int out_size)
{
    const float* X1   = (const float*)d_in[0];
    const float* X2   = (const float*)d_in[1];
    const float* X3   = (const float*)d_in[2];
    const float* X4   = (const float*)d_in[3];
    const float* Wq   = (const float*)d_in[4];
    const float* bq   = (const float*)d_in[5];
    const float* Wv_s = (const float*)d_in[8];
    const float* bv_s = (const float*)d_in[9];
    const float* Wo_s = (const float*)d_in[10];
    const float* bo_s = (const float*)d_in[11];
    const float* Wk_c = (const float*)d_in[12];
    const float* bk_c = (const float*)d_in[13];
    const float* Wv_c = (const float*)d_in[14];
    const float* bv_c = (const float*)d_in[15];
    const float* Wo_c = (const float*)d_in[16];
    const float* bo_c = (const float*)d_in[17];
    const float* Wc   = (const float*)d_in[18];
    const float* bc   = (const float*)d_in[19];

    float* out    = (float*)d_out;
    float* logits = out + (size_t)MTOT * DD;

    __nv_bfloat16 *gXs, *gW1b, *gA2, *gWocS, *gWosS, *gWvsT;
    __half *gXh, *gWh;
    float *gC1a, *gC1b, *gWeff, *gb1a, *gb1b, *gzero;
    cudaGetSymbolAddress((void**)&gXs,   g_Xs);
    cudaGetSymbolAddress((void**)&gXh,   g_Xh);
    cudaGetSymbolAddress((void**)&gWh,   g_Wh);
    cudaGetSymbolAddress((void**)&gW1b,  g_W1b);
    cudaGetSymbolAddress((void**)&gC1a,  g_C1a);
    cudaGetSymbolAddress((void**)&gC1b,  g_C1b);
    cudaGetSymbolAddress((void**)&gA2,   g_A2);
    cudaGetSymbolAddress((void**)&gWocS, g_WocS);
    cudaGetSymbolAddress((void**)&gWosS, g_WosS);
    cudaGetSymbolAddress((void**)&gWvsT, g_WvsT);
    cudaGetSymbolAddress((void**)&gWeff, g_Weff);
    cudaGetSymbolAddress((void**)&gb1a,  g_b1a);
    cudaGetSymbolAddress((void**)&gb1b,  g_b1b);
    cudaGetSymbolAddress((void**)&gzero, g_zero);

    cudaFuncSetAttribute(gemm_mma<false>,
                         cudaFuncAttributeMaxDynamicSharedMemorySize, GEMM_SMEM);
    cudaFuncSetAttribute(gemm_mma<true>,
                         cudaFuncAttributeMaxDynamicSharedMemorySize, GEMM_SMEM);

    // prep: splits + fp16 copies + weight-space fold of the self path
    split_X_kernel<<<MTOT, 256>>>(X1, X2, X3, X4, gXs, gXh);
    to_half_kernel<<<1024, 256>>>(Wq,   gWh);
    to_half_kernel<<<1024, 256>>>(Wk_c, gWh + (size_t)1024 * DD);
    split_Bhl<<<1024, 256>>>(Wv_c, gW1b);
    split_Bhl<<<1024, 256>>>(Wo_c, gWocS);
    split_Ahl<<<1024, 256>>>(Wo_s, gWosS);
    transpose_split_B<<<4096, 256>>>(Wv_s, gWvsT);

    // Weff[o,i] = sum_m Wos[o,m] * Wvs[m,i]   (tiny split GEMM, K=3072)
    gemm_mma<false><<<dim3(4, 8), 256, GEMM_SMEM>>>(
        (const uint16_t*)gWosS, (const uint16_t*)gWvsT, gzero, nullptr, 0,
        gWeff, 1024, 1024, K1);
    split_Bhl<<<1024, 256>>>(gWeff, gW1b + (size_t)1024 * K1);

    bias_init_kernel<<<4, 256>>>(bq, gb1a, gb1b);
    bs_eff_kernel<<<128, 256>>>(Wo_s, bv_s, bo_s, gb1b);

    // score GEMM (fp16 single): C1a[32768,2048] = Xh @ [Wq;Wk_c]^T + [bq|0]
    gemm_mma<true><<<dim3(N2 / 256, MTOT / 128), 256, GEMM_SMEM>>>(
        (const uint16_t*)gXh, (const uint16_t*)gWh, gb1a, nullptr, 0,
        gC1a, MTOT, N2, DD);

    // value GEMM (bf16 3-term): C1b[32768,2048] = Xs @ [Wv_c;Weff]^T + [0|bS]
    gemm_mma<false><<<dim3(N2 / 256, MTOT / 128), 256, GEMM_SMEM>>>(
        (const uint16_t*)gXs, (const uint16_t*)gW1b, gb1b, nullptr, 0,
        gC1b, MTOT, N2, K1);

    // attention combine -> ctx bf16 split straight into A2
    combine_kernel<<<NB, 128>>>(gC1a, gC1b, bk_c, bv_c, gA2);

    // GEMM2: d = ctx @ Wo_c^T + bo_c + S   (S = C1b cols 1024..2047)
    gemm_mma<false><<<dim3(DD / 256, MTOT / 128), 256, GEMM_SMEM>>>(
        (const uint16_t*)gA2, (const uint16_t*)gWocS, bo_c, gC1b + 1024, N2,
        out, MTOT, DD, K1);

    // logits = d @ Wc^T + bc
    logits_kernel<<<MTOT / 8, 256>>>(out, Wc, bc, logits);
}

// round 7
// speedup vs baseline: 5.6308x; 1.4040x over previous
#include <cuda_runtime.h>
#include <cuda_bf16.h>
#include <cuda_fp16.h>
#include <cstdint>
#include <cstddef>

// ---------------------------------------------------------------------------
// MultiModalClassifier, GB300, mma.sync GEMMs with precision tiering.
//   B=8192, D=1024, H=4 (hd=256), C=4, M=32768
// Algebra:
//   self_out = X@(Wo_s@Wv_s)^T + (Wo_s@bv_s + bo_s)   [1-key softmax == 1]
//   cross: K_ij = Kc_i - Kc_j + bk_c, V_ij = Vc_i - Vc_j + bv_c
//   d = S + ctx@Wo_c^T + bo_c
// Precision tiers (R6 measured: fp16 scores added only ~4e-5):
//   Q|Kc|Vc + GEMM2 : single fp16, K=1024
//   S (self path)    : bf16 3-term split, K=3072 (err ~2^-16), Weff likewise
// ---------------------------------------------------------------------------

#define NB 8192
#define DD 1024
#define MTOT 32768
#define HD 256
#define K1 3072
#define N1A 3072          // Q | Kc | Vc

// ------------------------------ scratch ------------------------------------
__device__ __nv_bfloat16 g_Xs  [(size_t)MTOT * K1];    // 192 MB (bf16 3-seg)
__device__ __half        g_Xh  [(size_t)MTOT * DD];    // 64 MB  (fp16 single)
__device__ __half        g_Wh  [(size_t)4096 * DD];    // 8 MB   (Wq;Wkc;Wvc;Woc)
__device__ __nv_bfloat16 g_W1s [(size_t)DD * K1];      // 6 MB   (Weff split)
__device__ float         g_C1a [(size_t)MTOT * N1A];   // 384 MB (Q|Kc|Vc)
__device__ float         g_S   [(size_t)MTOT * DD];    // 128 MB (self path)
__device__ __half        g_A2h [(size_t)MTOT * DD];    // 64 MB  (ctx fp16)
__device__ __nv_bfloat16 g_WosS[(size_t)DD * K1];      // 6 MB
__device__ __nv_bfloat16 g_WvsT[(size_t)DD * K1];      // 6 MB
__device__ float         g_Weff[(size_t)DD * DD];      // 4 MB
__device__ float         g_b1a[N1A];
__device__ float         g_b1s[DD];
__device__ float         g_zero[DD];                    // never written: zeros

// --------------------------- PTX helpers -----------------------------------
__device__ __forceinline__ uint32_t smem_u32(const void* p) {
    uint32_t a;
    asm("{ .reg .u64 t; cvta.to.shared.u64 t, %1; cvt.u32.u64 %0, t; }"
        : "=r"(a) : "l"(p));
    return a;
}

#define CP_ASYNC16(dst, src) \
    asm volatile("cp.async.cg.shared.global [%0], [%1], 16;" :: "r"(dst), "l"(src))
#define CP_COMMIT() asm volatile("cp.async.commit_group;" ::: "memory")
#define CP_WAIT(n)  asm volatile("cp.async.wait_group %0;" :: "n"(n) : "memory")

#define LDMATRIX_X4(r0, r1, r2, r3, addr)                                     \
    asm volatile("ldmatrix.sync.aligned.m8n8.x4.shared.b16 {%0,%1,%2,%3}, [%4];" \
                 : "=r"(r0), "=r"(r1), "=r"(r2), "=r"(r3) : "r"(addr))

#define MMA_BF16(d0, d1, d2, d3, a0, a1, a2, a3, b0, b1)                      \
    asm volatile("mma.sync.aligned.m16n8k16.row.col.f32.bf16.bf16.f32 "       \
                 "{%0,%1,%2,%3}, {%4,%5,%6,%7}, {%8,%9}, {%0,%1,%2,%3};"      \
                 : "+f"(d0), "+f"(d1), "+f"(d2), "+f"(d3)                     \
                 : "r"(a0), "r"(a1), "r"(a2), "r"(a3), "r"(b0), "r"(b1))

#define MMA_F16(d0, d1, d2, d3, a0, a1, a2, a3, b0, b1)                       \
    asm volatile("mma.sync.aligned.m16n8k16.row.col.f32.f16.f16.f32 "         \
                 "{%0,%1,%2,%3}, {%4,%5,%6,%7}, {%8,%9}, {%0,%1,%2,%3};"      \
                 : "+f"(d0), "+f"(d1), "+f"(d2), "+f"(d3)                     \
                 : "r"(a0), "r"(a1), "r"(a2), "r"(a3), "r"(b0), "r"(b1))

// --------------------------- GEMM kernel -----------------------------------
// C[M,N] = A[M,K] @ B[N,K]^T + bias (+ add), b16-typed in / fp32 out.
// CTA tile 128x256, BK=64, SW128 swizzle, 4-stage cp.async, 8 warps (2x4),
// warp tile 64x64. F16 selects fp16 mma (same fragments as bf16).
#define STAGES 4
#define STAGE_BYTES 49152          // A 16KB + B 32KB
#define GEMM_SMEM (STAGES * STAGE_BYTES)

__device__ __forceinline__ void load_stage(
    const uint16_t* __restrict__ A, const uint16_t* __restrict__ B,
    int K, int brow, int bcol, int kb, uint32_t st, int tid)
{
    #pragma unroll
    for (int i = 0; i < 12; i++) {
        int id = tid + 256 * i;
        if (id < 1024) {                       // A: 128 rows x 8 chunks
            int row = id >> 3, c = id & 7;
            const uint16_t* g = A + (size_t)(brow + row) * K + kb * 64 + c * 8;
            CP_ASYNC16(st + row * 128 + ((c ^ (row & 7)) * 16), g);
        } else {                               // B: 256 rows x 8 chunks
            int idb = id - 1024;
            int row = idb >> 3, c = idb & 7;
            const uint16_t* g = B + (size_t)(bcol + row) * K + kb * 64 + c * 8;
            CP_ASYNC16(st + 16384 + row * 128 + ((c ^ (row & 7)) * 16), g);
        }
    }
}

template <bool F16>
__global__ __launch_bounds__(256, 1)
void gemm_mma(const uint16_t* __restrict__ A,
              const uint16_t* __restrict__ B,
              const float* __restrict__ bias,
              const float* __restrict__ add, int add_ld,
              float* __restrict__ C, int M, int N, int K)
{
    extern __shared__ __align__(1024) char smem[];
    const uint32_t sbase = smem_u32(smem);
    const int tid  = threadIdx.x;
    const int wid  = tid >> 5, lane = tid & 31;
    const int wm   = wid >> 2, wn = wid & 3;     // 2 x 4 warps
    const int brow = blockIdx.y * 128, bcol = blockIdx.x * 256;
    const int NKB  = K >> 6;

    float acc[4][8][4];
    #pragma unroll
    for (int i = 0; i < 4; i++)
        #pragma unroll
        for (int j = 0; j < 8; j++)
            #pragma unroll
            for (int k = 0; k < 4; k++) acc[i][j][k] = 0.f;

    load_stage(A, B, K, brow, bcol, 0, sbase, tid);                  CP_COMMIT();
    load_stage(A, B, K, brow, bcol, 1, sbase + STAGE_BYTES, tid);    CP_COMMIT();
    load_stage(A, B, K, brow, bcol, 2, sbase + 2 * STAGE_BYTES, tid);CP_COMMIT();

    int a_off[4], a_sw[4];
    #pragma unroll
    for (int mt = 0; mt < 4; mt++) {
        int r = wm * 64 + mt * 16 + (lane & 15);
        a_off[mt] = r * 128; a_sw[mt] = r & 7;
    }
    const int a_kh = lane >> 4;
    int b_off[4], b_sw[4];
    #pragma unroll
    for (int np = 0; np < 4; np++) {
        int r = wn * 64 + np * 16 + ((lane >> 4) & 1) * 8 + (lane & 7);
        b_off[np] = r * 128; b_sw[np] = r & 7;
    }
    const int b_kh = (lane >> 3) & 1;

    for (int kb = 0; kb < NKB; kb++) {
        if (kb < NKB - 2)       CP_WAIT(2);
        else if (kb == NKB - 2) CP_WAIT(1);
        else                    CP_WAIT(0);
        __syncthreads();
        if (kb + 3 < NKB) {
            load_stage(A, B, K, brow, bcol, kb + 3,
                       sbase + ((kb + 3) & 3) * STAGE_BYTES, tid);
            CP_COMMIT();
        }
        const uint32_t sA = sbase + (kb & 3) * STAGE_BYTES;
        const uint32_t sB = sA + 16384;

        #pragma unroll
        for (int ks = 0; ks < 4; ks++) {
            uint32_t af[4][4], bf[4][4];
            #pragma unroll
            for (int mt = 0; mt < 4; mt++) {
                int cc = ks * 2 + a_kh;
                LDMATRIX_X4(af[mt][0], af[mt][1], af[mt][2], af[mt][3],
                            sA + a_off[mt] + ((cc ^ a_sw[mt]) * 16));
            }
            #pragma unroll
            for (int np = 0; np < 4; np++) {
                int cc = ks * 2 + b_kh;
                LDMATRIX_X4(bf[np][0], bf[np][1], bf[np][2], bf[np][3],
                            sB + b_off[np] + ((cc ^ b_sw[np]) * 16));
            }
            #pragma unroll
            for (int mt = 0; mt < 4; mt++)
                #pragma unroll
                for (int nt = 0; nt < 8; nt++) {
                    if (F16)
                        MMA_F16(acc[mt][nt][0], acc[mt][nt][1],
                                acc[mt][nt][2], acc[mt][nt][3],
                                af[mt][0], af[mt][1], af[mt][2], af[mt][3],
                                bf[nt >> 1][(nt & 1) * 2],
                                bf[nt >> 1][(nt & 1) * 2 + 1]);
                    else
                        MMA_BF16(acc[mt][nt][0], acc[mt][nt][1],
                                 acc[mt][nt][2], acc[mt][nt][3],
                                 af[mt][0], af[mt][1], af[mt][2], af[mt][3],
                                 bf[nt >> 1][(nt & 1) * 2],
                                 bf[nt >> 1][(nt & 1) * 2 + 1]);
                }
        }
    }

    #pragma unroll
    for (int mt = 0; mt < 4; mt++) {
        const int r0 = brow + wm * 64 + mt * 16 + (lane >> 2);
        #pragma unroll
        for (int nt = 0; nt < 8; nt++) {
            const int c0 = bcol + wn * 64 + nt * 8 + (lane & 3) * 2;
            const float bx = bias[c0], by = bias[c0 + 1];
            float a0 = acc[mt][nt][0] + bx, a1 = acc[mt][nt][1] + by;
            float a2 = acc[mt][nt][2] + bx, a3 = acc[mt][nt][3] + by;
            if (add) {
                a0 += add[(size_t)r0 * add_ld + c0];
                a1 += add[(size_t)r0 * add_ld + c0 + 1];
                a2 += add[(size_t)(r0 + 8) * add_ld + c0];
                a3 += add[(size_t)(r0 + 8) * add_ld + c0 + 1];
            }
            float2 v0 = { a0, a1 }, v1 = { a2, a3 };
            *(float2*)&C[(size_t)r0 * N + c0]       = v0;
            *(float2*)&C[(size_t)(r0 + 8) * N + c0] = v1;
        }
    }
}

// --------------------------- split kernels ---------------------------------
__device__ __forceinline__ void split1(float a, __nv_bfloat16& h, __nv_bfloat16& l) {
    h = __float2bfloat16(a);
    l = __float2bfloat16(a - __bfloat162float(h));
}

// A-operand layout [hi|lo|hi]
__global__ __launch_bounds__(256) void split_Ahl(
    const float* __restrict__ src, __nv_bfloat16* __restrict__ dst)
{
    size_t idx = (size_t)blockIdx.x * blockDim.x + threadIdx.x;
    size_t n = idx >> 8;
    int c4 = (int)(idx & 255) * 4;
    float4 v = *(const float4*)&src[n * DD + c4];
    __nv_bfloat16 h[4], l[4];
    split1(v.x, h[0], l[0]); split1(v.y, h[1], l[1]);
    split1(v.z, h[2], l[2]); split1(v.w, h[3], l[3]);
    __nv_bfloat16* row = dst + n * K1;
    *(uint2*)&row[c4]          = *(uint2*)h;
    *(uint2*)&row[DD + c4]     = *(uint2*)l;
    *(uint2*)&row[2 * DD + c4] = *(uint2*)h;
}

// B-operand layout [hi|hi|lo]
__global__ __launch_bounds__(256) void split_Bhl(
    const float* __restrict__ src, __nv_bfloat16* __restrict__ dst)
{
    size_t idx = (size_t)blockIdx.x * blockDim.x + threadIdx.x;
    size_t n = idx >> 8;
    int c4 = (int)(idx & 255) * 4;
    float4 v = *(const float4*)&src[n * DD + c4];
    __nv_bfloat16 h[4], l[4];
    split1(v.x, h[0], l[0]); split1(v.y, h[1], l[1]);
    split1(v.z, h[2], l[2]); split1(v.w, h[3], l[3]);
    __nv_bfloat16* row = dst + n * K1;
    *(uint2*)&row[c4]          = *(uint2*)h;
    *(uint2*)&row[DD + c4]     = *(uint2*)h;
    *(uint2*)&row[2 * DD + c4] = *(uint2*)l;
}

// fp32 -> fp16 row copy (1024-col matrices)
__global__ __launch_bounds__(256) void to_half_kernel(
    const float* __restrict__ src, __half* __restrict__ dst)
{
    size_t idx = (size_t)blockIdx.x * blockDim.x + threadIdx.x;
    float4 v = *(const float4*)&src[idx * 4];
    __half h[4] = { __float2half(v.x), __float2half(v.y),
                    __float2half(v.z), __float2half(v.w) };
    *(uint2*)&dst[idx * 4] = *(uint2*)h;
}

// WvsT[i,m] = Wvs[m,i], B layout [hi|hi|lo]
__global__ __launch_bounds__(256) void transpose_split_B(
    const float* __restrict__ Wvs, __nv_bfloat16* __restrict__ dst)
{
    size_t idx = (size_t)blockIdx.x * blockDim.x + threadIdx.x;
    int m = (int)(idx >> 10);
    int i = (int)(idx & 1023);
    float v = Wvs[(size_t)m * DD + i];
    __nv_bfloat16 h, l; split1(v, h, l);
    __nv_bfloat16* row = dst + (size_t)i * K1;
    row[m] = h; row[DD + m] = h; row[2 * DD + m] = l;
}

// Xs = [hi|lo|hi] of stacked X (bf16), Xh = fp16 single
__global__ __launch_bounds__(256) void split_X_kernel(
    const float* __restrict__ X1, const float* __restrict__ X2,
    const float* __restrict__ X3, const float* __restrict__ X4,
    __nv_bfloat16* __restrict__ Xs, __half* __restrict__ Xh)
{
    size_t idx = (size_t)blockIdx.x * blockDim.x + threadIdx.x;
    size_t r = idx >> 8;
    int c4 = (int)(idx & 255) * 4;
    const float* src = (r < NB) ? X1 : (r < 2 * NB) ? X2 : (r < 3 * NB) ? X3 : X4;
    float4 v = *(const float4*)&src[(r & (NB - 1)) * DD + c4];
    __nv_bfloat16 h[4], l[4];
    split1(v.x, h[0], l[0]); split1(v.y, h[1], l[1]);
    split1(v.z, h[2], l[2]); split1(v.w, h[3], l[3]);
    __nv_bfloat16* row = Xs + r * K1;
    *(uint2*)&row[c4]          = *(uint2*)h;
    *(uint2*)&row[DD + c4]     = *(uint2*)l;
    *(uint2*)&row[2 * DD + c4] = *(uint2*)h;
    __half hf[4] = { __float2half(v.x), __float2half(v.y),
                     __float2half(v.z), __float2half(v.w) };
    *(uint2*)&Xh[r * DD + c4] = *(uint2*)hf;
}

// --------------------------- bias kernels ----------------------------------
__device__ __forceinline__ float wsum(float v) {
    #pragma unroll
    for (int o = 16; o; o >>= 1) v += __shfl_xor_sync(0xffffffffu, v, o);
    return v;
}

__global__ __launch_bounds__(256) void bias_init_kernel(
    const float* __restrict__ bq, float* __restrict__ b1a)
{
    int i = blockIdx.x * blockDim.x + threadIdx.x;
    if (i < DD) { b1a[i] = bq[i]; b1a[DD + i] = 0.f; b1a[2 * DD + i] = 0.f; }
}

// b1s[o] = dot(Wos[o,:], bvs) + bos[o]
__global__ __launch_bounds__(256) void bs_eff_kernel(
    const float* __restrict__ Wos, const float* __restrict__ bvs,
    const float* __restrict__ bos, float* __restrict__ b1s)
{
    int o = blockIdx.x * 8 + (threadIdx.x >> 5);
    int lane = threadIdx.x & 31;
    float s = 0.f;
    for (int k = lane; k < DD; k += 32)
        s = fmaf(Wos[(size_t)o * DD + k], bvs[k], s);
    s = wsum(s);
    if (lane == 0) b1s[o] = s + bos[o];
}

// --------------------------- combine ---------------------------------------
// ctx_i = Vc_i + bv_c - sum_j a_ij Vc_j, written as fp16 into A2h.
__global__ __launch_bounds__(128) void combine_kernel(
    const float* __restrict__ C1a,   // Q | Kc | Vc  (ld 3072)
    const float* __restrict__ bk, const float* __restrict__ bv,
    __half* __restrict__ A2h)
{
    const int b    = blockIdx.x;
    const int h    = threadIdx.x >> 5;
    const int lane = threadIdx.x & 31;
    const int base_d = h * HD + lane;

    float q[4][8], kc[4][8], vc[4][8];
    #pragma unroll
    for (int i = 0; i < 4; i++) {
        size_t row = (size_t)(i * NB + b) * N1A + base_d;
        #pragma unroll
        for (int e = 0; e < 8; e++) {
            q [i][e] = C1a[row + e * 32];
            kc[i][e] = C1a[row + 1024 + e * 32];
            vc[i][e] = C1a[row + 2048 + e * 32];
        }
    }
    float bke[8], bve[8];
    #pragma unroll
    for (int e = 0; e < 8; e++) {
        bke[e] = bk[base_d + e * 32];
        bve[e] = bv[base_d + e * 32];
    }

    float a[4][4];
    #pragma unroll
    for (int i = 0; i < 4; i++) {
        float s[4];
        #pragma unroll
        for (int j = 0; j < 4; j++) {
            float p = 0.f;
            #pragma unroll
            for (int e = 0; e < 8; e++)
                p = fmaf(q[i][e], kc[i][e] - kc[j][e] + bke[e], p);
            s[j] = wsum(p) * (1.f / 16.f);
        }
        float m = -1e30f;
        #pragma unroll
        for (int j = 0; j < 4; j++) if (j != i && s[j] > m) m = s[j];
        float den = 0.f;
        #pragma unroll
        for (int j = 0; j < 4; j++) {
            float ex = (j == i) ? 0.f : __expf(s[j] - m);
            a[i][j] = ex; den += ex;
        }
        float inv = 1.f / den;
        #pragma unroll
        for (int j = 0; j < 4; j++) a[i][j] *= inv;
    }

    #pragma unroll
    for (int i = 0; i < 4; i++) {
        __half* row = A2h + (size_t)(i * NB + b) * DD;
        #pragma unroll
        for (int e = 0; e < 8; e++) {
            float c = vc[i][e] + bve[e];
            #pragma unroll
            for (int j = 0; j < 4; j++)
                c = fmaf(-a[i][j], vc[j][e], c);
            row[base_d + e * 32] = __float2half(c);
        }
    }
}

// --------------------------- logits ----------------------------------------
__global__ __launch_bounds__(256) void logits_kernel(
    const float* __restrict__ D, const float* __restrict__ Wc,
    const float* __restrict__ bc, float* __restrict__ out)
{
    const int warp = (blockIdx.x * blockDim.x + threadIdx.x) >> 5;
    const int lane = threadIdx.x & 31;
    if (warp >= MTOT) return;
    const float* drow = D + (size_t)warp * DD;
    float s0 = 0.f, s1 = 0.f, s2 = 0.f, s3 = 0.f;
    for (int k = lane; k < DD; k += 32) {
        float d = drow[k];
        s0 = fmaf(d, Wc[k],          s0);
        s1 = fmaf(d, Wc[DD + k],     s1);
        s2 = fmaf(d, Wc[2 * DD + k], s2);
        s3 = fmaf(d, Wc[3 * DD + k], s3);
    }
    s0 = wsum(s0); s1 = wsum(s1); s2 = wsum(s2); s3 = wsum(s3);
    if (lane == 0) {
        out[(size_t)warp * 4 + 0] = s0 + bc[0];
        out[(size_t)warp * 4 + 1] = s1 + bc[1];
        out[(size_t)warp * 4 + 2] = s2 + bc[2];
        out[(size_t)warp * 4 + 3] = s3 + bc[3];
    }
}

// ---------------------------------------------------------------------------
extern "C" void kernel_launch(void* const* d_in, const int* in_sizes, int n_in,
                              void* d_out, int out_size)
{
    const float* X1   = (const float*)d_in[0];
    const float* X2   = (const float*)d_in[1];
    const float* X3   = (const float*)d_in[2];
    const float* X4   = (const float*)d_in[3];
    const float* Wq   = (const float*)d_in[4];
    const float* bq   = (const float*)d_in[5];
    const float* Wv_s = (const float*)d_in[8];
    const float* bv_s = (const float*)d_in[9];
    const float* Wo_s = (const float*)d_in[10];
    const float* bo_s = (const float*)d_in[11];
    const float* Wk_c = (const float*)d_in[12];
    const float* bk_c = (const float*)d_in[13];
    const float* Wv_c = (const float*)d_in[14];
    const float* bv_c = (const float*)d_in[15];
    const float* Wo_c = (const float*)d_in[16];
    const float* bo_c = (const float*)d_in[17];
    const float* Wc   = (const float*)d_in[18];
    const float* bc   = (const float*)d_in[19];

    float* out    = (float*)d_out;
    float* logits = out + (size_t)MTOT * DD;

    __nv_bfloat16 *gXs, *gW1s, *gWosS, *gWvsT;
    __half *gXh, *gWh, *gA2h;
    float *gC1a, *gS, *gWeff, *gb1a, *gb1s, *gzero;
    cudaGetSymbolAddress((void**)&gXs,   g_Xs);
    cudaGetSymbolAddress((void**)&gXh,   g_Xh);
    cudaGetSymbolAddress((void**)&gWh,   g_Wh);
    cudaGetSymbolAddress((void**)&gW1s,  g_W1s);
    cudaGetSymbolAddress((void**)&gC1a,  g_C1a);
    cudaGetSymbolAddress((void**)&gS,    g_S);
    cudaGetSymbolAddress((void**)&gA2h,  g_A2h);
    cudaGetSymbolAddress((void**)&gWosS, g_WosS);
    cudaGetSymbolAddress((void**)&gWvsT, g_WvsT);
    cudaGetSymbolAddress((void**)&gWeff, g_Weff);
    cudaGetSymbolAddress((void**)&gb1a,  g_b1a);
    cudaGetSymbolAddress((void**)&gb1s,  g_b1s);
    cudaGetSymbolAddress((void**)&gzero, g_zero);

    cudaFuncSetAttribute(gemm_mma<false>,
                         cudaFuncAttributeMaxDynamicSharedMemorySize, GEMM_SMEM);
    cudaFuncSetAttribute(gemm_mma<true>,
                         cudaFuncAttributeMaxDynamicSharedMemorySize, GEMM_SMEM);

    // prep: splits + fp16 copies + weight-space fold of the self path
    split_X_kernel<<<MTOT, 256>>>(X1, X2, X3, X4, gXs, gXh);
    to_half_kernel<<<1024, 256>>>(Wq,   gWh);
    to_half_kernel<<<1024, 256>>>(Wk_c, gWh + (size_t)1024 * DD);
    to_half_kernel<<<1024, 256>>>(Wv_c, gWh + (size_t)2048 * DD);
    to_half_kernel<<<1024, 256>>>(Wo_c, gWh + (size_t)3072 * DD);
    split_Ahl<<<1024, 256>>>(Wo_s, gWosS);
    transpose_split_B<<<4096, 256>>>(Wv_s, gWvsT);

    // Weff[o,i] = sum_m Wos[o,m] * Wvs[m,i]   (tiny split GEMM, K=3072)
    gemm_mma<false><<<dim3(4, 8), 256, GEMM_SMEM>>>(
        (const uint16_t*)gWosS, (const uint16_t*)gWvsT, gzero, nullptr, 0,
        gWeff, 1024, 1024, K1);
    split_Bhl<<<1024, 256>>>(gWeff, gW1s);

    bias_init_kernel<<<4, 256>>>(bq, gb1a);
    bs_eff_kernel<<<128, 256>>>(Wo_s, bv_s, bo_s, gb1s);

    // GEMM1a (fp16): C1a[32768,3072] = Xh @ [Wq;Wkc;Wvc]^T + [bq|0|0]
    gemm_mma<true><<<dim3(N1A / 256, MTOT / 128), 256, GEMM_SMEM>>>(
        (const uint16_t*)gXh, (const uint16_t*)gWh, gb1a, nullptr, 0,
        gC1a, MTOT, N1A, DD);

    // GEMM1s (bf16 3-term): S[32768,1024] = Xs @ Weff^T + bS
    gemm_mma<false><<<dim3(DD / 256, MTOT / 128), 256, GEMM_SMEM>>>(
        (const uint16_t*)gXs, (const uint16_t*)gW1s, gb1s, nullptr, 0,
        gS, MTOT, DD, K1);

    // attention combine -> ctx fp16 into A2h
    combine_kernel<<<NB, 128>>>(gC1a, bk_c, bv_c, gA2h);

    // GEMM2 (fp16): d = ctx @ Wo_c^T + bo_c + S
    gemm_mma<true><<<dim3(DD / 256, MTOT / 128), 256, GEMM_SMEM>>>(
        (const uint16_t*)gA2h, (const uint16_t*)(gWh + (size_t)3072 * DD),
        bo_c, gS, DD, out, MTOT, DD, DD);

    // logits = d @ Wc^T + bc
    logits_kernel<<<MTOT / 8, 256>>>(out, Wc, bc, logits);
}

// round 8
// speedup vs baseline: 7.3564x; 1.3065x over previous
#include <cuda_runtime.h>
#include <cuda_bf16.h>
#include <cuda_fp16.h>
#include <cstdint>
#include <cstddef>

// ---------------------------------------------------------------------------
// MultiModalClassifier, GB300, mma.sync fp16 GEMMs (Weff folded exactly).
//   B=8192, D=1024, H=4 (hd=256), C=4, M=32768
// Algebra:
//   self_out = X@Weff^T + bS,  Weff = Wo_s@Wv_s, bS = Wo_s@bv_s + bo_s
//   cross: K_ij = Kc_i - Kc_j + bk_c, V_ij = Vc_i - Vc_j + bv_c
//   d = S + ctx@Wo_c^T + bo_c
// Precision: all big GEMMs single fp16 (measured ~3e-4 RMS per path);
// Weff itself computed in bf16 3-term split (exact to ~2^-16) then cast.
// ---------------------------------------------------------------------------

#define NB 8192
#define DD 1024
#define MTOT 32768
#define HD 256
#define K1 3072
#define N1A 4096          // Q | Kc | Vc | S

// ------------------------------ scratch ------------------------------------
__device__ __half        g_Xh  [(size_t)MTOT * DD];    // 64 MB  (fp16 X)
__device__ __half        g_Wh  [(size_t)5120 * DD];    // 10 MB  (Wq;Wkc;Wvc;Weff;Woc)
__device__ float         g_C1a [(size_t)MTOT * N1A];   // 512 MB (Q|Kc|Vc|S)
__device__ __half        g_A2h [(size_t)MTOT * DD];    // 64 MB  (ctx fp16)
__device__ __nv_bfloat16 g_WosS[(size_t)DD * K1];      // 6 MB
__device__ __nv_bfloat16 g_WvsT[(size_t)DD * K1];      // 6 MB
__device__ float         g_Weff[(size_t)DD * DD];      // 4 MB
__device__ float         g_b1a[N1A];
__device__ float         g_zero[DD];                    // never written: zeros

// --------------------------- PTX helpers -----------------------------------
__device__ __forceinline__ uint32_t smem_u32(const void* p) {
    uint32_t a;
    asm("{ .reg .u64 t; cvta.to.shared.u64 t, %1; cvt.u32.u64 %0, t; }"
        : "=r"(a) : "l"(p));
    return a;
}

#define CP_ASYNC16(dst, src) \
    asm volatile("cp.async.cg.shared.global [%0], [%1], 16;" :: "r"(dst), "l"(src))
#define CP_COMMIT() asm volatile("cp.async.commit_group;" ::: "memory")
#define CP_WAIT(n)  asm volatile("cp.async.wait_group %0;" :: "n"(n) : "memory")

#define LDMATRIX_X4(r0, r1, r2, r3, addr)                                     \
    asm volatile("ldmatrix.sync.aligned.m8n8.x4.shared.b16 {%0,%1,%2,%3}, [%4];" \
                 : "=r"(r0), "=r"(r1), "=r"(r2), "=r"(r3) : "r"(addr))

#define MMA_BF16(d0, d1, d2, d3, a0, a1, a2, a3, b0, b1)                      \
    asm volatile("mma.sync.aligned.m16n8k16.row.col.f32.bf16.bf16.f32 "       \
                 "{%0,%1,%2,%3}, {%4,%5,%6,%7}, {%8,%9}, {%0,%1,%2,%3};"      \
                 : "+f"(d0), "+f"(d1), "+f"(d2), "+f"(d3)                     \
                 : "r"(a0), "r"(a1), "r"(a2), "r"(a3), "r"(b0), "r"(b1))

#define MMA_F16(d0, d1, d2, d3, a0, a1, a2, a3, b0, b1)                       \
    asm volatile("mma.sync.aligned.m16n8k16.row.col.f32.f16.f16.f32 "         \
                 "{%0,%1,%2,%3}, {%4,%5,%6,%7}, {%8,%9}, {%0,%1,%2,%3};"      \
                 : "+f"(d0), "+f"(d1), "+f"(d2), "+f"(d3)                     \
                 : "r"(a0), "r"(a1), "r"(a2), "r"(a3), "r"(b0), "r"(b1))

// --------------------------- GEMM kernel -----------------------------------
// C[M,N] = A[M,K] @ B[N,K]^T + bias (+ add), b16-typed in / fp32 out.
// CTA tile 128x256, BK=64, SW128 swizzle, 4-stage cp.async, 8 warps (2x4),
// warp tile 64x64. F16 selects fp16 mma (same fragments as bf16).
#define STAGES 4
#define STAGE_BYTES 49152          // A 16KB + B 32KB
#define GEMM_SMEM (STAGES * STAGE_BYTES)

__device__ __forceinline__ void load_stage(
    const uint16_t* __restrict__ A, const uint16_t* __restrict__ B,
    int K, int brow, int bcol, int kb, uint32_t st, int tid)
{
    #pragma unroll
    for (int i = 0; i < 12; i++) {
        int id = tid + 256 * i;
        if (id < 1024) {                       // A: 128 rows x 8 chunks
            int row = id >> 3, c = id & 7;
            const uint16_t* g = A + (size_t)(brow + row) * K + kb * 64 + c * 8;
            CP_ASYNC16(st + row * 128 + ((c ^ (row & 7)) * 16), g);
        } else {                               // B: 256 rows x 8 chunks
            int idb = id - 1024;
            int row = idb >> 3, c = idb & 7;
            const uint16_t* g = B + (size_t)(bcol + row) * K + kb * 64 + c * 8;
            CP_ASYNC16(st + 16384 + row * 128 + ((c ^ (row & 7)) * 16), g);
        }
    }
}

template <bool F16>
__global__ __launch_bounds__(256, 1)
void gemm_mma(const uint16_t* __restrict__ A,
              const uint16_t* __restrict__ B,
              const float* __restrict__ bias,
              const float* __restrict__ add, int add_ld,
              float* __restrict__ C, int M, int N, int K)
{
    extern __shared__ __align__(1024) char smem[];
    const uint32_t sbase = smem_u32(smem);
    const int tid  = threadIdx.x;
    const int wid  = tid >> 5, lane = tid & 31;
    const int wm   = wid >> 2, wn = wid & 3;     // 2 x 4 warps
    const int brow = blockIdx.y * 128, bcol = blockIdx.x * 256;
    const int NKB  = K >> 6;

    float acc[4][8][4];
    #pragma unroll
    for (int i = 0; i < 4; i++)
        #pragma unroll
        for (int j = 0; j < 8; j++)
            #pragma unroll
            for (int k = 0; k < 4; k++) acc[i][j][k] = 0.f;

    load_stage(A, B, K, brow, bcol, 0, sbase, tid);                  CP_COMMIT();
    load_stage(A, B, K, brow, bcol, 1, sbase + STAGE_BYTES, tid);    CP_COMMIT();
    load_stage(A, B, K, brow, bcol, 2, sbase + 2 * STAGE_BYTES, tid);CP_COMMIT();

    int a_off[4], a_sw[4];
    #pragma unroll
    for (int mt = 0; mt < 4; mt++) {
        int r = wm * 64 + mt * 16 + (lane & 15);
        a_off[mt] = r * 128; a_sw[mt] = r & 7;
    }
    const int a_kh = lane >> 4;
    int b_off[4], b_sw[4];
    #pragma unroll
    for (int np = 0; np < 4; np++) {
        int r = wn * 64 + np * 16 + ((lane >> 4) & 1) * 8 + (lane & 7);
        b_off[np] = r * 128; b_sw[np] = r & 7;
    }
    const int b_kh = (lane >> 3) & 1;

    for (int kb = 0; kb < NKB; kb++) {
        if (kb < NKB - 2)       CP_WAIT(2);
        else if (kb == NKB - 2) CP_WAIT(1);
        else                    CP_WAIT(0);
        __syncthreads();
        if (kb + 3 < NKB) {
            load_stage(A, B, K, brow, bcol, kb + 3,
                       sbase + ((kb + 3) & 3) * STAGE_BYTES, tid);
            CP_COMMIT();
        }
        const uint32_t sA = sbase + (kb & 3) * STAGE_BYTES;
        const uint32_t sB = sA + 16384;

        #pragma unroll
        for (int ks = 0; ks < 4; ks++) {
            uint32_t af[4][4], bf[4][4];
            #pragma unroll
            for (int mt = 0; mt < 4; mt++) {
                int cc = ks * 2 + a_kh;
                LDMATRIX_X4(af[mt][0], af[mt][1], af[mt][2], af[mt][3],
                            sA + a_off[mt] + ((cc ^ a_sw[mt]) * 16));
            }
            #pragma unroll
            for (int np = 0; np < 4; np++) {
                int cc = ks * 2 + b_kh;
                LDMATRIX_X4(bf[np][0], bf[np][1], bf[np][2], bf[np][3],
                            sB + b_off[np] + ((cc ^ b_sw[np]) * 16));
            }
            #pragma unroll
            for (int mt = 0; mt < 4; mt++)
                #pragma unroll
                for (int nt = 0; nt < 8; nt++) {
                    if (F16)
                        MMA_F16(acc[mt][nt][0], acc[mt][nt][1],
                                acc[mt][nt][2], acc[mt][nt][3],
                                af[mt][0], af[mt][1], af[mt][2], af[mt][3],
                                bf[nt >> 1][(nt & 1) * 2],
                                bf[nt >> 1][(nt & 1) * 2 + 1]);
                    else
                        MMA_BF16(acc[mt][nt][0], acc[mt][nt][1],
                                 acc[mt][nt][2], acc[mt][nt][3],
                                 af[mt][0], af[mt][1], af[mt][2], af[mt][3],
                                 bf[nt >> 1][(nt & 1) * 2],
                                 bf[nt >> 1][(nt & 1) * 2 + 1]);
                }
        }
    }

    #pragma unroll
    for (int mt = 0; mt < 4; mt++) {
        const int r0 = brow + wm * 64 + mt * 16 + (lane >> 2);
        #pragma unroll
        for (int nt = 0; nt < 8; nt++) {
            const int c0 = bcol + wn * 64 + nt * 8 + (lane & 3) * 2;
            const float bx = bias[c0], by = bias[c0 + 1];
            float a0 = acc[mt][nt][0] + bx, a1 = acc[mt][nt][1] + by;
            float a2 = acc[mt][nt][2] + bx, a3 = acc[mt][nt][3] + by;
            if (add) {
                a0 += add[(size_t)r0 * add_ld + c0];
                a1 += add[(size_t)r0 * add_ld + c0 + 1];
                a2 += add[(size_t)(r0 + 8) * add_ld + c0];
                a3 += add[(size_t)(r0 + 8) * add_ld + c0 + 1];
            }
            float2 v0 = { a0, a1 }, v1 = { a2, a3 };
            *(float2*)&C[(size_t)r0 * N + c0]       = v0;
            *(float2*)&C[(size_t)(r0 + 8) * N + c0] = v1;
        }
    }
}

// --------------------------- split / cast kernels ---------------------------
__device__ __forceinline__ void split1(float a, __nv_bfloat16& h, __nv_bfloat16& l) {
    h = __float2bfloat16(a);
    l = __float2bfloat16(a - __bfloat162float(h));
}

// A-operand layout [hi|lo|hi]
__global__ __launch_bounds__(256) void split_Ahl(
    const float* __restrict__ src, __nv_bfloat16* __restrict__ dst)
{
    size_t idx = (size_t)blockIdx.x * blockDim.x + threadIdx.x;
    size_t n = idx >> 8;
    int c4 = (int)(idx & 255) * 4;
    float4 v = *(const float4*)&src[n * DD + c4];
    __nv_bfloat16 h[4], l[4];
    split1(v.x, h[0], l[0]); split1(v.y, h[1], l[1]);
    split1(v.z, h[2], l[2]); split1(v.w, h[3], l[3]);
    __nv_bfloat16* row = dst + n * K1;
    *(uint2*)&row[c4]          = *(uint2*)h;
    *(uint2*)&row[DD + c4]     = *(uint2*)l;
    *(uint2*)&row[2 * DD + c4] = *(uint2*)h;
}

// WvsT[i,m] = Wvs[m,i], B layout [hi|hi|lo]
__global__ __launch_bounds__(256) void transpose_split_B(
    const float* __restrict__ Wvs, __nv_bfloat16* __restrict__ dst)
{
    size_t idx = (size_t)blockIdx.x * blockDim.x + threadIdx.x;
    int m = (int)(idx >> 10);
    int i = (int)(idx & 1023);
    float v = Wvs[(size_t)m * DD + i];
    __nv_bfloat16 h, l; split1(v, h, l);
    __nv_bfloat16* row = dst + (size_t)i * K1;
    row[m] = h; row[DD + m] = h; row[2 * DD + m] = l;
}

// fp32 -> fp16 copy
__global__ __launch_bounds__(256) void to_half_kernel(
    const float* __restrict__ src, __half* __restrict__ dst)
{
    size_t idx = (size_t)blockIdx.x * blockDim.x + threadIdx.x;
    float4 v = *(const float4*)&src[idx * 4];
    __half h[4] = { __float2half(v.x), __float2half(v.y),
                    __float2half(v.z), __float2half(v.w) };
    *(uint2*)&dst[idx * 4] = *(uint2*)h;
}

// stacked X -> fp16
__global__ __launch_bounds__(256) void x_to_half_kernel(
    const float* __restrict__ X1, const float* __restrict__ X2,
    const float* __restrict__ X3, const float* __restrict__ X4,
    __half* __restrict__ Xh)
{
    size_t idx = (size_t)blockIdx.x * blockDim.x + threadIdx.x;
    size_t r = idx >> 8;
    int c4 = (int)(idx & 255) * 4;
    const float* src = (r < NB) ? X1 : (r < 2 * NB) ? X2 : (r < 3 * NB) ? X3 : X4;
    float4 v = *(const float4*)&src[(r & (NB - 1)) * DD + c4];
    __half hf[4] = { __float2half(v.x), __float2half(v.y),
                     __float2half(v.z), __float2half(v.w) };
    *(uint2*)&Xh[r * DD + c4] = *(uint2*)hf;
}

// --------------------------- bias kernels ----------------------------------
__device__ __forceinline__ float wsum(float v) {
    #pragma unroll
    for (int o = 16; o; o >>= 1) v += __shfl_xor_sync(0xffffffffu, v, o);
    return v;
}

__global__ __launch_bounds__(256) void bias_init_kernel(
    const float* __restrict__ bq, float* __restrict__ b1a)
{
    int i = blockIdx.x * blockDim.x + threadIdx.x;
    if (i < DD) { b1a[i] = bq[i]; b1a[DD + i] = 0.f; b1a[2 * DD + i] = 0.f; }
}

// b1a[3072+o] = dot(Wos[o,:], bvs) + bos[o]
__global__ __launch_bounds__(256) void bs_eff_kernel(
    const float* __restrict__ Wos, const float* __restrict__ bvs,
    const float* __restrict__ bos, float* __restrict__ b1a)
{
    int o = blockIdx.x * 8 + (threadIdx.x >> 5);
    int lane = threadIdx.x & 31;
    float s = 0.f;
    for (int k = lane; k < DD; k += 32)
        s = fmaf(Wos[(size_t)o * DD + k], bvs[k], s);
    s = wsum(s);
    if (lane == 0) b1a[3 * DD + o] = s + bos[o];
}

// --------------------------- combine ---------------------------------------
// ctx_i = Vc_i + bv_c - sum_j a_ij Vc_j, written as fp16 into A2h.
__global__ __launch_bounds__(128) void combine_kernel(
    const float* __restrict__ C1a,   // Q | Kc | Vc | S  (ld 4096)
    const float* __restrict__ bk, const float* __restrict__ bv,
    __half* __restrict__ A2h)
{
    const int b    = blockIdx.x;
    const int h    = threadIdx.x >> 5;
    const int lane = threadIdx.x & 31;
    const int base_d = h * HD + lane;

    float q[4][8], kc[4][8], vc[4][8];
    #pragma unroll
    for (int i = 0; i < 4; i++) {
        size_t row = (size_t)(i * NB + b) * N1A + base_d;
        #pragma unroll
        for (int e = 0; e < 8; e++) {
            q [i][e] = C1a[row + e * 32];
            kc[i][e] = C1a[row + 1024 + e * 32];
            vc[i][e] = C1a[row + 2048 + e * 32];
        }
    }
    float bke[8], bve[8];
    #pragma unroll
    for (int e = 0; e < 8; e++) {
        bke[e] = bk[base_d + e * 32];
        bve[e] = bv[base_d + e * 32];
    }

    float a[4][4];
    #pragma unroll
    for (int i = 0; i < 4; i++) {
        float s[4];
        #pragma unroll
        for (int j = 0; j < 4; j++) {
            float p = 0.f;
            #pragma unroll
            for (int e = 0; e < 8; e++)
                p = fmaf(q[i][e], kc[i][e] - kc[j][e] + bke[e], p);
            s[j] = wsum(p) * (1.f / 16.f);
        }
        float m = -1e30f;
        #pragma unroll
        for (int j = 0; j < 4; j++) if (j != i && s[j] > m) m = s[j];
        float den = 0.f;
        #pragma unroll
        for (int j = 0; j < 4; j++) {
            float ex = (j == i) ? 0.f : __expf(s[j] - m);
            a[i][j] = ex; den += ex;
        }
        float inv = 1.f / den;
        #pragma unroll
        for (int j = 0; j < 4; j++) a[i][j] *= inv;
    }

    #pragma unroll
    for (int i = 0; i < 4; i++) {
        __half* row = A2h + (size_t)(i * NB + b) * DD;
        #pragma unroll
        for (int e = 0; e < 8; e++) {
            float c = vc[i][e] + bve[e];
            #pragma unroll
            for (int j = 0; j < 4; j++)
                c = fmaf(-a[i][j], vc[j][e], c);
            row[base_d + e * 32] = __float2half(c);
        }
    }
}

// --------------------------- logits ----------------------------------------
__global__ __launch_bounds__(256) void logits_kernel(
    const float* __restrict__ D, const float* __restrict__ Wc,
    const float* __restrict__ bc, float* __restrict__ out)
{
    const int warp = (blockIdx.x * blockDim.x + threadIdx.x) >> 5;
    const int lane = threadIdx.x & 31;
    if (warp >= MTOT) return;
    const float* drow = D + (size_t)warp * DD;
    float s0 = 0.f, s1 = 0.f, s2 = 0.f, s3 = 0.f;
    for (int k = lane; k < DD; k += 32) {
        float d = drow[k];
        s0 = fmaf(d, Wc[k],          s0);
        s1 = fmaf(d, Wc[DD + k],     s1);
        s2 = fmaf(d, Wc[2 * DD + k], s2);
        s3 = fmaf(d, Wc[3 * DD + k], s3);
    }
    s0 = wsum(s0); s1 = wsum(s1); s2 = wsum(s2); s3 = wsum(s3);
    if (lane == 0) {
        out[(size_t)warp * 4 + 0] = s0 + bc[0];
        out[(size_t)warp * 4 + 1] = s1 + bc[1];
        out[(size_t)warp * 4 + 2] = s2 + bc[2];
        out[(size_t)warp * 4 + 3] = s3 + bc[3];
    }
}

// ---------------------------------------------------------------------------
extern "C" void kernel_launch(void* const* d_in, const int* in_sizes, int n_in,
                              void* d_out, int out_size)
{
    const float* X1   = (const float*)d_in[0];
    const float* X2   = (const float*)d_in[1];
    const float* X3   = (const float*)d_in[2];
    const float* X4   = (const float*)d_in[3];
    const float* Wq   = (const float*)d_in[4];
    const float* bq   = (const float*)d_in[5];
    const float* Wv_s = (const float*)d_in[8];
    const float* bv_s = (const float*)d_in[9];
    const float* Wo_s = (const float*)d_in[10];
    const float* bo_s = (const float*)d_in[11];
    const float* Wk_c = (const float*)d_in[12];
    const float* bk_c = (const float*)d_in[13];
    const float* Wv_c = (const float*)d_in[14];
    const float* bv_c = (const float*)d_in[15];
    const float* Wo_c = (const float*)d_in[16];
    const float* bo_c = (const float*)d_in[17];
    const float* Wc   = (const float*)d_in[18];
    const float* bc   = (const float*)d_in[19];

    float* out    = (float*)d_out;
    float* logits = out + (size_t)MTOT * DD;

    __nv_bfloat16 *gWosS, *gWvsT;
    __half *gXh, *gWh, *gA2h;
    float *gC1a, *gWeff, *gb1a, *gzero;
    cudaGetSymbolAddress((void**)&gXh,   g_Xh);
    cudaGetSymbolAddress((void**)&gWh,   g_Wh);
    cudaGetSymbolAddress((void**)&gC1a,  g_C1a);
    cudaGetSymbolAddress((void**)&gA2h,  g_A2h);
    cudaGetSymbolAddress((void**)&gWosS, g_WosS);
    cudaGetSymbolAddress((void**)&gWvsT, g_WvsT);
    cudaGetSymbolAddress((void**)&gWeff, g_Weff);
    cudaGetSymbolAddress((void**)&gb1a,  g_b1a);
    cudaGetSymbolAddress((void**)&gzero, g_zero);

    cudaFuncSetAttribute(gemm_mma<false>,
                         cudaFuncAttributeMaxDynamicSharedMemorySize, GEMM_SMEM);
    cudaFuncSetAttribute(gemm_mma<true>,
                         cudaFuncAttributeMaxDynamicSharedMemorySize, GEMM_SMEM);

    // prep: fp16 casts + exact weight-space fold of the self path
    x_to_half_kernel<<<MTOT, 256>>>(X1, X2, X3, X4, gXh);
    to_half_kernel<<<1024, 256>>>(Wq,   gWh);
    to_half_kernel<<<1024, 256>>>(Wk_c, gWh + (size_t)1024 * DD);
    to_half_kernel<<<1024, 256>>>(Wv_c, gWh + (size_t)2048 * DD);
    to_half_kernel<<<1024, 256>>>(Wo_c, gWh + (size_t)4096 * DD);
    split_Ahl<<<1024, 256>>>(Wo_s, gWosS);
    transpose_split_B<<<4096, 256>>>(Wv_s, gWvsT);

    // Weff[o,i] = sum_m Wos[o,m] * Wvs[m,i]  (bf16 3-term, exact to ~2^-16)
    gemm_mma<false><<<dim3(4, 8), 256, GEMM_SMEM>>>(
        (const uint16_t*)gWosS, (const uint16_t*)gWvsT, gzero, nullptr, 0,
        gWeff, 1024, 1024, K1);
    to_half_kernel<<<1024, 256>>>(gWeff, gWh + (size_t)3072 * DD);

    bias_init_kernel<<<4, 256>>>(bq, gb1a);
    bs_eff_kernel<<<128, 256>>>(Wo_s, bv_s, bo_s, gb1a);

    // GEMM1 (fp16): C1a[32768,4096] = Xh @ [Wq;Wkc;Wvc;Weff]^T + [bq|0|0|bS]
    gemm_mma<true><<<dim3(N1A / 256, MTOT / 128), 256, GEMM_SMEM>>>(
        (const uint16_t*)gXh, (const uint16_t*)gWh, gb1a, nullptr, 0,
        gC1a, MTOT, N1A, DD);

    // attention combine -> ctx fp16 into A2h
    combine_kernel<<<NB, 128>>>(gC1a, bk_c, bv_c, gA2h);

    // GEMM2 (fp16): d = ctx @ Wo_c^T + bo_c + S   (S = C1a cols 3072..4095)
    gemm_mma<true><<<dim3(DD / 256, MTOT / 128), 256, GEMM_SMEM>>>(
        (const uint16_t*)gA2h, (const uint16_t*)(gWh + (size_t)4096 * DD),
        bo_c, gC1a + 3072, N1A, out, MTOT, DD, DD);

    // logits = d @ Wc^T + bc
    logits_kernel<<<MTOT / 8, 256>>>(out, Wc, bc, logits);
}

// round 9
// speedup vs baseline: 7.5173x; 1.0219x over previous
#include <cuda_runtime.h>
#include <cuda_bf16.h>
#include <cuda_fp16.h>
#include <cstdint>
#include <cstddef>

// ---------------------------------------------------------------------------
// MultiModalClassifier, GB300, mma.sync fp16 GEMMs, fp16 intermediates.
//   B=8192, D=1024, H=4 (hd=256), C=4, M=32768
// Algebra:
//   self_out = X@Weff^T + bS,  Weff = Wo_s@Wv_s, bS = Wo_s@bv_s + bo_s
//   cross: K_ij = Kc_i - Kc_j + bk_c, V_ij = Vc_i - Vc_j + bv_c
//   d = S + ctx@Wo_c^T + bo_c
// Precision: fp16 single GEMMs + fp16 intermediate storage (C1, ctx);
// Weff computed in bf16 3-term split (exact to ~2^-16) then cast to fp16.
// ---------------------------------------------------------------------------

#define NB 8192
#define DD 1024
#define MTOT 32768
#define HD 256
#define K1 3072
#define N1A 4096          // Q | Kc | Vc | S

// ------------------------------ scratch ------------------------------------
__device__ __half        g_Xh  [(size_t)MTOT * DD];    // 64 MB  (fp16 X)
__device__ __half        g_Wh  [(size_t)5120 * DD];    // 10 MB  (Wq;Wkc;Wvc;Weff;Woc)
__device__ __half        g_C1h [(size_t)MTOT * N1A];   // 256 MB (Q|Kc|Vc|S fp16)
__device__ __half        g_A2h [(size_t)MTOT * DD];    // 64 MB  (ctx fp16)
__device__ __nv_bfloat16 g_WosS[(size_t)DD * K1];      // 6 MB
__device__ __nv_bfloat16 g_WvsT[(size_t)DD * K1];      // 6 MB
__device__ float         g_Weff[(size_t)DD * DD];      // 4 MB
__device__ float         g_b1a[N1A];
__device__ float         g_zero[DD];                    // never written: zeros

// --------------------------- PTX helpers -----------------------------------
__device__ __forceinline__ uint32_t smem_u32(const void* p) {
    uint32_t a;
    asm("{ .reg .u64 t; cvta.to.shared.u64 t, %1; cvt.u32.u64 %0, t; }"
        : "=r"(a) : "l"(p));
    return a;
}

#define CP_ASYNC16(dst, src) \
    asm volatile("cp.async.cg.shared.global [%0], [%1], 16;" :: "r"(dst), "l"(src))
#define CP_COMMIT() asm volatile("cp.async.commit_group;" ::: "memory")
#define CP_WAIT(n)  asm volatile("cp.async.wait_group %0;" :: "n"(n) : "memory")

#define LDMATRIX_X4(r0, r1, r2, r3, addr)                                     \
    asm volatile("ldmatrix.sync.aligned.m8n8.x4.shared.b16 {%0,%1,%2,%3}, [%4];" \
                 : "=r"(r0), "=r"(r1), "=r"(r2), "=r"(r3) : "r"(addr))

#define MMA_BF16(d0, d1, d2, d3, a0, a1, a2, a3, b0, b1)                      \
    asm volatile("mma.sync.aligned.m16n8k16.row.col.f32.bf16.bf16.f32 "       \
                 "{%0,%1,%2,%3}, {%4,%5,%6,%7}, {%8,%9}, {%0,%1,%2,%3};"      \
                 : "+f"(d0), "+f"(d1), "+f"(d2), "+f"(d3)                     \
                 : "r"(a0), "r"(a1), "r"(a2), "r"(a3), "r"(b0), "r"(b1))

#define MMA_F16(d0, d1, d2, d3, a0, a1, a2, a3, b0, b1)                       \
    asm volatile("mma.sync.aligned.m16n8k16.row.col.f32.f16.f16.f32 "         \
                 "{%0,%1,%2,%3}, {%4,%5,%6,%7}, {%8,%9}, {%0,%1,%2,%3};"      \
                 : "+f"(d0), "+f"(d1), "+f"(d2), "+f"(d3)                     \
                 : "r"(a0), "r"(a1), "r"(a2), "r"(a3), "r"(b0), "r"(b1))

// --------------------------- GEMM kernel -----------------------------------
// C[M,N] = A[M,K] @ B[N,K]^T + bias (+ fp16 add), b16-typed in.
// OUT16: fp16 output, else fp32. CTA tile 128x256, BK=64, SW128 swizzle,
// 4-stage cp.async, 8 warps (2x4), warp tile 64x64.
#define STAGES 4
#define STAGE_BYTES 49152          // A 16KB + B 32KB
#define GEMM_SMEM (STAGES * STAGE_BYTES)

__device__ __forceinline__ void load_stage(
    const uint16_t* __restrict__ A, const uint16_t* __restrict__ B,
    int K, int brow, int bcol, int kb, uint32_t st, int tid)
{
    #pragma unroll
    for (int i = 0; i < 12; i++) {
        int id = tid + 256 * i;
        if (id < 1024) {                       // A: 128 rows x 8 chunks
            int row = id >> 3, c = id & 7;
            const uint16_t* g = A + (size_t)(brow + row) * K + kb * 64 + c * 8;
            CP_ASYNC16(st + row * 128 + ((c ^ (row & 7)) * 16), g);
        } else {                               // B: 256 rows x 8 chunks
            int idb = id - 1024;
            int row = idb >> 3, c = idb & 7;
            const uint16_t* g = B + (size_t)(bcol + row) * K + kb * 64 + c * 8;
            CP_ASYNC16(st + 16384 + row * 128 + ((c ^ (row & 7)) * 16), g);
        }
    }
}

template <bool F16, bool OUT16>
__global__ __launch_bounds__(256, 1)
void gemm_mma(const uint16_t* __restrict__ A,
              const uint16_t* __restrict__ B,
              const float* __restrict__ bias,
              const __half* __restrict__ add, int add_ld,
              void* __restrict__ Cv, int M, int N, int K)
{
    extern __shared__ __align__(1024) char smem[];
    const uint32_t sbase = smem_u32(smem);
    const int tid  = threadIdx.x;
    const int wid  = tid >> 5, lane = tid & 31;
    const int wm   = wid >> 2, wn = wid & 3;     // 2 x 4 warps
    const int brow = blockIdx.y * 128, bcol = blockIdx.x * 256;
    const int NKB  = K >> 6;

    float acc[4][8][4];
    #pragma unroll
    for (int i = 0; i < 4; i++)
        #pragma unroll
        for (int j = 0; j < 8; j++)
            #pragma unroll
            for (int k = 0; k < 4; k++) acc[i][j][k] = 0.f;

    load_stage(A, B, K, brow, bcol, 0, sbase, tid);                  CP_COMMIT();
    load_stage(A, B, K, brow, bcol, 1, sbase + STAGE_BYTES, tid);    CP_COMMIT();
    load_stage(A, B, K, brow, bcol, 2, sbase + 2 * STAGE_BYTES, tid);CP_COMMIT();

    int a_off[4], a_sw[4];
    #pragma unroll
    for (int mt = 0; mt < 4; mt++) {
        int r = wm * 64 + mt * 16 + (lane & 15);
        a_off[mt] = r * 128; a_sw[mt] = r & 7;
    }
    const int a_kh = lane >> 4;
    int b_off[4], b_sw[4];
    #pragma unroll
    for (int np = 0; np < 4; np++) {
        int r = wn * 64 + np * 16 + ((lane >> 4) & 1) * 8 + (lane & 7);
        b_off[np] = r * 128; b_sw[np] = r & 7;
    }
    const int b_kh = (lane >> 3) & 1;

    for (int kb = 0; kb < NKB; kb++) {
        if (kb < NKB - 2)       CP_WAIT(2);
        else if (kb == NKB - 2) CP_WAIT(1);
        else                    CP_WAIT(0);
        __syncthreads();
        if (kb + 3 < NKB) {
            load_stage(A, B, K, brow, bcol, kb + 3,
                       sbase + ((kb + 3) & 3) * STAGE_BYTES, tid);
            CP_COMMIT();
        }
        const uint32_t sA = sbase + (kb & 3) * STAGE_BYTES;
        const uint32_t sB = sA + 16384;

        #pragma unroll
        for (int ks = 0; ks < 4; ks++) {
            uint32_t af[4][4], bf[4][4];
            #pragma unroll
            for (int mt = 0; mt < 4; mt++) {
                int cc = ks * 2 + a_kh;
                LDMATRIX_X4(af[mt][0], af[mt][1], af[mt][2], af[mt][3],
                            sA + a_off[mt] + ((cc ^ a_sw[mt]) * 16));
            }
            #pragma unroll
            for (int np = 0; np < 4; np++) {
                int cc = ks * 2 + b_kh;
                LDMATRIX_X4(bf[np][0], bf[np][1], bf[np][2], bf[np][3],
                            sB + b_off[np] + ((cc ^ b_sw[np]) * 16));
            }
            #pragma unroll
            for (int mt = 0; mt < 4; mt++)
                #pragma unroll
                for (int nt = 0; nt < 8; nt++) {
                    if (F16)
                        MMA_F16(acc[mt][nt][0], acc[mt][nt][1],
                                acc[mt][nt][2], acc[mt][nt][3],
                                af[mt][0], af[mt][1], af[mt][2], af[mt][3],
                                bf[nt >> 1][(nt & 1) * 2],
                                bf[nt >> 1][(nt & 1) * 2 + 1]);
                    else
                        MMA_BF16(acc[mt][nt][0], acc[mt][nt][1],
                                 acc[mt][nt][2], acc[mt][nt][3],
                                 af[mt][0], af[mt][1], af[mt][2], af[mt][3],
                                 bf[nt >> 1][(nt & 1) * 2],
                                 bf[nt >> 1][(nt & 1) * 2 + 1]);
                }
        }
    }

    #pragma unroll
    for (int mt = 0; mt < 4; mt++) {
        const int r0 = brow + wm * 64 + mt * 16 + (lane >> 2);
        #pragma unroll
        for (int nt = 0; nt < 8; nt++) {
            const int c0 = bcol + wn * 64 + nt * 8 + (lane & 3) * 2;
            const float bx = bias[c0], by = bias[c0 + 1];
            float a0 = acc[mt][nt][0] + bx, a1 = acc[mt][nt][1] + by;
            float a2 = acc[mt][nt][2] + bx, a3 = acc[mt][nt][3] + by;
            if (add) {
                a0 += __half2float(add[(size_t)r0 * add_ld + c0]);
                a1 += __half2float(add[(size_t)r0 * add_ld + c0 + 1]);
                a2 += __half2float(add[(size_t)(r0 + 8) * add_ld + c0]);
                a3 += __half2float(add[(size_t)(r0 + 8) * add_ld + c0 + 1]);
            }
            if (OUT16) {
                __half* C = (__half*)Cv;
                __half2 v0 = __floats2half2_rn(a0, a1);
                __half2 v1 = __floats2half2_rn(a2, a3);
                *(__half2*)&C[(size_t)r0 * N + c0]       = v0;
                *(__half2*)&C[(size_t)(r0 + 8) * N + c0] = v1;
            } else {
                float* C = (float*)Cv;
                float2 v0 = { a0, a1 }, v1 = { a2, a3 };
                *(float2*)&C[(size_t)r0 * N + c0]       = v0;
                *(float2*)&C[(size_t)(r0 + 8) * N + c0] = v1;
            }
        }
    }
}

// --------------------------- split / cast kernels ---------------------------
__device__ __forceinline__ void split1(float a, __nv_bfloat16& h, __nv_bfloat16& l) {
    h = __float2bfloat16(a);
    l = __float2bfloat16(a - __bfloat162float(h));
}

// A-operand layout [hi|lo|hi]
__global__ __launch_bounds__(256) void split_Ahl(
    const float* __restrict__ src, __nv_bfloat16* __restrict__ dst)
{
    size_t idx = (size_t)blockIdx.x * blockDim.x + threadIdx.x;
    size_t n = idx >> 8;
    int c4 = (int)(idx & 255) * 4;
    float4 v = *(const float4*)&src[n * DD + c4];
    __nv_bfloat16 h[4], l[4];
    split1(v.x, h[0], l[0]); split1(v.y, h[1], l[1]);
    split1(v.z, h[2], l[2]); split1(v.w, h[3], l[3]);
    __nv_bfloat16* row = dst + n * K1;
    *(uint2*)&row[c4]          = *(uint2*)h;
    *(uint2*)&row[DD + c4]     = *(uint2*)l;
    *(uint2*)&row[2 * DD + c4] = *(uint2*)h;
}

// WvsT[i,m] = Wvs[m,i], B layout [hi|hi|lo]
__global__ __launch_bounds__(256) void transpose_split_B(
    const float* __restrict__ Wvs, __nv_bfloat16* __restrict__ dst)
{
    size_t idx = (size_t)blockIdx.x * blockDim.x + threadIdx.x;
    int m = (int)(idx >> 10);
    int i = (int)(idx & 1023);
    float v = Wvs[(size_t)m * DD + i];
    __nv_bfloat16 h, l; split1(v, h, l);
    __nv_bfloat16* row = dst + (size_t)i * K1;
    row[m] = h; row[DD + m] = h; row[2 * DD + m] = l;
}

// fp32 -> fp16 copy
__global__ __launch_bounds__(256) void to_half_kernel(
    const float* __restrict__ src, __half* __restrict__ dst)
{
    size_t idx = (size_t)blockIdx.x * blockDim.x + threadIdx.x;
    float4 v = *(const float4*)&src[idx * 4];
    __half h[4] = { __float2half(v.x), __float2half(v.y),
                    __float2half(v.z), __float2half(v.w) };
    *(uint2*)&dst[idx * 4] = *(uint2*)h;
}

// stacked X -> fp16
__global__ __launch_bounds__(256) void x_to_half_kernel(
    const float* __restrict__ X1, const float* __restrict__ X2,
    const float* __restrict__ X3, const float* __restrict__ X4,
    __half* __restrict__ Xh)
{
    size_t idx = (size_t)blockIdx.x * blockDim.x + threadIdx.x;
    size_t r = idx >> 8;
    int c4 = (int)(idx & 255) * 4;
    const float* src = (r < NB) ? X1 : (r < 2 * NB) ? X2 : (r < 3 * NB) ? X3 : X4;
    float4 v = *(const float4*)&src[(r & (NB - 1)) * DD + c4];
    __half hf[4] = { __float2half(v.x), __float2half(v.y),
                     __float2half(v.z), __float2half(v.w) };
    *(uint2*)&Xh[r * DD + c4] = *(uint2*)hf;
}

// --------------------------- bias kernels ----------------------------------
__device__ __forceinline__ float wsum(float v) {
    #pragma unroll
    for (int o = 16; o; o >>= 1) v += __shfl_xor_sync(0xffffffffu, v, o);
    return v;
}

__global__ __launch_bounds__(256) void bias_init_kernel(
    const float* __restrict__ bq, float* __restrict__ b1a)
{
    int i = blockIdx.x * blockDim.x + threadIdx.x;
    if (i < DD) { b1a[i] = bq[i]; b1a[DD + i] = 0.f; b1a[2 * DD + i] = 0.f; }
}

// b1a[3072+o] = dot(Wos[o,:], bvs) + bos[o]
__global__ __launch_bounds__(256) void bs_eff_kernel(
    const float* __restrict__ Wos, const float* __restrict__ bvs,
    const float* __restrict__ bos, float* __restrict__ b1a)
{
    int o = blockIdx.x * 8 + (threadIdx.x >> 5);
    int lane = threadIdx.x & 31;
    float s = 0.f;
    for (int k = lane; k < DD; k += 32)
        s = fmaf(Wos[(size_t)o * DD + k], bvs[k], s);
    s = wsum(s);
    if (lane == 0) b1a[3 * DD + o] = s + bos[o];
}

// --------------------------- combine ---------------------------------------
// ctx_i = Vc_i + bv_c - sum_j a_ij Vc_j, fp16 in (C1h) / fp16 out (A2h).
__global__ __launch_bounds__(128) void combine_kernel(
    const __half* __restrict__ C1h,   // Q | Kc | Vc | S  (ld 4096)
    const float* __restrict__ bk, const float* __restrict__ bv,
    __half* __restrict__ A2h)
{
    const int b    = blockIdx.x;
    const int h    = threadIdx.x >> 5;
    const int lane = threadIdx.x & 31;
    const int base_d = h * HD + lane;

    float q[4][8], kc[4][8], vc[4][8];
    #pragma unroll
    for (int i = 0; i < 4; i++) {
        size_t row = (size_t)(i * NB + b) * N1A + base_d;
        #pragma unroll
        for (int e = 0; e < 8; e++) {
            q [i][e] = __half2float(C1h[row + e * 32]);
            kc[i][e] = __half2float(C1h[row + 1024 + e * 32]);
            vc[i][e] = __half2float(C1h[row + 2048 + e * 32]);
        }
    }
    float bke[8], bve[8];
    #pragma unroll
    for (int e = 0; e < 8; e++) {
        bke[e] = bk[base_d + e * 32];
        bve[e] = bv[base_d + e * 32];
    }

    float a[4][4];
    #pragma unroll
    for (int i = 0; i < 4; i++) {
        float s[4];
        #pragma unroll
        for (int j = 0; j < 4; j++) {
            float p = 0.f;
            #pragma unroll
            for (int e = 0; e < 8; e++)
                p = fmaf(q[i][e], kc[i][e] - kc[j][e] + bke[e], p);
            s[j] = wsum(p) * (1.f / 16.f);
        }
        float m = -1e30f;
        #pragma unroll
        for (int j = 0; j < 4; j++) if (j != i && s[j] > m) m = s[j];
        float den = 0.f;
        #pragma unroll
        for (int j = 0; j < 4; j++) {
            float ex = (j == i) ? 0.f : __expf(s[j] - m);
            a[i][j] = ex; den += ex;
        }
        float inv = 1.f / den;
        #pragma unroll
        for (int j = 0; j < 4; j++) a[i][j] *= inv;
    }

    #pragma unroll
    for (int i = 0; i < 4; i++) {
        __half* row = A2h + (size_t)(i * NB + b) * DD;
        #pragma unroll
        for (int e = 0; e < 8; e++) {
            float c = vc[i][e] + bve[e];
            #pragma unroll
            for (int j = 0; j < 4; j++)
                c = fmaf(-a[i][j], vc[j][e], c);
            row[base_d + e * 32] = __float2half(c);
        }
    }
}

// --------------------------- logits ----------------------------------------
__global__ __launch_bounds__(256) void logits_kernel(
    const float* __restrict__ D, const float* __restrict__ Wc,
    const float* __restrict__ bc, float* __restrict__ out)
{
    const int warp = (blockIdx.x * blockDim.x + threadIdx.x) >> 5;
    const int lane = threadIdx.x & 31;
    if (warp >= MTOT) return;
    const float* drow = D + (size_t)warp * DD;
    float s0 = 0.f, s1 = 0.f, s2 = 0.f, s3 = 0.f;
    for (int k = lane; k < DD; k += 32) {
        float d = drow[k];
        s0 = fmaf(d, Wc[k],          s0);
        s1 = fmaf(d, Wc[DD + k],     s1);
        s2 = fmaf(d, Wc[2 * DD + k], s2);
        s3 = fmaf(d, Wc[3 * DD + k], s3);
    }
    s0 = wsum(s0); s1 = wsum(s1); s2 = wsum(s2); s3 = wsum(s3);
    if (lane == 0) {
        out[(size_t)warp * 4 + 0] = s0 + bc[0];
        out[(size_t)warp * 4 + 1] = s1 + bc[1];
        out[(size_t)warp * 4 + 2] = s2 + bc[2];
        out[(size_t)warp * 4 + 3] = s3 + bc[3];
    }
}

// ---------------------------------------------------------------------------
extern "C" void kernel_launch(void* const* d_in, const int* in_sizes, int n_in,
                              void* d_out, int out_size)
{
    const float* X1   = (const float*)d_in[0];
    const float* X2   = (const float*)d_in[1];
    const float* X3   = (const float*)d_in[2];
    const float* X4   = (const float*)d_in[3];
    const float* Wq   = (const float*)d_in[4];
    const float* bq   = (const float*)d_in[5];
    const float* Wv_s = (const float*)d_in[8];
    const float* bv_s = (const float*)d_in[9];
    const float* Wo_s = (const float*)d_in[10];
    const float* bo_s = (const float*)d_in[11];
    const float* Wk_c = (const float*)d_in[12];
    const float* bk_c = (const float*)d_in[13];
    const float* Wv_c = (const float*)d_in[14];
    const float* bv_c = (const float*)d_in[15];
    const float* Wo_c = (const float*)d_in[16];
    const float* bo_c = (const float*)d_in[17];
    const float* Wc   = (const float*)d_in[18];
    const float* bc   = (const float*)d_in[19];

    float* out    = (float*)d_out;
    float* logits = out + (size_t)MTOT * DD;

    __nv_bfloat16 *gWosS, *gWvsT;
    __half *gXh, *gWh, *gC1h, *gA2h;
    float *gWeff, *gb1a, *gzero;
    cudaGetSymbolAddress((void**)&gXh,   g_Xh);
    cudaGetSymbolAddress((void**)&gWh,   g_Wh);
    cudaGetSymbolAddress((void**)&gC1h,  g_C1h);
    cudaGetSymbolAddress((void**)&gA2h,  g_A2h);
    cudaGetSymbolAddress((void**)&gWosS, g_WosS);
    cudaGetSymbolAddress((void**)&gWvsT, g_WvsT);
    cudaGetSymbolAddress((void**)&gWeff, g_Weff);
    cudaGetSymbolAddress((void**)&gb1a,  g_b1a);
    cudaGetSymbolAddress((void**)&gzero, g_zero);

    cudaFuncSetAttribute((const void*)gemm_mma<false, false>,
                         cudaFuncAttributeMaxDynamicSharedMemorySize, GEMM_SMEM);
    cudaFuncSetAttribute((const void*)gemm_mma<true, true>,
                         cudaFuncAttributeMaxDynamicSharedMemorySize, GEMM_SMEM);
    cudaFuncSetAttribute((const void*)gemm_mma<true, false>,
                         cudaFuncAttributeMaxDynamicSharedMemorySize, GEMM_SMEM);

    // prep: fp16 casts + exact weight-space fold of the self path
    x_to_half_kernel<<<MTOT, 256>>>(X1, X2, X3, X4, gXh);
    to_half_kernel<<<1024, 256>>>(Wq,   gWh);
    to_half_kernel<<<1024, 256>>>(Wk_c, gWh + (size_t)1024 * DD);
    to_half_kernel<<<1024, 256>>>(Wv_c, gWh + (size_t)2048 * DD);
    to_half_kernel<<<1024, 256>>>(Wo_c, gWh + (size_t)4096 * DD);
    split_Ahl<<<1024, 256>>>(Wo_s, gWosS);
    transpose_split_B<<<4096, 256>>>(Wv_s, gWvsT);

    // Weff[o,i] = sum_m Wos[o,m] * Wvs[m,i]  (bf16 3-term, exact to ~2^-16)
    gemm_mma<false, false><<<dim3(4, 8), 256, GEMM_SMEM>>>(
        (const uint16_t*)gWosS, (const uint16_t*)gWvsT, gzero, nullptr, 0,
        gWeff, 1024, 1024, K1);
    to_half_kernel<<<1024, 256>>>(gWeff, gWh + (size_t)3072 * DD);

    bias_init_kernel<<<4, 256>>>(bq, gb1a);
    bs_eff_kernel<<<128, 256>>>(Wo_s, bv_s, bo_s, gb1a);

    // GEMM1 (fp16 in/out): C1h[32768,4096] = Xh @ [Wq;Wkc;Wvc;Weff]^T + b1a
    gemm_mma<true, true><<<dim3(N1A / 256, MTOT / 128), 256, GEMM_SMEM>>>(
        (const uint16_t*)gXh, (const uint16_t*)gWh, gb1a, nullptr, 0,
        gC1h, MTOT, N1A, DD);

    // attention combine -> ctx fp16 into A2h
    combine_kernel<<<NB, 128>>>(gC1h, bk_c, bv_c, gA2h);

    // GEMM2 (fp16 in, fp32 out): d = ctx @ Wo_c^T + bo_c + S (fp16 addend)
    gemm_mma<true, false><<<dim3(DD / 256, MTOT / 128), 256, GEMM_SMEM>>>(
        (const uint16_t*)gA2h, (const uint16_t*)(gWh + (size_t)4096 * DD),
        bo_c, gC1h + 3072, N1A, out, MTOT, DD, DD);

    // logits = d @ Wc^T + bc
    logits_kernel<<<MTOT / 8, 256>>>(out, Wc, bc, logits);
}

// round 11
// speedup vs baseline: 7.7814x; 1.0351x over previous
#include <cuda_runtime.h>
#include <cuda_bf16.h>
#include <cuda_fp16.h>
#include <cstdint>
#include <cstddef>

// ---------------------------------------------------------------------------
// MultiModalClassifier, GB300, mma.sync fp16 GEMMs, fp16 intermediates.
//   B=8192, D=1024, H=4 (hd=256), C=4, M=32768
// Algebra (R9 structure — R10 showed the cross-path output fold is INVALID
// because attention weights are per-head):
//   self_out = X@Weff^T + bS,  Weff = Wo_s@Wv_s, bS = Wo_s@bv_s + bo_s
//   cross: K_ij = Kc_i - Kc_j + bk_c, V_ij = Vc_i - Vc_j + bv_c
//   d = S + ctx@Wo_c^T + bo_c
// Precision: fp16 single GEMMs + fp16 intermediates; Weff via bf16 3-term
// split (exact to ~2^-16), computed split-K (6 chunks) + deterministic reduce.
// ---------------------------------------------------------------------------

#define NB 8192
#define DD 1024
#define MTOT 32768
#define HD 256
#define K1 3072
#define N1A 4096          // Q | Kc | Vc | S

// ------------------------------ scratch ------------------------------------
__device__ __half        g_Xh  [(size_t)MTOT * DD];    // 64 MB
__device__ __half        g_Wh  [(size_t)5120 * DD];    // 10 MB (Wq;Wkc;Wvc;Weff;Woc)
__device__ __half        g_C1h [(size_t)MTOT * N1A];   // 256 MB (Q|Kc|Vc|S)
__device__ __half        g_A2h [(size_t)MTOT * DD];    // 64 MB  (ctx fp16)
__device__ __nv_bfloat16 g_WosS[(size_t)DD * K1];      // 6 MB (A split of Wo_s)
__device__ __nv_bfloat16 g_WvsT[(size_t)DD * K1];      // 6 MB (B split of Wv_s^T)
__device__ float         g_part[(size_t)6 * DD * DD];  // 24 MB split-K partials
__device__ float         g_b1a[N1A];
__device__ float         g_zero[DD];                    // never written: zeros

// --------------------------- PTX helpers -----------------------------------
__device__ __forceinline__ uint32_t smem_u32(const void* p) {
    uint32_t a;
    asm("{ .reg .u64 t; cvta.to.shared.u64 t, %1; cvt.u32.u64 %0, t; }"
        : "=r"(a) : "l"(p));
    return a;
}

#define CP_ASYNC16(dst, src) \
    asm volatile("cp.async.cg.shared.global [%0], [%1], 16;" :: "r"(dst), "l"(src))
#define CP_COMMIT() asm volatile("cp.async.commit_group;" ::: "memory")
#define CP_WAIT(n)  asm volatile("cp.async.wait_group %0;" :: "n"(n) : "memory")

#define LDMATRIX_X4(r0, r1, r2, r3, addr)                                     \
    asm volatile("ldmatrix.sync.aligned.m8n8.x4.shared.b16 {%0,%1,%2,%3}, [%4];" \
                 : "=r"(r0), "=r"(r1), "=r"(r2), "=r"(r3) : "r"(addr))

#define MMA_BF16(d0, d1, d2, d3, a0, a1, a2, a3, b0, b1)                      \
    asm volatile("mma.sync.aligned.m16n8k16.row.col.f32.bf16.bf16.f32 "       \
                 "{%0,%1,%2,%3}, {%4,%5,%6,%7}, {%8,%9}, {%0,%1,%2,%3};"      \
                 : "+f"(d0), "+f"(d1), "+f"(d2), "+f"(d3)                     \
                 : "r"(a0), "r"(a1), "r"(a2), "r"(a3), "r"(b0), "r"(b1))

#define MMA_F16(d0, d1, d2, d3, a0, a1, a2, a3, b0, b1)                       \
    asm volatile("mma.sync.aligned.m16n8k16.row.col.f32.f16.f16.f32 "         \
                 "{%0,%1,%2,%3}, {%4,%5,%6,%7}, {%8,%9}, {%0,%1,%2,%3};"      \
                 : "+f"(d0), "+f"(d1), "+f"(d2), "+f"(d3)                     \
                 : "r"(a0), "r"(a1), "r"(a2), "r"(a3), "r"(b0), "r"(b1))

// --------------------------- GEMM body -------------------------------------
// C tile = A[brow.., ld] @ B[bcol.., ld]^T + bias (+ fp16 add).
// CTA tile 128x256, BK=64, SW128 swizzle, 4-stage cp.async, 8 warps (2x4),
// warp tile 64x64. K = reduction length, ld = row stride of A and B.
#define STAGES 4
#define STAGE_BYTES 49152          // A 16KB + B 32KB
#define GEMM_SMEM (STAGES * STAGE_BYTES)

__device__ __forceinline__ void load_stage(
    const uint16_t* __restrict__ A, const uint16_t* __restrict__ B,
    int ld, int brow, int bcol, int kb, uint32_t st, int tid)
{
    #pragma unroll
    for (int i = 0; i < 12; i++) {
        int id = tid + 256 * i;
        if (id < 1024) {                       // A: 128 rows x 8 chunks
            int row = id >> 3, c = id & 7;
            const uint16_t* g = A + (size_t)(brow + row) * ld + kb * 64 + c * 8;
            CP_ASYNC16(st + row * 128 + ((c ^ (row & 7)) * 16), g);
        } else {                               // B: 256 rows x 8 chunks
            int idb = id - 1024;
            int row = idb >> 3, c = idb & 7;
            const uint16_t* g = B + (size_t)(bcol + row) * ld + kb * 64 + c * 8;
            CP_ASYNC16(st + 16384 + row * 128 + ((c ^ (row & 7)) * 16), g);
        }
    }
}

template <bool F16, bool OUT16>
__device__ __forceinline__ void gemm_body(
    const uint16_t* __restrict__ A, const uint16_t* __restrict__ B,
    const float* __restrict__ bias,
    const __half* __restrict__ add, int add_ld,
    void* __restrict__ Cv, int N, int K, int ld,
    int brow, int bcol, char* smem)
{
    const uint32_t sbase = smem_u32(smem);
    const int tid  = threadIdx.x;
    const int wid  = tid >> 5, lane = tid & 31;
    const int wm   = wid >> 2, wn = wid & 3;     // 2 x 4 warps
    const int NKB  = K >> 6;

    float acc[4][8][4];
    #pragma unroll
    for (int i = 0; i < 4; i++)
        #pragma unroll
        for (int j = 0; j < 8; j++)
            #pragma unroll
            for (int k = 0; k < 4; k++) acc[i][j][k] = 0.f;

    load_stage(A, B, ld, brow, bcol, 0, sbase, tid);                  CP_COMMIT();
    load_stage(A, B, ld, brow, bcol, 1, sbase + STAGE_BYTES, tid);    CP_COMMIT();
    load_stage(A, B, ld, brow, bcol, 2, sbase + 2 * STAGE_BYTES, tid);CP_COMMIT();

    int a_off[4], a_sw[4];
    #pragma unroll
    for (int mt = 0; mt < 4; mt++) {
        int r = wm * 64 + mt * 16 + (lane & 15);
        a_off[mt] = r * 128; a_sw[mt] = r & 7;
    }
    const int a_kh = lane >> 4;
    int b_off[4], b_sw[4];
    #pragma unroll
    for (int np = 0; np < 4; np++) {
        int r = wn * 64 + np * 16 + ((lane >> 4) & 1) * 8 + (lane & 7);
        b_off[np] = r * 128; b_sw[np] = r & 7;
    }
    const int b_kh = (lane >> 3) & 1;

    for (int kb = 0; kb < NKB; kb++) {
        if (kb < NKB - 2)       CP_WAIT(2);
        else if (kb == NKB - 2) CP_WAIT(1);
        else                    CP_WAIT(0);
        __syncthreads();
        if (kb + 3 < NKB) {
            load_stage(A, B, ld, brow, bcol, kb + 3,
                       sbase + ((kb + 3) & 3) * STAGE_BYTES, tid);
            CP_COMMIT();
        }
        const uint32_t sA = sbase + (kb & 3) * STAGE_BYTES;
        const uint32_t sB = sA + 16384;

        #pragma unroll
        for (int ks = 0; ks < 4; ks++) {
            uint32_t af[4][4], bf[4][4];
            #pragma unroll
            for (int mt = 0; mt < 4; mt++) {
                int cc = ks * 2 + a_kh;
                LDMATRIX_X4(af[mt][0], af[mt][1], af[mt][2], af[mt][3],
                            sA + a_off[mt] + ((cc ^ a_sw[mt]) * 16));
            }
            #pragma unroll
            for (int np = 0; np < 4; np++) {
                int cc = ks * 2 + b_kh;
                LDMATRIX_X4(bf[np][0], bf[np][1], bf[np][2], bf[np][3],
                            sB + b_off[np] + ((cc ^ b_sw[np]) * 16));
            }
            #pragma unroll
            for (int mt = 0; mt < 4; mt++)
                #pragma unroll
                for (int nt = 0; nt < 8; nt++) {
                    if (F16)
                        MMA_F16(acc[mt][nt][0], acc[mt][nt][1],
                                acc[mt][nt][2], acc[mt][nt][3],
                                af[mt][0], af[mt][1], af[mt][2], af[mt][3],
                                bf[nt >> 1][(nt & 1) * 2],
                                bf[nt >> 1][(nt & 1) * 2 + 1]);
                    else
                        MMA_BF16(acc[mt][nt][0], acc[mt][nt][1],
                                 acc[mt][nt][2], acc[mt][nt][3],
                                 af[mt][0], af[mt][1], af[mt][2], af[mt][3],
                                 bf[nt >> 1][(nt & 1) * 2],
                                 bf[nt >> 1][(nt & 1) * 2 + 1]);
                }
        }
    }

    #pragma unroll
    for (int mt = 0; mt < 4; mt++) {
        const int r0 = brow + wm * 64 + mt * 16 + (lane >> 2);
        #pragma unroll
        for (int nt = 0; nt < 8; nt++) {
            const int c0 = bcol + wn * 64 + nt * 8 + (lane & 3) * 2;
            const float bx = bias[c0], by = bias[c0 + 1];
            float a0 = acc[mt][nt][0] + bx, a1 = acc[mt][nt][1] + by;
            float a2 = acc[mt][nt][2] + bx, a3 = acc[mt][nt][3] + by;
            if (add) {
                a0 += __half2float(add[(size_t)r0 * add_ld + c0]);
                a1 += __half2float(add[(size_t)r0 * add_ld + c0 + 1]);
                a2 += __half2float(add[(size_t)(r0 + 8) * add_ld + c0]);
                a3 += __half2float(add[(size_t)(r0 + 8) * add_ld + c0 + 1]);
            }
            if (OUT16) {
                __half* C = (__half*)Cv;
                __half2 v0 = __floats2half2_rn(a0, a1);
                __half2 v1 = __floats2half2_rn(a2, a3);
                *(__half2*)&C[(size_t)r0 * N + c0]       = v0;
                *(__half2*)&C[(size_t)(r0 + 8) * N + c0] = v1;
            } else {
                float* C = (float*)Cv;
                float2 v0 = { a0, a1 }, v1 = { a2, a3 };
                *(float2*)&C[(size_t)r0 * N + c0]       = v0;
                *(float2*)&C[(size_t)(r0 + 8) * N + c0] = v1;
            }
        }
    }
}

// GEMM1: fp16 in/out, ld == K.
__global__ __launch_bounds__(256, 1)
void gemm1_kernel(const uint16_t* __restrict__ A, const uint16_t* __restrict__ B,
                  const float* __restrict__ bias, __half* __restrict__ C,
                  int N, int K)
{
    extern __shared__ __align__(1024) char smem[];
    gemm_body<true, true>(A, B, bias, nullptr, 0, C, N, K, K,
                          blockIdx.y * 128, blockIdx.x * 256, smem);
}

// GEMM2: fp16 in, fp32 out, fp16 addend (S).
__global__ __launch_bounds__(256, 1)
void gemm2_kernel(const uint16_t* __restrict__ A, const uint16_t* __restrict__ B,
                  const float* __restrict__ bias,
                  const __half* __restrict__ add, int add_ld,
                  float* __restrict__ C, int N, int K)
{
    extern __shared__ __align__(1024) char smem[];
    gemm_body<true, false>(A, B, bias, add, add_ld, C, N, K, K,
                           blockIdx.y * 128, blockIdx.x * 256, smem);
}

// Split-K Weff fold: chunk z covers K=512 of K1=3072 (ld=K1), bf16 3-term.
__global__ __launch_bounds__(256, 1)
void wgemm_splitk(const uint16_t* __restrict__ A0, const uint16_t* __restrict__ B0,
                  const float* __restrict__ zero, float* __restrict__ Cpart)
{
    extern __shared__ __align__(1024) char smem[];
    const int z = blockIdx.z;
    float* C = Cpart + (size_t)z * DD * DD;
    gemm_body<false, false>(A0 + z * 512, B0 + z * 512, zero, nullptr, 0,
                            C, DD, 512, K1,
                            blockIdx.y * 128, blockIdx.x * 256, smem);
}

// Reduce 6 split-K partials -> fp16 Weff into Wh block 3072 (S weights).
__global__ __launch_bounds__(256) void wreduce_kernel(
    const float* __restrict__ part, __half* __restrict__ Wh)
{
    size_t off = ((size_t)blockIdx.x * blockDim.x + threadIdx.x) * 4;
    float4 s = { 0.f, 0.f, 0.f, 0.f };
    #pragma unroll
    for (int c = 0; c < 6; c++) {
        float4 v = *(const float4*)&part[(size_t)c * DD * DD + off];
        s.x += v.x; s.y += v.y; s.z += v.z; s.w += v.w;
    }
    __half h[4] = { __float2half(s.x), __float2half(s.y),
                    __float2half(s.z), __float2half(s.w) };
    *(uint2*)&Wh[(size_t)3072 * DD + off] = *(uint2*)h;
}

// --------------------------- split / cast kernels ---------------------------
__device__ __forceinline__ void split1(float a, __nv_bfloat16& h, __nv_bfloat16& l) {
    h = __float2bfloat16(a);
    l = __float2bfloat16(a - __bfloat162float(h));
}

// A-operand layout [hi|lo|hi]  (Wo_s)
__global__ __launch_bounds__(256) void split_Ahl(
    const float* __restrict__ src, __nv_bfloat16* __restrict__ dst)
{
    size_t idx = (size_t)blockIdx.x * blockDim.x + threadIdx.x;
    size_t n = idx >> 8;
    int c4 = (int)(idx & 255) * 4;
    float4 v = *(const float4*)&src[n * DD + c4];
    __nv_bfloat16 h[4], l[4];
    split1(v.x, h[0], l[0]); split1(v.y, h[1], l[1]);
    split1(v.z, h[2], l[2]); split1(v.w, h[3], l[3]);
    __nv_bfloat16* row = dst + n * K1;
    *(uint2*)&row[c4]          = *(uint2*)h;
    *(uint2*)&row[DD + c4]     = *(uint2*)l;
    *(uint2*)&row[2 * DD + c4] = *(uint2*)h;
}

// T[i,m] = W[m,i], B layout [hi|hi|lo]  (Wv_s^T)
__global__ __launch_bounds__(256) void transpose_split_B(
    const float* __restrict__ W, __nv_bfloat16* __restrict__ dst)
{
    size_t idx = (size_t)blockIdx.x * blockDim.x + threadIdx.x;
    int m = (int)(idx >> 10);
    int i = (int)(idx & 1023);
    float v = W[(size_t)m * DD + i];
    __nv_bfloat16 h, l; split1(v, h, l);
    __nv_bfloat16* row = dst + (size_t)i * K1;
    row[m] = h; row[DD + m] = h; row[2 * DD + m] = l;
}

// Merged fp32 -> fp16 casts: Wq->0, Wkc->1024, Wvc->2048, Woc->4096 (rows of Wh)
__global__ __launch_bounds__(256) void w_to_half_kernel(
    const float* __restrict__ Wq, const float* __restrict__ Wkc,
    const float* __restrict__ Wvc, const float* __restrict__ Woc,
    __half* __restrict__ Wh)
{
    size_t idx = (size_t)blockIdx.x * blockDim.x + threadIdx.x;
    int sel = (int)(idx >> 18);                 // 2^18 float4 per matrix
    size_t off = (idx & ((1u << 18) - 1)) * 4;
    const float* src = (sel == 0) ? Wq : (sel == 1) ? Wkc : (sel == 2) ? Wvc : Woc;
    size_t base = (size_t)((sel == 3) ? 4096 : sel * 1024) * DD;
    float4 v = *(const float4*)&src[off];
    __half h[4] = { __float2half(v.x), __float2half(v.y),
                    __float2half(v.z), __float2half(v.w) };
    *(uint2*)&Wh[base + off] = *(uint2*)h;
}

// stacked X -> fp16
__global__ __launch_bounds__(256) void x_to_half_kernel(
    const float* __restrict__ X1, const float* __restrict__ X2,
    const float* __restrict__ X3, const float* __restrict__ X4,
    __half* __restrict__ Xh)
{
    size_t idx = (size_t)blockIdx.x * blockDim.x + threadIdx.x;
    size_t r = idx >> 8;
    int c4 = (int)(idx & 255) * 4;
    const float* src = (r < NB) ? X1 : (r < 2 * NB) ? X2 : (r < 3 * NB) ? X3 : X4;
    float4 v = *(const float4*)&src[(r & (NB - 1)) * DD + c4];
    __half hf[4] = { __float2half(v.x), __float2half(v.y),
                     __float2half(v.z), __float2half(v.w) };
    *(uint2*)&Xh[r * DD + c4] = *(uint2*)hf;
}

// --------------------------- bias kernels ----------------------------------
__device__ __forceinline__ float wsum(float v) {
    #pragma unroll
    for (int o = 16; o; o >>= 1) v += __shfl_xor_sync(0xffffffffu, v, o);
    return v;
}

__global__ __launch_bounds__(256) void bias_init_kernel(
    const float* __restrict__ bq, float* __restrict__ b1a)
{
    int i = blockIdx.x * blockDim.x + threadIdx.x;
    if (i < DD) { b1a[i] = bq[i]; b1a[DD + i] = 0.f; b1a[2 * DD + i] = 0.f; }
}

// b1a[3072+o] = dot(Wos[o,:], bvs) + bos[o]
__global__ __launch_bounds__(256) void bs_eff_kernel(
    const float* __restrict__ Wos, const float* __restrict__ bvs,
    const float* __restrict__ bos, float* __restrict__ b1a)
{
    int o = blockIdx.x * 8 + (threadIdx.x >> 5);
    int lane = threadIdx.x & 31;
    float s = 0.f;
    for (int k = lane; k < DD; k += 32)
        s = fmaf(Wos[(size_t)o * DD + k], bvs[k], s);
    s = wsum(s);
    if (lane == 0) b1a[3 * DD + o] = s + bos[o];
}

// --------------------------- combine ---------------------------------------
// ctx_i = Vc_i + bv_c - sum_j a_ij Vc_j, fp16 in (C1h) / fp16 out (A2h).
__global__ __launch_bounds__(128) void combine_kernel(
    const __half* __restrict__ C1h,   // Q | Kc | Vc | S  (ld 4096)
    const float* __restrict__ bk, const float* __restrict__ bv,
    __half* __restrict__ A2h)
{
    const int b    = blockIdx.x;
    const int h    = threadIdx.x >> 5;
    const int lane = threadIdx.x & 31;
    const int base_d = h * HD + lane;

    float q[4][8], kc[4][8], vc[4][8];
    #pragma unroll
    for (int i = 0; i < 4; i++) {
        size_t row = (size_t)(i * NB + b) * N1A + base_d;
        #pragma unroll
        for (int e = 0; e < 8; e++) {
            q [i][e] = __half2float(C1h[row + e * 32]);
            kc[i][e] = __half2float(C1h[row + 1024 + e * 32]);
            vc[i][e] = __half2float(C1h[row + 2048 + e * 32]);
        }
    }
    float bke[8], bve[8];
    #pragma unroll
    for (int e = 0; e < 8; e++) {
        bke[e] = bk[base_d + e * 32];
        bve[e] = bv[base_d + e * 32];
    }

    float a[4][4];
    #pragma unroll
    for (int i = 0; i < 4; i++) {
        float s[4];
        #pragma unroll
        for (int j = 0; j < 4; j++) {
            float p = 0.f;
            #pragma unroll
            for (int e = 0; e < 8; e++)
                p = fmaf(q[i][e], kc[i][e] - kc[j][e] + bke[e], p);
            s[j] = wsum(p) * (1.f / 16.f);
        }
        float m = -1e30f;
        #pragma unroll
        for (int j = 0; j < 4; j++) if (j != i && s[j] > m) m = s[j];
        float den = 0.f;
        #pragma unroll
        for (int j = 0; j < 4; j++) {
            float ex = (j == i) ? 0.f : __expf(s[j] - m);
            a[i][j] = ex; den += ex;
        }
        float inv = 1.f / den;
        #pragma unroll
        for (int j = 0; j < 4; j++) a[i][j] *= inv;
    }

    #pragma unroll
    for (int i = 0; i < 4; i++) {
        __half* row = A2h + (size_t)(i * NB + b) * DD;
        #pragma unroll
        for (int e = 0; e < 8; e++) {
            float c = vc[i][e] + bve[e];
            #pragma unroll
            for (int j = 0; j < 4; j++)
                c = fmaf(-a[i][j], vc[j][e], c);
            row[base_d + e * 32] = __float2half(c);
        }
    }
}

// --------------------------- logits ----------------------------------------
__global__ __launch_bounds__(256) void logits_kernel(
    const float* __restrict__ D, const float* __restrict__ Wc,
    const float* __restrict__ bc, float* __restrict__ out)
{
    const int warp = (blockIdx.x * blockDim.x + threadIdx.x) >> 5;
    const int lane = threadIdx.x & 31;
    if (warp >= MTOT) return;
    const float* drow = D + (size_t)warp * DD;
    float s0 = 0.f, s1 = 0.f, s2 = 0.f, s3 = 0.f;
    for (int k = lane; k < DD; k += 32) {
        float d = drow[k];
        s0 = fmaf(d, Wc[k],          s0);
        s1 = fmaf(d, Wc[DD + k],     s1);
        s2 = fmaf(d, Wc[2 * DD + k], s2);
        s3 = fmaf(d, Wc[3 * DD + k], s3);
    }
    s0 = wsum(s0); s1 = wsum(s1); s2 = wsum(s2); s3 = wsum(s3);
    if (lane == 0) {
        out[(size_t)warp * 4 + 0] = s0 + bc[0];
        out[(size_t)warp * 4 + 1] = s1 + bc[1];
        out[(size_t)warp * 4 + 2] = s2 + bc[2];
        out[(size_t)warp * 4 + 3] = s3 + bc[3];
    }
}

// ---------------------------------------------------------------------------
extern "C" void kernel_launch(void* const* d_in, const int* in_sizes, int n_in,
                              void* d_out, int out_size)
{
    const float* X1   = (const float*)d_in[0];
    const float* X2   = (const float*)d_in[1];
    const float* X3   = (const float*)d_in[2];
    const float* X4   = (const float*)d_in[3];
    const float* Wq   = (const float*)d_in[4];
    const float* bq   = (const float*)d_in[5];
    const float* Wv_s = (const float*)d_in[8];
    const float* bv_s = (const float*)d_in[9];
    const float* Wo_s = (const float*)d_in[10];
    const float* bo_s = (const float*)d_in[11];
    const float* Wk_c = (const float*)d_in[12];
    const float* bk_c = (const float*)d_in[13];
    const float* Wv_c = (const float*)d_in[14];
    const float* bv_c = (const float*)d_in[15];
    const float* Wo_c = (const float*)d_in[16];
    const float* bo_c = (const float*)d_in[17];
    const float* Wc   = (const float*)d_in[18];
    const float* bc   = (const float*)d_in[19];

    float* out    = (float*)d_out;
    float* logits = out + (size_t)MTOT * DD;

    __nv_bfloat16 *gWosS, *gWvsT;
    __half *gXh, *gWh, *gC1h, *gA2h;
    float *gPart, *gb1a, *gzero;
    cudaGetSymbolAddress((void**)&gXh,   g_Xh);
    cudaGetSymbolAddress((void**)&gWh,   g_Wh);
    cudaGetSymbolAddress((void**)&gC1h,  g_C1h);
    cudaGetSymbolAddress((void**)&gA2h,  g_A2h);
    cudaGetSymbolAddress((void**)&gWosS, g_WosS);
    cudaGetSymbolAddress((void**)&gWvsT, g_WvsT);
    cudaGetSymbolAddress((void**)&gPart, g_part);
    cudaGetSymbolAddress((void**)&gb1a,  g_b1a);
    cudaGetSymbolAddress((void**)&gzero, g_zero);

    cudaFuncSetAttribute((const void*)gemm1_kernel,
                         cudaFuncAttributeMaxDynamicSharedMemorySize, GEMM_SMEM);
    cudaFuncSetAttribute((const void*)gemm2_kernel,
                         cudaFuncAttributeMaxDynamicSharedMemorySize, GEMM_SMEM);
    cudaFuncSetAttribute((const void*)wgemm_splitk,
                         cudaFuncAttributeMaxDynamicSharedMemorySize, GEMM_SMEM);

    // prep: fp16 casts + bf16 splits for the exact Weff fold
    x_to_half_kernel<<<MTOT, 256>>>(X1, X2, X3, X4, gXh);
    w_to_half_kernel<<<4096, 256>>>(Wq, Wk_c, Wv_c, Wo_c, gWh);
    split_Ahl<<<1024, 256>>>(Wo_s, gWosS);
    transpose_split_B<<<4096, 256>>>(Wv_s, gWvsT);

    // Weff = Wo_s@Wv_s via split-K bf16 3-term (6 x K=512) + reduce -> fp16
    wgemm_splitk<<<dim3(4, 8, 6), 256, GEMM_SMEM>>>(
        (const uint16_t*)gWosS, (const uint16_t*)gWvsT, gzero, gPart);
    wreduce_kernel<<<1024, 256>>>(gPart, gWh);

    bias_init_kernel<<<4, 256>>>(bq, gb1a);
    bs_eff_kernel<<<128, 256>>>(Wo_s, bv_s, bo_s, gb1a);

    // GEMM1 (fp16 in/out): C1h[32768,4096] = Xh @ [Wq;Wkc;Wvc;Weff]^T + b1a
    gemm1_kernel<<<dim3(N1A / 256, MTOT / 128), 256, GEMM_SMEM>>>(
        (const uint16_t*)gXh, (const uint16_t*)gWh, gb1a, gC1h, N1A, DD);

    // attention combine -> ctx fp16 into A2h
    combine_kernel<<<NB, 128>>>(gC1h, bk_c, bv_c, gA2h);

    // GEMM2 (fp16 in, fp32 out): d = ctx @ Wo_c^T + bo_c + S (fp16 addend)
    gemm2_kernel<<<dim3(DD / 256, MTOT / 128), 256, GEMM_SMEM>>>(
        (const uint16_t*)gA2h, (const uint16_t*)(gWh + (size_t)4096 * DD),
        bo_c, gC1h + 3072, N1A, out, DD, DD);

    // logits = d @ Wc^T + bc
    logits_kernel<<<MTOT / 8, 256>>>(out, Wc, bc, logits);
}

// round 12
// speedup vs baseline: 8.1431x; 1.0465x over previous
#include <cuda_runtime.h>
#include <cuda_bf16.h>
#include <cuda_fp16.h>
#include <cstdint>
#include <cstddef>

// ---------------------------------------------------------------------------
// MultiModalClassifier, GB300, mma.sync fp16 GEMMs, fp16 intermediates.
//   B=8192, D=1024, H=4 (hd=256), C=4, M=32768
// Algebra (cross-path output fold is INVALID — per-head attention weights):
//   self_out = X@Weff^T + bS,  Weff = Wo_s@Wv_s, bS = Wo_s@bv_s + bo_s
//   cross: K_ij = Kc_i - Kc_j + bk_c, V_ij = Vc_i - Vc_j + bv_c
//   d = S + ctx@Wo_c^T + bo_c;  logits fused into GEMM2 epilogue.
// Precision: fp16 single GEMMs + fp16 intermediates; Weff via bf16 3-term
// split (exact ~2^-16), split-K (6 chunks) + deterministic reduce.
// ---------------------------------------------------------------------------

#define NB 8192
#define DD 1024
#define MTOT 32768
#define HD 256
#define K1 3072
#define N1A 4096          // Q | Kc | Vc | S

// ------------------------------ scratch ------------------------------------
__device__ __half        g_Xh  [(size_t)MTOT * DD];    // 64 MB
__device__ __half        g_Wh  [(size_t)5120 * DD];    // 10 MB (Wq;Wkc;Wvc;Weff;Woc)
__device__ __half        g_C1h [(size_t)MTOT * N1A];   // 256 MB (Q|Kc|Vc|S)
__device__ __half        g_A2h [(size_t)MTOT * DD];    // 64 MB  (ctx fp16)
__device__ __nv_bfloat16 g_WosS[(size_t)DD * K1];      // 6 MB (A split of Wo_s)
__device__ __nv_bfloat16 g_WvsT[(size_t)DD * K1];      // 6 MB (B split of Wv_s^T)
__device__ float         g_part[(size_t)6 * DD * DD];  // 24 MB split-K partials
__device__ float         g_plog[(size_t)4 * MTOT * 4]; // 2 MB logits partials
__device__ float         g_b1a[N1A];
__device__ float         g_zero[DD];                    // never written: zeros

// --------------------------- PTX helpers -----------------------------------
__device__ __forceinline__ uint32_t smem_u32(const void* p) {
    uint32_t a;
    asm("{ .reg .u64 t; cvta.to.shared.u64 t, %1; cvt.u32.u64 %0, t; }"
        : "=r"(a) : "l"(p));
    return a;
}

#define CP_ASYNC16(dst, src) \
    asm volatile("cp.async.cg.shared.global [%0], [%1], 16;" :: "r"(dst), "l"(src))
#define CP_COMMIT() asm volatile("cp.async.commit_group;" ::: "memory")
#define CP_WAIT(n)  asm volatile("cp.async.wait_group %0;" :: "n"(n) : "memory")

#define LDMATRIX_X4(r0, r1, r2, r3, addr)                                     \
    asm volatile("ldmatrix.sync.aligned.m8n8.x4.shared.b16 {%0,%1,%2,%3}, [%4];" \
                 : "=r"(r0), "=r"(r1), "=r"(r2), "=r"(r3) : "r"(addr))

#define MMA_BF16(d0, d1, d2, d3, a0, a1, a2, a3, b0, b1)                      \
    asm volatile("mma.sync.aligned.m16n8k16.row.col.f32.bf16.bf16.f32 "       \
                 "{%0,%1,%2,%3}, {%4,%5,%6,%7}, {%8,%9}, {%0,%1,%2,%3};"      \
                 : "+f"(d0), "+f"(d1), "+f"(d2), "+f"(d3)                     \
                 : "r"(a0), "r"(a1), "r"(a2), "r"(a3), "r"(b0), "r"(b1))

#define MMA_F16(d0, d1, d2, d3, a0, a1, a2, a3, b0, b1)                       \
    asm volatile("mma.sync.aligned.m16n8k16.row.col.f32.f16.f16.f32 "         \
                 "{%0,%1,%2,%3}, {%4,%5,%6,%7}, {%8,%9}, {%0,%1,%2,%3};"      \
                 : "+f"(d0), "+f"(d1), "+f"(d2), "+f"(d3)                     \
                 : "r"(a0), "r"(a1), "r"(a2), "r"(a3), "r"(b0), "r"(b1))

// --------------------------- GEMM body -------------------------------------
// C tile = A[brow.., ld] @ B[bcol.., ld]^T + bias (+ fp16 add).
// CTA tile 128x256, BK=64, SW128 swizzle, 4-stage cp.async, 8 warps (2x4),
// warp tile 64x64. DOLOG: also emit per-CTA logits partials (deterministic).
#define STAGES 4
#define STAGE_BYTES 49152          // A 16KB + B 32KB
#define GEMM_SMEM (STAGES * STAGE_BYTES)

__device__ __forceinline__ void load_stage(
    const uint16_t* __restrict__ A, const uint16_t* __restrict__ B,
    int ld, int brow, int bcol, int kb, uint32_t st, int tid)
{
    #pragma unroll
    for (int i = 0; i < 12; i++) {
        int id = tid + 256 * i;
        if (id < 1024) {                       // A: 128 rows x 8 chunks
            int row = id >> 3, c = id & 7;
            const uint16_t* g = A + (size_t)(brow + row) * ld + kb * 64 + c * 8;
            CP_ASYNC16(st + row * 128 + ((c ^ (row & 7)) * 16), g);
        } else {                               // B: 256 rows x 8 chunks
            int idb = id - 1024;
            int row = idb >> 3, c = idb & 7;
            const uint16_t* g = B + (size_t)(bcol + row) * ld + kb * 64 + c * 8;
            CP_ASYNC16(st + 16384 + row * 128 + ((c ^ (row & 7)) * 16), g);
        }
    }
}

template <bool F16, bool OUT16, bool DOLOG>
__device__ __forceinline__ void gemm_body(
    const uint16_t* __restrict__ A, const uint16_t* __restrict__ B,
    const float* __restrict__ bias,
    const __half* __restrict__ add, int add_ld,
    void* __restrict__ Cv, int N, int K, int ld,
    int brow, int bcol, int bxid,
    const float* __restrict__ Wc, float* __restrict__ plog, char* smem)
{
    __shared__ float sred[4][128][4];            // used only when DOLOG
    const uint32_t sbase = smem_u32(smem);
    const int tid  = threadIdx.x;
    const int wid  = tid >> 5, lane = tid & 31;
    const int wm   = wid >> 2, wn = wid & 3;     // 2 x 4 warps
    const int NKB  = K >> 6;

    float acc[4][8][4];
    #pragma unroll
    for (int i = 0; i < 4; i++)
        #pragma unroll
        for (int j = 0; j < 8; j++)
            #pragma unroll
            for (int k = 0; k < 4; k++) acc[i][j][k] = 0.f;

    load_stage(A, B, ld, brow, bcol, 0, sbase, tid);                  CP_COMMIT();
    load_stage(A, B, ld, brow, bcol, 1, sbase + STAGE_BYTES, tid);    CP_COMMIT();
    load_stage(A, B, ld, brow, bcol, 2, sbase + 2 * STAGE_BYTES, tid);CP_COMMIT();

    int a_off[4], a_sw[4];
    #pragma unroll
    for (int mt = 0; mt < 4; mt++) {
        int r = wm * 64 + mt * 16 + (lane & 15);
        a_off[mt] = r * 128; a_sw[mt] = r & 7;
    }
    const int a_kh = lane >> 4;
    int b_off[4], b_sw[4];
    #pragma unroll
    for (int np = 0; np < 4; np++) {
        int r = wn * 64 + np * 16 + ((lane >> 4) & 1) * 8 + (lane & 7);
        b_off[np] = r * 128; b_sw[np] = r & 7;
    }
    const int b_kh = (lane >> 3) & 1;

    for (int kb = 0; kb < NKB; kb++) {
        if (kb < NKB - 2)       CP_WAIT(2);
        else if (kb == NKB - 2) CP_WAIT(1);
        else                    CP_WAIT(0);
        __syncthreads();
        if (kb + 3 < NKB) {
            load_stage(A, B, ld, brow, bcol, kb + 3,
                       sbase + ((kb + 3) & 3) * STAGE_BYTES, tid);
            CP_COMMIT();
        }
        const uint32_t sA = sbase + (kb & 3) * STAGE_BYTES;
        const uint32_t sB = sA + 16384;

        #pragma unroll
        for (int ks = 0; ks < 4; ks++) {
            uint32_t af[4][4], bf[4][4];
            #pragma unroll
            for (int mt = 0; mt < 4; mt++) {
                int cc = ks * 2 + a_kh;
                LDMATRIX_X4(af[mt][0], af[mt][1], af[mt][2], af[mt][3],
                            sA + a_off[mt] + ((cc ^ a_sw[mt]) * 16));
            }
            #pragma unroll
            for (int np = 0; np < 4; np++) {
                int cc = ks * 2 + b_kh;
                LDMATRIX_X4(bf[np][0], bf[np][1], bf[np][2], bf[np][3],
                            sB + b_off[np] + ((cc ^ b_sw[np]) * 16));
            }
            #pragma unroll
            for (int mt = 0; mt < 4; mt++)
                #pragma unroll
                for (int nt = 0; nt < 8; nt++) {
                    if (F16)
                        MMA_F16(acc[mt][nt][0], acc[mt][nt][1],
                                acc[mt][nt][2], acc[mt][nt][3],
                                af[mt][0], af[mt][1], af[mt][2], af[mt][3],
                                bf[nt >> 1][(nt & 1) * 2],
                                bf[nt >> 1][(nt & 1) * 2 + 1]);
                    else
                        MMA_BF16(acc[mt][nt][0], acc[mt][nt][1],
                                 acc[mt][nt][2], acc[mt][nt][3],
                                 af[mt][0], af[mt][1], af[mt][2], af[mt][3],
                                 bf[nt >> 1][(nt & 1) * 2],
                                 bf[nt >> 1][(nt & 1) * 2 + 1]);
                }
        }
    }

    #pragma unroll
    for (int mt = 0; mt < 4; mt++) {
        const int r0 = brow + wm * 64 + mt * 16 + (lane >> 2);
        float p0[4] = {0.f, 0.f, 0.f, 0.f}, p1[4] = {0.f, 0.f, 0.f, 0.f};
        #pragma unroll
        for (int nt = 0; nt < 8; nt++) {
            const int c0 = bcol + wn * 64 + nt * 8 + (lane & 3) * 2;
            const float bx = bias[c0], by = bias[c0 + 1];
            float a0 = acc[mt][nt][0] + bx, a1 = acc[mt][nt][1] + by;
            float a2 = acc[mt][nt][2] + bx, a3 = acc[mt][nt][3] + by;
            if (add) {
                a0 += __half2float(add[(size_t)r0 * add_ld + c0]);
                a1 += __half2float(add[(size_t)r0 * add_ld + c0 + 1]);
                a2 += __half2float(add[(size_t)(r0 + 8) * add_ld + c0]);
                a3 += __half2float(add[(size_t)(r0 + 8) * add_ld + c0 + 1]);
            }
            if (OUT16) {
                __half* C = (__half*)Cv;
                __half2 v0 = __floats2half2_rn(a0, a1);
                __half2 v1 = __floats2half2_rn(a2, a3);
                *(__half2*)&C[(size_t)r0 * N + c0]       = v0;
                *(__half2*)&C[(size_t)(r0 + 8) * N + c0] = v1;
            } else {
                float* C = (float*)Cv;
                float2 v0 = { a0, a1 }, v1 = { a2, a3 };
                *(float2*)&C[(size_t)r0 * N + c0]       = v0;
                *(float2*)&C[(size_t)(r0 + 8) * N + c0] = v1;
            }
            if (DOLOG) {
                #pragma unroll
                for (int c = 0; c < 4; c++) {
                    float w0 = Wc[c * DD + c0], w1 = Wc[c * DD + c0 + 1];
                    p0[c] = fmaf(a0, w0, fmaf(a1, w1, p0[c]));
                    p1[c] = fmaf(a2, w0, fmaf(a3, w1, p1[c]));
                }
            }
        }
        if (DOLOG) {
            #pragma unroll
            for (int c = 0; c < 4; c++) {
                p0[c] += __shfl_xor_sync(0xffffffffu, p0[c], 1);
                p0[c] += __shfl_xor_sync(0xffffffffu, p0[c], 2);
                p1[c] += __shfl_xor_sync(0xffffffffu, p1[c], 1);
                p1[c] += __shfl_xor_sync(0xffffffffu, p1[c], 2);
            }
            if ((lane & 3) == 0) {
                int rl = wm * 64 + mt * 16 + (lane >> 2);
                #pragma unroll
                for (int c = 0; c < 4; c++) {
                    sred[wn][rl][c]     = p0[c];
                    sred[wn][rl + 8][c] = p1[c];
                }
            }
        }
    }
    if (DOLOG) {
        __syncthreads();
        for (int t = tid; t < 512; t += 256) {
            int row = t >> 2, c = t & 3;
            float s = sred[0][row][c] + sred[1][row][c]
                    + sred[2][row][c] + sred[3][row][c];
            plog[((size_t)bxid * MTOT + brow + row) * 4 + c] = s;
        }
    }
}

// GEMM1: fp16 in/out, ld == K.
__global__ __launch_bounds__(256, 1)
void gemm1_kernel(const uint16_t* __restrict__ A, const uint16_t* __restrict__ B,
                  const float* __restrict__ bias, __half* __restrict__ C,
                  int N, int K)
{
    extern __shared__ __align__(1024) char smem[];
    gemm_body<true, true, false>(A, B, bias, nullptr, 0, C, N, K, K,
                                 blockIdx.y * 128, blockIdx.x * 256, 0,
                                 nullptr, nullptr, smem);
}

// GEMM2: fp16 in, fp32 out, fp16 addend (S), fused logits partials.
__global__ __launch_bounds__(256, 1)
void gemm2_kernel(const uint16_t* __restrict__ A, const uint16_t* __restrict__ B,
                  const float* __restrict__ bias,
                  const __half* __restrict__ add, int add_ld,
                  float* __restrict__ C, int N, int K,
                  const float* __restrict__ Wc, float* __restrict__ plog)
{
    extern __shared__ __align__(1024) char smem[];
    gemm_body<true, false, true>(A, B, bias, add, add_ld, C, N, K, K,
                                 blockIdx.y * 128, blockIdx.x * 256,
                                 blockIdx.x, Wc, plog, smem);
}

// Split-K Weff fold: chunk z covers K=512 of K1=3072 (ld=K1), bf16 3-term.
__global__ __launch_bounds__(256, 1)
void wgemm_splitk(const uint16_t* __restrict__ A0, const uint16_t* __restrict__ B0,
                  const float* __restrict__ zero, float* __restrict__ Cpart)
{
    extern __shared__ __align__(1024) char smem[];
    const int z = blockIdx.z;
    float* C = Cpart + (size_t)z * DD * DD;
    gemm_body<false, false, false>(A0 + z * 512, B0 + z * 512, zero, nullptr, 0,
                                   C, DD, 512, K1,
                                   blockIdx.y * 128, blockIdx.x * 256, 0,
                                   nullptr, nullptr, smem);
}

// Reduce 6 split-K partials -> fp16 Weff into Wh block 3072 (S weights).
__global__ __launch_bounds__(256) void wreduce_kernel(
    const float* __restrict__ part, __half* __restrict__ Wh)
{
    size_t off = ((size_t)blockIdx.x * blockDim.x + threadIdx.x) * 4;
    float4 s = { 0.f, 0.f, 0.f, 0.f };
    #pragma unroll
    for (int c = 0; c < 6; c++) {
        float4 v = *(const float4*)&part[(size_t)c * DD * DD + off];
        s.x += v.x; s.y += v.y; s.z += v.z; s.w += v.w;
    }
    __half h[4] = { __float2half(s.x), __float2half(s.y),
                    __float2half(s.z), __float2half(s.w) };
    *(uint2*)&Wh[(size_t)3072 * DD + off] = *(uint2*)h;
}

// Reduce logits partials (fixed order over 4 column blocks) + bc.
__global__ __launch_bounds__(256) void reduce_logits_kernel(
    const float* __restrict__ plog, const float* __restrict__ bc,
    float* __restrict__ logits)
{
    size_t idx = (size_t)blockIdx.x * 256 + threadIdx.x;   // MTOT*4 total
    float s = bc[idx & 3];
    s += plog[idx];
    s += plog[(size_t)MTOT * 4 + idx];
    s += plog[2 * (size_t)MTOT * 4 + idx];
    s += plog[3 * (size_t)MTOT * 4 + idx];
    logits[idx] = s;
}

// --------------------------- split / cast kernels ---------------------------
__device__ __forceinline__ void split1(float a, __nv_bfloat16& h, __nv_bfloat16& l) {
    h = __float2bfloat16(a);
    l = __float2bfloat16(a - __bfloat162float(h));
}

// A-operand layout [hi|lo|hi]  (Wo_s)
__global__ __launch_bounds__(256) void split_Ahl(
    const float* __restrict__ src, __nv_bfloat16* __restrict__ dst)
{
    size_t idx = (size_t)blockIdx.x * blockDim.x + threadIdx.x;
    size_t n = idx >> 8;
    int c4 = (int)(idx & 255) * 4;
    float4 v = *(const float4*)&src[n * DD + c4];
    __nv_bfloat16 h[4], l[4];
    split1(v.x, h[0], l[0]); split1(v.y, h[1], l[1]);
    split1(v.z, h[2], l[2]); split1(v.w, h[3], l[3]);
    __nv_bfloat16* row = dst + n * K1;
    *(uint2*)&row[c4]          = *(uint2*)h;
    *(uint2*)&row[DD + c4]     = *(uint2*)l;
    *(uint2*)&row[2 * DD + c4] = *(uint2*)h;
}

// Tiled transpose+split: dst[i][..] gets W[:,i], B layout [hi|hi|lo].
// 32x32 fp32 tile via smem; 8-byte vector stores along contiguous m.
__global__ __launch_bounds__(256) void transpose_split_B(
    const float* __restrict__ W, __nv_bfloat16* __restrict__ dst)
{
    __shared__ float tile[32][33];
    const int i0 = (blockIdx.x & 31) * 32;     // i tile (cols of W)
    const int m0 = (blockIdx.x >> 5) * 32;     // m tile (rows of W)
    const int tx = threadIdx.x & 31, ty = threadIdx.x >> 5;   // 32 x 8
    #pragma unroll
    for (int r = 0; r < 4; r++)
        tile[ty * 4 + r][tx] = W[(size_t)(m0 + ty * 4 + r) * DD + i0 + tx];
    __syncthreads();
    const int il = threadIdx.x >> 3;           // 0..31
    const int mq = (threadIdx.x & 7) * 4;      // 0,4,..,28
    __nv_bfloat16 h[4], l[4];
    #pragma unroll
    for (int r = 0; r < 4; r++)
        split1(tile[mq + r][il], h[r], l[r]);
    __nv_bfloat16* row = dst + (size_t)(i0 + il) * K1 + m0 + mq;
    *(uint2*)&row[0]      = *(uint2*)h;
    *(uint2*)&row[DD]     = *(uint2*)h;
    *(uint2*)&row[2 * DD] = *(uint2*)l;
}

// Merged fp32 -> fp16 casts: Wq->0, Wkc->1024, Wvc->2048, Woc->4096 (rows of Wh)
__global__ __launch_bounds__(256) void w_to_half_kernel(
    const float* __restrict__ Wq, const float* __restrict__ Wkc,
    const float* __restrict__ Wvc, const float* __restrict__ Woc,
    __half* __restrict__ Wh)
{
    size_t idx = (size_t)blockIdx.x * blockDim.x + threadIdx.x;
    int sel = (int)(idx >> 18);                 // 2^18 float4 per matrix
    size_t off = (idx & ((1u << 18) - 1)) * 4;
    const float* src = (sel == 0) ? Wq : (sel == 1) ? Wkc : (sel == 2) ? Wvc : Woc;
    size_t base = (size_t)((sel == 3) ? 4096 : sel * 1024) * DD;
    float4 v = *(const float4*)&src[off];
    __half h[4] = { __float2half(v.x), __float2half(v.y),
                    __float2half(v.z), __float2half(v.w) };
    *(uint2*)&Wh[base + off] = *(uint2*)h;
}

// stacked X -> fp16
__global__ __launch_bounds__(256) void x_to_half_kernel(
    const float* __restrict__ X1, const float* __restrict__ X2,
    const float* __restrict__ X3, const float* __restrict__ X4,
    __half* __restrict__ Xh)
{
    size_t idx = (size_t)blockIdx.x * blockDim.x + threadIdx.x;
    size_t r = idx >> 8;
    int c4 = (int)(idx & 255) * 4;
    const float* src = (r < NB) ? X1 : (r < 2 * NB) ? X2 : (r < 3 * NB) ? X3 : X4;
    float4 v = *(const float4*)&src[(r & (NB - 1)) * DD + c4];
    __half hf[4] = { __float2half(v.x), __float2half(v.y),
                     __float2half(v.z), __float2half(v.w) };
    *(uint2*)&Xh[r * DD + c4] = *(uint2*)hf;
}

// --------------------------- bias kernels ----------------------------------
__device__ __forceinline__ float wsum(float v) {
    #pragma unroll
    for (int o = 16; o; o >>= 1) v += __shfl_xor_sync(0xffffffffu, v, o);
    return v;
}

__global__ __launch_bounds__(256) void bias_init_kernel(
    const float* __restrict__ bq, float* __restrict__ b1a)
{
    int i = blockIdx.x * blockDim.x + threadIdx.x;
    if (i < DD) { b1a[i] = bq[i]; b1a[DD + i] = 0.f; b1a[2 * DD + i] = 0.f; }
}

// b1a[3072+o] = dot(Wos[o,:], bvs) + bos[o]
__global__ __launch_bounds__(256) void bs_eff_kernel(
    const float* __restrict__ Wos, const float* __restrict__ bvs,
    const float* __restrict__ bos, float* __restrict__ b1a)
{
    int o = blockIdx.x * 8 + (threadIdx.x >> 5);
    int lane = threadIdx.x & 31;
    float s = 0.f;
    for (int k = lane; k < DD; k += 32)
        s = fmaf(Wos[(size_t)o * DD + k], bvs[k], s);
    s = wsum(s);
    if (lane == 0) b1a[3 * DD + o] = s + bos[o];
}

// --------------------------- combine ---------------------------------------
// ctx_i = Vc_i + bv_c - sum_j a_ij Vc_j, fp16 in (C1h) / fp16 out (A2h).
__global__ __launch_bounds__(128) void combine_kernel(
    const __half* __restrict__ C1h,   // Q | Kc | Vc | S  (ld 4096)
    const float* __restrict__ bk, const float* __restrict__ bv,
    __half* __restrict__ A2h)
{
    const int b    = blockIdx.x;
    const int h    = threadIdx.x >> 5;
    const int lane = threadIdx.x & 31;
    const int base_d = h * HD + lane;

    float q[4][8], kc[4][8], vc[4][8];
    #pragma unroll
    for (int i = 0; i < 4; i++) {
        size_t row = (size_t)(i * NB + b) * N1A + base_d;
        #pragma unroll
        for (int e = 0; e < 8; e++) {
            q [i][e] = __half2float(C1h[row + e * 32]);
            kc[i][e] = __half2float(C1h[row + 1024 + e * 32]);
            vc[i][e] = __half2float(C1h[row + 2048 + e * 32]);
        }
    }
    float bke[8], bve[8];
    #pragma unroll
    for (int e = 0; e < 8; e++) {
        bke[e] = bk[base_d + e * 32];
        bve[e] = bv[base_d + e * 32];
    }

    float a[4][4];
    #pragma unroll
    for (int i = 0; i < 4; i++) {
        float s[4];
        #pragma unroll
        for (int j = 0; j < 4; j++) {
            float p = 0.f;
            #pragma unroll
            for (int e = 0; e < 8; e++)
                p = fmaf(q[i][e], kc[i][e] - kc[j][e] + bke[e], p);
            s[j] = wsum(p) * (1.f / 16.f);
        }
        float m = -1e30f;
        #pragma unroll
        for (int j = 0; j < 4; j++) if (j != i && s[j] > m) m = s[j];
        float den = 0.f;
        #pragma unroll
        for (int j = 0; j < 4; j++) {
            float ex = (j == i) ? 0.f : __expf(s[j] - m);
            a[i][j] = ex; den += ex;
        }
        float inv = 1.f / den;
        #pragma unroll
        for (int j = 0; j < 4; j++) a[i][j] *= inv;
    }

    #pragma unroll
    for (int i = 0; i < 4; i++) {
        __half* row = A2h + (size_t)(i * NB + b) * DD;
        #pragma unroll
        for (int e = 0; e < 8; e++) {
            float c = vc[i][e] + bve[e];
            #pragma unroll
            for (int j = 0; j < 4; j++)
                c = fmaf(-a[i][j], vc[j][e], c);
            row[base_d + e * 32] = __float2half(c);
        }
    }
}

// ---------------------------------------------------------------------------
extern "C" void kernel_launch(void* const* d_in, const int* in_sizes, int n_in,
                              void* d_out, int out_size)
{
    const float* X1   = (const float*)d_in[0];
    const float* X2   = (const float*)d_in[1];
    const float* X3   = (const float*)d_in[2];
    const float* X4   = (const float*)d_in[3];
    const float* Wq   = (const float*)d_in[4];
    const float* bq   = (const float*)d_in[5];
    const float* Wv_s = (const float*)d_in[8];
    const float* bv_s = (const float*)d_in[9];
    const float* Wo_s = (const float*)d_in[10];
    const float* bo_s = (const float*)d_in[11];
    const float* Wk_c = (const float*)d_in[12];
    const float* bk_c = (const float*)d_in[13];
    const float* Wv_c = (const float*)d_in[14];
    const float* bv_c = (const float*)d_in[15];
    const float* Wo_c = (const float*)d_in[16];
    const float* bo_c = (const float*)d_in[17];
    const float* Wc   = (const float*)d_in[18];
    const float* bc   = (const float*)d_in[19];

    float* out    = (float*)d_out;
    float* logits = out + (size_t)MTOT * DD;

    __nv_bfloat16 *gWosS, *gWvsT;
    __half *gXh, *gWh, *gC1h, *gA2h;
    float *gPart, *gPlog, *gb1a, *gzero;
    cudaGetSymbolAddress((void**)&gXh,   g_Xh);
    cudaGetSymbolAddress((void**)&gWh,   g_Wh);
    cudaGetSymbolAddress((void**)&gC1h,  g_C1h);
    cudaGetSymbolAddress((void**)&gA2h,  g_A2h);
    cudaGetSymbolAddress((void**)&gWosS, g_WosS);
    cudaGetSymbolAddress((void**)&gWvsT, g_WvsT);
    cudaGetSymbolAddress((void**)&gPart, g_part);
    cudaGetSymbolAddress((void**)&gPlog, g_plog);
    cudaGetSymbolAddress((void**)&gb1a,  g_b1a);
    cudaGetSymbolAddress((void**)&gzero, g_zero);

    cudaFuncSetAttribute((const void*)gemm1_kernel,
                         cudaFuncAttributeMaxDynamicSharedMemorySize, GEMM_SMEM);
    cudaFuncSetAttribute((const void*)gemm2_kernel,
                         cudaFuncAttributeMaxDynamicSharedMemorySize, GEMM_SMEM);
    cudaFuncSetAttribute((const void*)wgemm_splitk,
                         cudaFuncAttributeMaxDynamicSharedMemorySize, GEMM_SMEM);

    // prep: fp16 casts + bf16 splits for the exact Weff fold
    x_to_half_kernel<<<MTOT, 256>>>(X1, X2, X3, X4, gXh);
    w_to_half_kernel<<<4096, 256>>>(Wq, Wk_c, Wv_c, Wo_c, gWh);
    split_Ahl<<<1024, 256>>>(Wo_s, gWosS);
    transpose_split_B<<<1024, 256>>>(Wv_s, gWvsT);

    // Weff = Wo_s@Wv_s via split-K bf16 3-term (6 x K=512) + reduce -> fp16
    wgemm_splitk<<<dim3(4, 8, 6), 256, GEMM_SMEM>>>(
        (const uint16_t*)gWosS, (const uint16_t*)gWvsT, gzero, gPart);
    wreduce_kernel<<<1024, 256>>>(gPart, gWh);

    bias_init_kernel<<<4, 256>>>(bq, gb1a);
    bs_eff_kernel<<<128, 256>>>(Wo_s, bv_s, bo_s, gb1a);

    // GEMM1 (fp16 in/out): C1h[32768,4096] = Xh @ [Wq;Wkc;Wvc;Weff]^T + b1a
    gemm1_kernel<<<dim3(N1A / 256, MTOT / 128), 256, GEMM_SMEM>>>(
        (const uint16_t*)gXh, (const uint16_t*)gWh, gb1a, gC1h, N1A, DD);

    // attention combine -> ctx fp16 into A2h
    combine_kernel<<<NB, 128>>>(gC1h, bk_c, bv_c, gA2h);

    // GEMM2 (fp16 in, fp32 out): d = ctx @ Wo_c^T + bo_c + S, with fused
    // per-column-block logits partials (deterministic).
    gemm2_kernel<<<dim3(DD / 256, MTOT / 128), 256, GEMM_SMEM>>>(
        (const uint16_t*)gA2h, (const uint16_t*)(gWh + (size_t)4096 * DD),
        bo_c, gC1h + 3072, N1A, out, DD, DD, Wc, gPlog);

    // logits = sum of 4 column-block partials (fixed order) + bc
    reduce_logits_kernel<<<MTOT * 4 / 256, 256>>>(gPlog, bc, logits);
}

// round 13
// speedup vs baseline: 8.2350x; 1.0113x over previous
#include <cuda_runtime.h>
#include <cuda_bf16.h>
#include <cuda_fp16.h>
#include <cstdint>
#include <cstddef>

// ---------------------------------------------------------------------------
// MultiModalClassifier, GB300, mma.sync fp16 GEMMs, fp16 intermediates.
//   B=8192, D=1024, H=4 (hd=256), C=4, M=32768
// Algebra (cross-path output fold is INVALID — per-head attention weights):
//   self_out = X@Weff^T + bS,  Weff = Wo_s@Wv_s, bS = Wo_s@bv_s + bo_s
//   cross: K_ij = Kc_i - Kc_j + bk_c, V_ij = Vc_i - Vc_j + bv_c
//   d = S + ctx@Wo_c^T + bo_c;  logits fused into GEMM2 epilogue.
// Precision: fp16 single GEMMs + fp16 intermediates; Weff via bf16 3-term
// split (exact ~2^-16), split-K (6 chunks) + deterministic reduce.
// R13: double-buffered ldmatrix fragments in the GEMM mainloop + launch merges.
// ---------------------------------------------------------------------------

#define NB 8192
#define DD 1024
#define MTOT 32768
#define HD 256
#define K1 3072
#define N1A 4096          // Q | Kc | Vc | S

// ------------------------------ scratch ------------------------------------
__device__ __half        g_Xh  [(size_t)MTOT * DD];    // 64 MB
__device__ __half        g_Wh  [(size_t)5120 * DD];    // 10 MB (Wq;Wkc;Wvc;Weff;Woc)
__device__ __half        g_C1h [(size_t)MTOT * N1A];   // 256 MB (Q|Kc|Vc|S)
__device__ __half        g_A2h [(size_t)MTOT * DD];    // 64 MB  (ctx fp16)
__device__ __nv_bfloat16 g_WosS[(size_t)DD * K1];      // 6 MB (A split of Wo_s)
__device__ __nv_bfloat16 g_WvsT[(size_t)DD * K1];      // 6 MB (B split of Wv_s^T)
__device__ float         g_part[(size_t)6 * DD * DD];  // 24 MB split-K partials
__device__ float         g_plog[(size_t)4 * MTOT * 4]; // 2 MB logits partials
__device__ float         g_b1a[N1A];
__device__ float         g_zero[DD];                    // never written: zeros

// --------------------------- PTX helpers -----------------------------------
__device__ __forceinline__ uint32_t smem_u32(const void* p) {
    uint32_t a;
    asm("{ .reg .u64 t; cvta.to.shared.u64 t, %1; cvt.u32.u64 %0, t; }"
        : "=r"(a) : "l"(p));
    return a;
}

#define CP_ASYNC16(dst, src) \
    asm volatile("cp.async.cg.shared.global [%0], [%1], 16;" :: "r"(dst), "l"(src))
#define CP_COMMIT() asm volatile("cp.async.commit_group;" ::: "memory")
#define CP_WAIT(n)  asm volatile("cp.async.wait_group %0;" :: "n"(n) : "memory")

#define LDMATRIX_X4(r0, r1, r2, r3, addr)                                     \
    asm volatile("ldmatrix.sync.aligned.m8n8.x4.shared.b16 {%0,%1,%2,%3}, [%4];" \
                 : "=r"(r0), "=r"(r1), "=r"(r2), "=r"(r3) : "r"(addr))

#define MMA_BF16(d0, d1, d2, d3, a0, a1, a2, a3, b0, b1)                      \
    asm volatile("mma.sync.aligned.m16n8k16.row.col.f32.bf16.bf16.f32 "       \
                 "{%0,%1,%2,%3}, {%4,%5,%6,%7}, {%8,%9}, {%0,%1,%2,%3};"      \
                 : "+f"(d0), "+f"(d1), "+f"(d2), "+f"(d3)                     \
                 : "r"(a0), "r"(a1), "r"(a2), "r"(a3), "r"(b0), "r"(b1))

#define MMA_F16(d0, d1, d2, d3, a0, a1, a2, a3, b0, b1)                       \
    asm volatile("mma.sync.aligned.m16n8k16.row.col.f32.f16.f16.f32 "         \
                 "{%0,%1,%2,%3}, {%4,%5,%6,%7}, {%8,%9}, {%0,%1,%2,%3};"      \
                 : "+f"(d0), "+f"(d1), "+f"(d2), "+f"(d3)                     \
                 : "r"(a0), "r"(a1), "r"(a2), "r"(a3), "r"(b0), "r"(b1))

// --------------------------- GEMM body -------------------------------------
// C tile = A[brow.., ld] @ B[bcol.., ld]^T + bias (+ fp16 add).
// CTA tile 128x256, BK=64, SW128 swizzle, 4-stage cp.async, 8 warps (2x4),
// warp tile 64x64. Fragments double-buffered (LDSM for ks+1 overlaps MMA ks).
// DOLOG: also emit per-CTA logits partials (deterministic).
#define STAGES 4
#define STAGE_BYTES 49152          // A 16KB + B 32KB
#define GEMM_SMEM (STAGES * STAGE_BYTES)

__device__ __forceinline__ void load_stage(
    const uint16_t* __restrict__ A, const uint16_t* __restrict__ B,
    int ld, int brow, int bcol, int kb, uint32_t st, int tid)
{
    #pragma unroll
    for (int i = 0; i < 12; i++) {
        int id = tid + 256 * i;
        if (id < 1024) {                       // A: 128 rows x 8 chunks
            int row = id >> 3, c = id & 7;
            const uint16_t* g = A + (size_t)(brow + row) * ld + kb * 64 + c * 8;
            CP_ASYNC16(st + row * 128 + ((c ^ (row & 7)) * 16), g);
        } else {                               // B: 256 rows x 8 chunks
            int idb = id - 1024;
            int row = idb >> 3, c = idb & 7;
            const uint16_t* g = B + (size_t)(bcol + row) * ld + kb * 64 + c * 8;
            CP_ASYNC16(st + 16384 + row * 128 + ((c ^ (row & 7)) * 16), g);
        }
    }
}

template <bool F16, bool OUT16, bool DOLOG>
__device__ __forceinline__ void gemm_body(
    const uint16_t* __restrict__ A, const uint16_t* __restrict__ B,
    const float* __restrict__ bias,
    const __half* __restrict__ add, int add_ld,
    void* __restrict__ Cv, int N, int K, int ld,
    int brow, int bcol, int bxid,
    const float* __restrict__ Wc, float* __restrict__ plog, char* smem)
{
    __shared__ float sred[4][128][4];            // used only when DOLOG
    const uint32_t sbase = smem_u32(smem);
    const int tid  = threadIdx.x;
    const int wid  = tid >> 5, lane = tid & 31;
    const int wm   = wid >> 2, wn = wid & 3;     // 2 x 4 warps
    const int NKB  = K >> 6;

    float acc[4][8][4];
    #pragma unroll
    for (int i = 0; i < 4; i++)
        #pragma unroll
        for (int j = 0; j < 8; j++)
            #pragma unroll
            for (int k = 0; k < 4; k++) acc[i][j][k] = 0.f;

    load_stage(A, B, ld, brow, bcol, 0, sbase, tid);                  CP_COMMIT();
    load_stage(A, B, ld, brow, bcol, 1, sbase + STAGE_BYTES, tid);    CP_COMMIT();
    load_stage(A, B, ld, brow, bcol, 2, sbase + 2 * STAGE_BYTES, tid);CP_COMMIT();

    int a_off[4], a_sw[4];
    #pragma unroll
    for (int mt = 0; mt < 4; mt++) {
        int r = wm * 64 + mt * 16 + (lane & 15);
        a_off[mt] = r * 128; a_sw[mt] = r & 7;
    }
    const int a_kh = lane >> 4;
    int b_off[4], b_sw[4];
    #pragma unroll
    for (int np = 0; np < 4; np++) {
        int r = wn * 64 + np * 16 + ((lane >> 4) & 1) * 8 + (lane & 7);
        b_off[np] = r * 128; b_sw[np] = r & 7;
    }
    const int b_kh = (lane >> 3) & 1;

    uint32_t af[2][4][4], bf[2][4][4];           // double-buffered fragments

    #define LOAD_FRAGS(bi, ks, sA, sB)                                        \
        do {                                                                  \
            const int cca = (ks) * 2 + a_kh, ccb = (ks) * 2 + b_kh;           \
            _Pragma("unroll")                                                 \
            for (int mt = 0; mt < 4; mt++)                                    \
                LDMATRIX_X4(af[bi][mt][0], af[bi][mt][1],                     \
                            af[bi][mt][2], af[bi][mt][3],                     \
                            (sA) + a_off[mt] + ((cca ^ a_sw[mt]) * 16));      \
            _Pragma("unroll")                                                 \
            for (int np = 0; np < 4; np++)                                    \
                LDMATRIX_X4(bf[bi][np][0], bf[bi][np][1],                     \
                            bf[bi][np][2], bf[bi][np][3],                     \
                            (sB) + b_off[np] + ((ccb ^ b_sw[np]) * 16));      \
        } while (0)

    for (int kb = 0; kb < NKB; kb++) {
        if (kb < NKB - 2)       CP_WAIT(2);
        else if (kb == NKB - 2) CP_WAIT(1);
        else                    CP_WAIT(0);
        __syncthreads();
        if (kb + 3 < NKB) {
            load_stage(A, B, ld, brow, bcol, kb + 3,
                       sbase + ((kb + 3) & 3) * STAGE_BYTES, tid);
            CP_COMMIT();
        }
        const uint32_t sA = sbase + (kb & 3) * STAGE_BYTES;
        const uint32_t sB = sA + 16384;

        LOAD_FRAGS(0, 0, sA, sB);
        #pragma unroll
        for (int ks = 0; ks < 4; ks++) {
            if (ks < 3) LOAD_FRAGS((ks + 1) & 1, ks + 1, sA, sB);
            const int cu = ks & 1;
            #pragma unroll
            for (int mt = 0; mt < 4; mt++)
                #pragma unroll
                for (int nt = 0; nt < 8; nt++) {
                    if (F16)
                        MMA_F16(acc[mt][nt][0], acc[mt][nt][1],
                                acc[mt][nt][2], acc[mt][nt][3],
                                af[cu][mt][0], af[cu][mt][1],
                                af[cu][mt][2], af[cu][mt][3],
                                bf[cu][nt >> 1][(nt & 1) * 2],
                                bf[cu][nt >> 1][(nt & 1) * 2 + 1]);
                    else
                        MMA_BF16(acc[mt][nt][0], acc[mt][nt][1],
                                 acc[mt][nt][2], acc[mt][nt][3],
                                 af[cu][mt][0], af[cu][mt][1],
                                 af[cu][mt][2], af[cu][mt][3],
                                 bf[cu][nt >> 1][(nt & 1) * 2],
                                 bf[cu][nt >> 1][(nt & 1) * 2 + 1]);
                }
        }
    }
    #undef LOAD_FRAGS

    #pragma unroll
    for (int mt = 0; mt < 4; mt++) {
        const int r0 = brow + wm * 64 + mt * 16 + (lane >> 2);
        float p0[4] = {0.f, 0.f, 0.f, 0.f}, p1[4] = {0.f, 0.f, 0.f, 0.f};
        #pragma unroll
        for (int nt = 0; nt < 8; nt++) {
            const int c0 = bcol + wn * 64 + nt * 8 + (lane & 3) * 2;
            const float bx = bias[c0], by = bias[c0 + 1];
            float a0 = acc[mt][nt][0] + bx, a1 = acc[mt][nt][1] + by;
            float a2 = acc[mt][nt][2] + bx, a3 = acc[mt][nt][3] + by;
            if (add) {
                a0 += __half2float(add[(size_t)r0 * add_ld + c0]);
                a1 += __half2float(add[(size_t)r0 * add_ld + c0 + 1]);
                a2 += __half2float(add[(size_t)(r0 + 8) * add_ld + c0]);
                a3 += __half2float(add[(size_t)(r0 + 8) * add_ld + c0 + 1]);
            }
            if (OUT16) {
                __half* C = (__half*)Cv;
                __half2 v0 = __floats2half2_rn(a0, a1);
                __half2 v1 = __floats2half2_rn(a2, a3);
                *(__half2*)&C[(size_t)r0 * N + c0]       = v0;
                *(__half2*)&C[(size_t)(r0 + 8) * N + c0] = v1;
            } else {
                float* C = (float*)Cv;
                float2 v0 = { a0, a1 }, v1 = { a2, a3 };
                *(float2*)&C[(size_t)r0 * N + c0]       = v0;
                *(float2*)&C[(size_t)(r0 + 8) * N + c0] = v1;
            }
            if (DOLOG) {
                #pragma unroll
                for (int c = 0; c < 4; c++) {
                    float w0 = Wc[c * DD + c0], w1 = Wc[c * DD + c0 + 1];
                    p0[c] = fmaf(a0, w0, fmaf(a1, w1, p0[c]));
                    p1[c] = fmaf(a2, w0, fmaf(a3, w1, p1[c]));
                }
            }
        }
        if (DOLOG) {
            #pragma unroll
            for (int c = 0; c < 4; c++) {
                p0[c] += __shfl_xor_sync(0xffffffffu, p0[c], 1);
                p0[c] += __shfl_xor_sync(0xffffffffu, p0[c], 2);
                p1[c] += __shfl_xor_sync(0xffffffffu, p1[c], 1);
                p1[c] += __shfl_xor_sync(0xffffffffu, p1[c], 2);
            }
            if ((lane & 3) == 0) {
                int rl = wm * 64 + mt * 16 + (lane >> 2);
                #pragma unroll
                for (int c = 0; c < 4; c++) {
                    sred[wn][rl][c]     = p0[c];
                    sred[wn][rl + 8][c] = p1[c];
                }
            }
        }
    }
    if (DOLOG) {
        __syncthreads();
        for (int t = tid; t < 512; t += 256) {
            int row = t >> 2, c = t & 3;
            float s = sred[0][row][c] + sred[1][row][c]
                    + sred[2][row][c] + sred[3][row][c];
            plog[((size_t)bxid * MTOT + brow + row) * 4 + c] = s;
        }
    }
}

// GEMM1: fp16 in/out, ld == K.
__global__ __launch_bounds__(256, 1)
void gemm1_kernel(const uint16_t* __restrict__ A, const uint16_t* __restrict__ B,
                  const float* __restrict__ bias, __half* __restrict__ C,
                  int N, int K)
{
    extern __shared__ __align__(1024) char smem[];
    gemm_body<true, true, false>(A, B, bias, nullptr, 0, C, N, K, K,
                                 blockIdx.y * 128, blockIdx.x * 256, 0,
                                 nullptr, nullptr, smem);
}

// GEMM2: fp16 in, fp32 out, fp16 addend (S), fused logits partials.
__global__ __launch_bounds__(256, 1)
void gemm2_kernel(const uint16_t* __restrict__ A, const uint16_t* __restrict__ B,
                  const float* __restrict__ bias,
                  const __half* __restrict__ add, int add_ld,
                  float* __restrict__ C, int N, int K,
                  const float* __restrict__ Wc, float* __restrict__ plog)
{
    extern __shared__ __align__(1024) char smem[];
    gemm_body<true, false, true>(A, B, bias, add, add_ld, C, N, K, K,
                                 blockIdx.y * 128, blockIdx.x * 256,
                                 blockIdx.x, Wc, plog, smem);
}

// Split-K Weff fold: chunk z covers K=512 of K1=3072 (ld=K1), bf16 3-term.
__global__ __launch_bounds__(256, 1)
void wgemm_splitk(const uint16_t* __restrict__ A0, const uint16_t* __restrict__ B0,
                  const float* __restrict__ zero, float* __restrict__ Cpart)
{
    extern __shared__ __align__(1024) char smem[];
    const int z = blockIdx.z;
    float* C = Cpart + (size_t)z * DD * DD;
    gemm_body<false, false, false>(A0 + z * 512, B0 + z * 512, zero, nullptr, 0,
                                   C, DD, 512, K1,
                                   blockIdx.y * 128, blockIdx.x * 256, 0,
                                   nullptr, nullptr, smem);
}

// Reduce 6 split-K partials -> fp16 Weff into Wh block 3072 (S weights).
__global__ __launch_bounds__(256) void wreduce_kernel(
    const float* __restrict__ part, __half* __restrict__ Wh)
{
    size_t off = ((size_t)blockIdx.x * blockDim.x + threadIdx.x) * 4;
    float4 s = { 0.f, 0.f, 0.f, 0.f };
    #pragma unroll
    for (int c = 0; c < 6; c++) {
        float4 v = *(const float4*)&part[(size_t)c * DD * DD + off];
        s.x += v.x; s.y += v.y; s.z += v.z; s.w += v.w;
    }
    __half h[4] = { __float2half(s.x), __float2half(s.y),
                    __float2half(s.z), __float2half(s.w) };
    *(uint2*)&Wh[(size_t)3072 * DD + off] = *(uint2*)h;
}

// Reduce logits partials (fixed order over 4 column blocks) + bc.
__global__ __launch_bounds__(256) void reduce_logits_kernel(
    const float* __restrict__ plog, const float* __restrict__ bc,
    float* __restrict__ logits)
{
    size_t idx = (size_t)blockIdx.x * 256 + threadIdx.x;   // MTOT*4 total
    float s = bc[idx & 3];
    s += plog[idx];
    s += plog[(size_t)MTOT * 4 + idx];
    s += plog[2 * (size_t)MTOT * 4 + idx];
    s += plog[3 * (size_t)MTOT * 4 + idx];
    logits[idx] = s;
}

// --------------------------- split / cast kernels ---------------------------
__device__ __forceinline__ void split1(float a, __nv_bfloat16& h, __nv_bfloat16& l) {
    h = __float2bfloat16(a);
    l = __float2bfloat16(a - __bfloat162float(h));
}

// Merged bf16-split prep: blocks 0..1023 = A-layout split of Wo_s [hi|lo|hi];
// blocks 1024..2047 = tiled transpose+split of Wv_s [hi|hi|lo].
__global__ __launch_bounds__(256) void split_both_kernel(
    const float* __restrict__ Wos, const float* __restrict__ Wvs,
    __nv_bfloat16* __restrict__ dstA, __nv_bfloat16* __restrict__ dstB)
{
    if (blockIdx.x < 1024) {
        size_t idx = (size_t)blockIdx.x * 256 + threadIdx.x;
        size_t n = idx >> 8;
        int c4 = (int)(idx & 255) * 4;
        float4 v = *(const float4*)&Wos[n * DD + c4];
        __nv_bfloat16 h[4], l[4];
        split1(v.x, h[0], l[0]); split1(v.y, h[1], l[1]);
        split1(v.z, h[2], l[2]); split1(v.w, h[3], l[3]);
        __nv_bfloat16* row = dstA + n * K1;
        *(uint2*)&row[c4]          = *(uint2*)h;
        *(uint2*)&row[DD + c4]     = *(uint2*)l;
        *(uint2*)&row[2 * DD + c4] = *(uint2*)h;
    } else {
        __shared__ float tile[32][33];
        const int bb = blockIdx.x - 1024;
        const int i0 = (bb & 31) * 32;         // i tile (cols of W)
        const int m0 = (bb >> 5) * 32;         // m tile (rows of W)
        const int tx = threadIdx.x & 31, ty = threadIdx.x >> 5;   // 32 x 8
        #pragma unroll
        for (int r = 0; r < 4; r++)
            tile[ty * 4 + r][tx] = Wvs[(size_t)(m0 + ty * 4 + r) * DD + i0 + tx];
        __syncthreads();
        const int il = threadIdx.x >> 3;       // 0..31
        const int mq = (threadIdx.x & 7) * 4;  // 0,4,..,28
        __nv_bfloat16 h[4], l[4];
        #pragma unroll
        for (int r = 0; r < 4; r++)
            split1(tile[mq + r][il], h[r], l[r]);
        __nv_bfloat16* row = dstB + (size_t)(i0 + il) * K1 + m0 + mq;
        *(uint2*)&row[0]      = *(uint2*)h;
        *(uint2*)&row[DD]     = *(uint2*)h;
        *(uint2*)&row[2 * DD] = *(uint2*)l;
    }
}

// Merged fp32 -> fp16 casts. Blocks 0..32767: stacked X -> Xh.
// Blocks 32768..36863: Wq->0, Wkc->1024, Wvc->2048, Woc->4096 (rows of Wh).
__global__ __launch_bounds__(256) void cast_all_kernel(
    const float* __restrict__ X1, const float* __restrict__ X2,
    const float* __restrict__ X3, const float* __restrict__ X4,
    const float* __restrict__ Wq, const float* __restrict__ Wkc,
    const float* __restrict__ Wvc, const float* __restrict__ Woc,
    __half* __restrict__ Xh, __half* __restrict__ Wh)
{
    if (blockIdx.x < MTOT) {
        size_t idx = (size_t)blockIdx.x * 256 + threadIdx.x;
        size_t r = idx >> 8;
        int c4 = (int)(idx & 255) * 4;
        const float* src = (r < NB) ? X1 : (r < 2 * NB) ? X2
                         : (r < 3 * NB) ? X3 : X4;
        float4 v = *(const float4*)&src[(r & (NB - 1)) * DD + c4];
        __half hf[4] = { __float2half(v.x), __float2half(v.y),
                         __float2half(v.z), __float2half(v.w) };
        *(uint2*)&Xh[r * DD + c4] = *(uint2*)hf;
    } else {
        size_t idx = (size_t)(blockIdx.x - MTOT) * 256 + threadIdx.x;
        int sel = (int)(idx >> 18);             // 2^18 float4 per matrix
        size_t off = (idx & ((1u << 18) - 1)) * 4;
        const float* src = (sel == 0) ? Wq : (sel == 1) ? Wkc
                         : (sel == 2) ? Wvc : Woc;
        size_t base = (size_t)((sel == 3) ? 4096 : sel * 1024) * DD;
        float4 v = *(const float4*)&src[off];
        __half h[4] = { __float2half(v.x), __float2half(v.y),
                        __float2half(v.z), __float2half(v.w) };
        *(uint2*)&Wh[base + off] = *(uint2*)h;
    }
}

// --------------------------- bias kernel -----------------------------------
__device__ __forceinline__ float wsum(float v) {
    #pragma unroll
    for (int o = 16; o; o >>= 1) v += __shfl_xor_sync(0xffffffffu, v, o);
    return v;
}

// Merged: b1a[0..1023]=bq, [1024..3071]=0, [3072+o]=Wos[o,:]@bvs + bos[o].
__global__ __launch_bounds__(256) void bias_all_kernel(
    const float* __restrict__ bq,
    const float* __restrict__ Wos, const float* __restrict__ bvs,
    const float* __restrict__ bos, float* __restrict__ b1a)
{
    int idx = blockIdx.x * 256 + threadIdx.x;   // 128 blocks -> 32768 threads
    if (idx < DD)           b1a[idx] = bq[idx];
    else if (idx < 3 * DD)  b1a[idx] = 0.f;

    int o = blockIdx.x * 8 + (threadIdx.x >> 5);
    int lane = threadIdx.x & 31;
    float s = 0.f;
    for (int k = lane; k < DD; k += 32)
        s = fmaf(Wos[(size_t)o * DD + k], bvs[k], s);
    s = wsum(s);
    if (lane == 0) b1a[3 * DD + o] = s + bos[o];
}

// --------------------------- combine ---------------------------------------
// ctx_i = Vc_i + bv_c - sum_j a_ij Vc_j, fp16 in (C1h) / fp16 out (A2h).
__global__ __launch_bounds__(128) void combine_kernel(
    const __half* __restrict__ C1h,   // Q | Kc | Vc | S  (ld 4096)
    const float* __restrict__ bk, const float* __restrict__ bv,
    __half* __restrict__ A2h)
{
    const int b    = blockIdx.x;
    const int h    = threadIdx.x >> 5;
    const int lane = threadIdx.x & 31;
    const int base_d = h * HD + lane;

    float q[4][8], kc[4][8], vc[4][8];
    #pragma unroll
    for (int i = 0; i < 4; i++) {
        size_t row = (size_t)(i * NB + b) * N1A + base_d;
        #pragma unroll
        for (int e = 0; e < 8; e++) {
            q [i][e] = __half2float(C1h[row + e * 32]);
            kc[i][e] = __half2float(C1h[row + 1024 + e * 32]);
            vc[i][e] = __half2float(C1h[row + 2048 + e * 32]);
        }
    }
    float bke[8], bve[8];
    #pragma unroll
    for (int e = 0; e < 8; e++) {
        bke[e] = bk[base_d + e * 32];
        bve[e] = bv[base_d + e * 32];
    }

    float a[4][4];
    #pragma unroll
    for (int i = 0; i < 4; i++) {
        float s[4];
        #pragma unroll
        for (int j = 0; j < 4; j++) {
            float p = 0.f;
            #pragma unroll
            for (int e = 0; e < 8; e++)
                p = fmaf(q[i][e], kc[i][e] - kc[j][e] + bke[e], p);
            s[j] = wsum(p) * (1.f / 16.f);
        }
        float m = -1e30f;
        #pragma unroll
        for (int j = 0; j < 4; j++) if (j != i && s[j] > m) m = s[j];
        float den = 0.f;
        #pragma unroll
        for (int j = 0; j < 4; j++) {
            float ex = (j == i) ? 0.f : __expf(s[j] - m);
            a[i][j] = ex; den += ex;
        }
        float inv = 1.f / den;
        #pragma unroll
        for (int j = 0; j < 4; j++) a[i][j] *= inv;
    }

    #pragma unroll
    for (int i = 0; i < 4; i++) {
        __half* row = A2h + (size_t)(i * NB + b) * DD;
        #pragma unroll
        for (int e = 0; e < 8; e++) {
            float c = vc[i][e] + bve[e];
            #pragma unroll
            for (int j = 0; j < 4; j++)
                c = fmaf(-a[i][j], vc[j][e], c);
            row[base_d + e * 32] = __float2half(c);
        }
    }
}

// ---------------------------------------------------------------------------
extern "C" void kernel_launch(void* const* d_in, const int* in_sizes, int n_in,
                              void* d_out, int out_size)
{
    const float* X1   = (const float*)d_in[0];
    const float* X2   = (const float*)d_in[1];
    const float* X3   = (const float*)d_in[2];
    const float* X4   = (const float*)d_in[3];
    const float* Wq   = (const float*)d_in[4];
    const float* bq   = (const float*)d_in[5];
    const float* Wv_s = (const float*)d_in[8];
    const float* bv_s = (const float*)d_in[9];
    const float* Wo_s = (const float*)d_in[10];
    const float* bo_s = (const float*)d_in[11];
    const float* Wk_c = (const float*)d_in[12];
    const float* bk_c = (const float*)d_in[13];
    const float* Wv_c = (const float*)d_in[14];
    const float* bv_c = (const float*)d_in[15];
    const float* Wo_c = (const float*)d_in[16];
    const float* bo_c = (const float*)d_in[17];
    const float* Wc   = (const float*)d_in[18];
    const float* bc   = (const float*)d_in[19];

    float* out    = (float*)d_out;
    float* logits = out + (size_t)MTOT * DD;

    __nv_bfloat16 *gWosS, *gWvsT;
    __half *gXh, *gWh, *gC1h, *gA2h;
    float *gPart, *gPlog, *gb1a, *gzero;
    cudaGetSymbolAddress((void**)&gXh,   g_Xh);
    cudaGetSymbolAddress((void**)&gWh,   g_Wh);
    cudaGetSymbolAddress((void**)&gC1h,  g_C1h);
    cudaGetSymbolAddress((void**)&gA2h,  g_A2h);
    cudaGetSymbolAddress((void**)&gWosS, g_WosS);
    cudaGetSymbolAddress((void**)&gWvsT, g_WvsT);
    cudaGetSymbolAddress((void**)&gPart, g_part);
    cudaGetSymbolAddress((void**)&gPlog, g_plog);
    cudaGetSymbolAddress((void**)&gb1a,  g_b1a);
    cudaGetSymbolAddress((void**)&gzero, g_zero);

    cudaFuncSetAttribute((const void*)gemm1_kernel,
                         cudaFuncAttributeMaxDynamicSharedMemorySize, GEMM_SMEM);
    cudaFuncSetAttribute((const void*)gemm2_kernel,
                         cudaFuncAttributeMaxDynamicSharedMemorySize, GEMM_SMEM);
    cudaFuncSetAttribute((const void*)wgemm_splitk,
                         cudaFuncAttributeMaxDynamicSharedMemorySize, GEMM_SMEM);

    // prep: merged fp16 casts + merged bf16 splits for the exact Weff fold
    cast_all_kernel<<<MTOT + 4096, 256>>>(X1, X2, X3, X4,
                                          Wq, Wk_c, Wv_c, Wo_c, gXh, gWh);
    split_both_kernel<<<2048, 256>>>(Wo_s, Wv_s, gWosS, gWvsT);

    // Weff = Wo_s@Wv_s via split-K bf16 3-term (6 x K=512) + reduce -> fp16
    wgemm_splitk<<<dim3(4, 8, 6), 256, GEMM_SMEM>>>(
        (const uint16_t*)gWosS, (const uint16_t*)gWvsT, gzero, gPart);
    wreduce_kernel<<<1024, 256>>>(gPart, gWh);

    bias_all_kernel<<<128, 256>>>(bq, Wo_s, bv_s, bo_s, gb1a);

    // GEMM1 (fp16 in/out): C1h[32768,4096] = Xh @ [Wq;Wkc;Wvc;Weff]^T + b1a
    gemm1_kernel<<<dim3(N1A / 256, MTOT / 128), 256, GEMM_SMEM>>>(
        (const uint16_t*)gXh, (const uint16_t*)gWh, gb1a, gC1h, N1A, DD);

    // attention combine -> ctx fp16 into A2h
    combine_kernel<<<NB, 128>>>(gC1h, bk_c, bv_c, gA2h);

    // GEMM2 (fp16 in, fp32 out): d = ctx @ Wo_c^T + bo_c + S, with fused
    // per-column-block logits partials (deterministic).
    gemm2_kernel<<<dim3(DD / 256, MTOT / 128), 256, GEMM_SMEM>>>(
        (const uint16_t*)gA2h, (const uint16_t*)(gWh + (size_t)4096 * DD),
        bo_c, gC1h + 3072, N1A, out, DD, DD, Wc, gPlog);

    // logits = sum of 4 column-block partials (fixed order) + bc
    reduce_logits_kernel<<<MTOT * 4 / 256, 256>>>(gPlog, bc, logits);
}

// round 15
// speedup vs baseline: 8.3037x; 1.0084x over previous
#include <cuda_runtime.h>
#include <cuda_bf16.h>
#include <cuda_fp16.h>
#include <cstdint>
#include <cstddef>

// ---------------------------------------------------------------------------
// MultiModalClassifier, GB300, mma.sync fp16 GEMMs, fp16 intermediates.
//   B=8192, D=1024, H=4 (hd=256), C=4, M=32768
// Algebra (cross-path output fold is INVALID — per-head attention weights):
//   self_out = X@Weff^T + bS,  Weff = Wo_s@Wv_s, bS = Wo_s@bv_s + bo_s
//   cross: K_ij = Kc_i - Kc_j + bk_c, V_ij = Vc_i - Vc_j + bv_c
//   d = S + ctx@Wo_c^T + bo_c;  logits fused into GEMM2 epilogue.
// Precision: fp16 single everywhere (incl. Weff fold, fp32 accum).
// R14 bug: gemm2 instantiated <true,true> -> OUT16 wrote half2 into fp32 out.
// R15 fix: gemm2 = gemm_body<false, true>.
// ---------------------------------------------------------------------------

#define NB 8192
#define DD 1024
#define MTOT 32768
#define HD 256
#define N1A 4096          // Q | Kc | Vc | S

// ------------------------------ scratch ------------------------------------
__device__ __half g_Xh   [(size_t)MTOT * DD];    // 64 MB
__device__ __half g_Wh   [(size_t)5120 * DD];    // 10 MB (Wq;Wkc;Wvc;Weff;Woc)
__device__ __half g_C1h  [(size_t)MTOT * N1A];   // 256 MB (Q|Kc|Vc|S)
__device__ __half g_A2h  [(size_t)MTOT * DD];    // 64 MB  (ctx fp16)
__device__ __half g_Wos16[(size_t)DD * DD];      // 2 MB  (Wo_s fp16)
__device__ __half g_WvsT16[(size_t)DD * DD];     // 2 MB  (Wv_s^T fp16)
__device__ float  g_plog [(size_t)4 * MTOT * 4]; // 2 MB logits partials
__device__ float  g_b1a[N1A];
__device__ float  g_zero[DD];                     // never written: zeros

// --------------------------- PTX helpers -----------------------------------
__device__ __forceinline__ uint32_t smem_u32(const void* p) {
    uint32_t a;
    asm("{ .reg .u64 t; cvta.to.shared.u64 t, %1; cvt.u32.u64 %0, t; }"
        : "=r"(a) : "l"(p));
    return a;
}

#define CP_ASYNC16(dst, src) \
    asm volatile("cp.async.cg.shared.global [%0], [%1], 16;" :: "r"(dst), "l"(src))
#define CP_COMMIT() asm volatile("cp.async.commit_group;" ::: "memory")
#define CP_WAIT(n)  asm volatile("cp.async.wait_group %0;" :: "n"(n) : "memory")

#define LDMATRIX_X4(r0, r1, r2, r3, addr)                                     \
    asm volatile("ldmatrix.sync.aligned.m8n8.x4.shared.b16 {%0,%1,%2,%3}, [%4];" \
                 : "=r"(r0), "=r"(r1), "=r"(r2), "=r"(r3) : "r"(addr))

#define MMA_F16(d0, d1, d2, d3, a0, a1, a2, a3, b0, b1)                       \
    asm volatile("mma.sync.aligned.m16n8k16.row.col.f32.f16.f16.f32 "         \
                 "{%0,%1,%2,%3}, {%4,%5,%6,%7}, {%8,%9}, {%0,%1,%2,%3};"      \
                 : "+f"(d0), "+f"(d1), "+f"(d2), "+f"(d3)                     \
                 : "r"(a0), "r"(a1), "r"(a2), "r"(a3), "r"(b0), "r"(b1))

// --------------------------- GEMM body -------------------------------------
// C tile = A[brow.., ld] @ B[bcol.., ld]^T + bias (+ fp16 add).
// CTA tile 128x256, BK=64, SW128 swizzle, 4-stage cp.async, 8 warps (2x4),
// warp tile 64x64, double-buffered fragments.
// DOLOG: also emit per-CTA logits partials (deterministic).
#define STAGES 4
#define STAGE_BYTES 49152          // A 16KB + B 32KB
#define GEMM_SMEM (STAGES * STAGE_BYTES)

__device__ __forceinline__ void load_stage(
    const uint16_t* __restrict__ A, const uint16_t* __restrict__ B,
    int ld, int brow, int bcol, int kb, uint32_t st, int tid)
{
    #pragma unroll
    for (int i = 0; i < 12; i++) {
        int id = tid + 256 * i;
        if (id < 1024) {                       // A: 128 rows x 8 chunks
            int row = id >> 3, c = id & 7;
            const uint16_t* g = A + (size_t)(brow + row) * ld + kb * 64 + c * 8;
            CP_ASYNC16(st + row * 128 + ((c ^ (row & 7)) * 16), g);
        } else {                               // B: 256 rows x 8 chunks
            int idb = id - 1024;
            int row = idb >> 3, c = idb & 7;
            const uint16_t* g = B + (size_t)(bcol + row) * ld + kb * 64 + c * 8;
            CP_ASYNC16(st + 16384 + row * 128 + ((c ^ (row & 7)) * 16), g);
        }
    }
}

template <bool OUT16, bool DOLOG>
__device__ __forceinline__ void gemm_body(
    const uint16_t* __restrict__ A, const uint16_t* __restrict__ B,
    const float* __restrict__ bias,
    const __half* __restrict__ add, int add_ld,
    void* __restrict__ Cv, int N, int K, int ld,
    int brow, int bcol, int bxid,
    const float* __restrict__ Wc, float* __restrict__ plog, char* smem)
{
    __shared__ float sred[4][128][4];            // used only when DOLOG
    const uint32_t sbase = smem_u32(smem);
    const int tid  = threadIdx.x;
    const int wid  = tid >> 5, lane = tid & 31;
    const int wm   = wid >> 2, wn = wid & 3;     // 2 x 4 warps
    const int NKB  = K >> 6;

    float acc[4][8][4];
    #pragma unroll
    for (int i = 0; i < 4; i++)
        #pragma unroll
        for (int j = 0; j < 8; j++)
            #pragma unroll
            for (int k = 0; k < 4; k++) acc[i][j][k] = 0.f;

    load_stage(A, B, ld, brow, bcol, 0, sbase, tid);                  CP_COMMIT();
    load_stage(A, B, ld, brow, bcol, 1, sbase + STAGE_BYTES, tid);    CP_COMMIT();
    load_stage(A, B, ld, brow, bcol, 2, sbase + 2 * STAGE_BYTES, tid);CP_COMMIT();

    int a_off[4], a_sw[4];
    #pragma unroll
    for (int mt = 0; mt < 4; mt++) {
        int r = wm * 64 + mt * 16 + (lane & 15);
        a_off[mt] = r * 128; a_sw[mt] = r & 7;
    }
    const int a_kh = lane >> 4;
    int b_off[4], b_sw[4];
    #pragma unroll
    for (int np = 0; np < 4; np++) {
        int r = wn * 64 + np * 16 + ((lane >> 4) & 1) * 8 + (lane & 7);
        b_off[np] = r * 128; b_sw[np] = r & 7;
    }
    const int b_kh = (lane >> 3) & 1;

    uint32_t af[2][4][4], bf[2][4][4];           // double-buffered fragments

    #define LOAD_FRAGS(bi, ks, sA, sB)                                        \
        do {                                                                  \
            const int cca = (ks) * 2 + a_kh, ccb = (ks) * 2 + b_kh;           \
            _Pragma("unroll")                                                 \
            for (int mt = 0; mt < 4; mt++)                                    \
                LDMATRIX_X4(af[bi][mt][0], af[bi][mt][1],                     \
                            af[bi][mt][2], af[bi][mt][3],                     \
                            (sA) + a_off[mt] + ((cca ^ a_sw[mt]) * 16));      \
            _Pragma("unroll")                                                 \
            for (int np = 0; np < 4; np++)                                    \
                LDMATRIX_X4(bf[bi][np][0], bf[bi][np][1],                     \
                            bf[bi][np][2], bf[bi][np][3],                     \
                            (sB) + b_off[np] + ((ccb ^ b_sw[np]) * 16));      \
        } while (0)

    for (int kb = 0; kb < NKB; kb++) {
        if (kb < NKB - 2)       CP_WAIT(2);
        else if (kb == NKB - 2) CP_WAIT(1);
        else                    CP_WAIT(0);
        __syncthreads();
        if (kb + 3 < NKB) {
            load_stage(A, B, ld, brow, bcol, kb + 3,
                       sbase + ((kb + 3) & 3) * STAGE_BYTES, tid);
            CP_COMMIT();
        }
        const uint32_t sA = sbase + (kb & 3) * STAGE_BYTES;
        const uint32_t sB = sA + 16384;

        LOAD_FRAGS(0, 0, sA, sB);
        #pragma unroll
        for (int ks = 0; ks < 4; ks++) {
            if (ks < 3) LOAD_FRAGS((ks + 1) & 1, ks + 1, sA, sB);
            const int cu = ks & 1;
            #pragma unroll
            for (int mt = 0; mt < 4; mt++)
                #pragma unroll
                for (int nt = 0; nt < 8; nt++)
                    MMA_F16(acc[mt][nt][0], acc[mt][nt][1],
                            acc[mt][nt][2], acc[mt][nt][3],
                            af[cu][mt][0], af[cu][mt][1],
                            af[cu][mt][2], af[cu][mt][3],
                            bf[cu][nt >> 1][(nt & 1) * 2],
                            bf[cu][nt >> 1][(nt & 1) * 2 + 1]);
        }
    }
    #undef LOAD_FRAGS

    #pragma unroll
    for (int mt = 0; mt < 4; mt++) {
        const int r0 = brow + wm * 64 + mt * 16 + (lane >> 2);
        float p0[4] = {0.f, 0.f, 0.f, 0.f}, p1[4] = {0.f, 0.f, 0.f, 0.f};
        #pragma unroll
        for (int nt = 0; nt < 8; nt++) {
            const int c0 = bcol + wn * 64 + nt * 8 + (lane & 3) * 2;
            const float bx = bias[c0], by = bias[c0 + 1];
            float a0 = acc[mt][nt][0] + bx, a1 = acc[mt][nt][1] + by;
            float a2 = acc[mt][nt][2] + bx, a3 = acc[mt][nt][3] + by;
            if (add) {
                a0 += __half2float(add[(size_t)r0 * add_ld + c0]);
                a1 += __half2float(add[(size_t)r0 * add_ld + c0 + 1]);
                a2 += __half2float(add[(size_t)(r0 + 8) * add_ld + c0]);
                a3 += __half2float(add[(size_t)(r0 + 8) * add_ld + c0 + 1]);
            }
            if (OUT16) {
                __half* C = (__half*)Cv;
                __half2 v0 = __floats2half2_rn(a0, a1);
                __half2 v1 = __floats2half2_rn(a2, a3);
                *(__half2*)&C[(size_t)r0 * N + c0]       = v0;
                *(__half2*)&C[(size_t)(r0 + 8) * N + c0] = v1;
            } else {
                float* C = (float*)Cv;
                float2 v0 = { a0, a1 }, v1 = { a2, a3 };
                *(float2*)&C[(size_t)r0 * N + c0]       = v0;
                *(float2*)&C[(size_t)(r0 + 8) * N + c0] = v1;
            }
            if (DOLOG) {
                #pragma unroll
                for (int c = 0; c < 4; c++) {
                    float w0 = Wc[c * DD + c0], w1 = Wc[c * DD + c0 + 1];
                    p0[c] = fmaf(a0, w0, fmaf(a1, w1, p0[c]));
                    p1[c] = fmaf(a2, w0, fmaf(a3, w1, p1[c]));
                }
            }
        }
        if (DOLOG) {
            #pragma unroll
            for (int c = 0; c < 4; c++) {
                p0[c] += __shfl_xor_sync(0xffffffffu, p0[c], 1);
                p0[c] += __shfl_xor_sync(0xffffffffu, p0[c], 2);
                p1[c] += __shfl_xor_sync(0xffffffffu, p1[c], 1);
                p1[c] += __shfl_xor_sync(0xffffffffu, p1[c], 2);
            }
            if ((lane & 3) == 0) {
                int rl = wm * 64 + mt * 16 + (lane >> 2);
                #pragma unroll
                for (int c = 0; c < 4; c++) {
                    sred[wn][rl][c]     = p0[c];
                    sred[wn][rl + 8][c] = p1[c];
                }
            }
        }
    }
    if (DOLOG) {
        __syncthreads();
        for (int t = tid; t < 512; t += 256) {
            int row = t >> 2, c = t & 3;
            float s = sred[0][row][c] + sred[1][row][c]
                    + sred[2][row][c] + sred[3][row][c];
            plog[((size_t)bxid * MTOT + brow + row) * 4 + c] = s;
        }
    }
}

// GEMM1: fp16 in/out, ld == K.
__global__ __launch_bounds__(256, 1)
void gemm1_kernel(const uint16_t* __restrict__ A, const uint16_t* __restrict__ B,
                  const float* __restrict__ bias, __half* __restrict__ C,
                  int N, int K)
{
    extern __shared__ __align__(1024) char smem[];
    gemm_body<true, false>(A, B, bias, nullptr, 0, C, N, K, K,
                           blockIdx.y * 128, blockIdx.x * 256, 0,
                           nullptr, nullptr, smem);
}

// GEMM2: fp16 in, fp32 out, fp16 addend (S), fused logits partials.
__global__ __launch_bounds__(256, 1)
void gemm2_kernel(const uint16_t* __restrict__ A, const uint16_t* __restrict__ B,
                  const float* __restrict__ bias,
                  const __half* __restrict__ add, int add_ld,
                  float* __restrict__ C, int N, int K,
                  const float* __restrict__ Wc, float* __restrict__ plog)
{
    extern __shared__ __align__(1024) char smem[];
    gemm_body<false, true>(A, B, bias, add, add_ld, C, N, K, K,
                           blockIdx.y * 128, blockIdx.x * 256,
                           blockIdx.x, Wc, plog, smem);
}

// Reduce logits partials (fixed order over 4 column blocks) + bc.
__global__ __launch_bounds__(256) void reduce_logits_kernel(
    const float* __restrict__ plog, const float* __restrict__ bc,
    float* __restrict__ logits)
{
    size_t idx = (size_t)blockIdx.x * 256 + threadIdx.x;   // MTOT*4 total
    float s = bc[idx & 3];
    s += plog[idx];
    s += plog[(size_t)MTOT * 4 + idx];
    s += plog[2 * (size_t)MTOT * 4 + idx];
    s += plog[3 * (size_t)MTOT * 4 + idx];
    logits[idx] = s;
}

// --------------------------- cast kernel -----------------------------------
// Blocks [0, MTOT): stacked X -> Xh.
// Blocks [MTOT, MTOT+5120): straight casts Wq->0, Wkc->1024, Wvc->2048,
//   Woc->4096 (rows of Wh), Wo_s -> Wos16.
// Blocks [MTOT+5120, MTOT+6144): tiled transpose-cast Wv_s -> WvsT16.
__global__ __launch_bounds__(256) void cast_all_kernel(
    const float* __restrict__ X1, const float* __restrict__ X2,
    const float* __restrict__ X3, const float* __restrict__ X4,
    const float* __restrict__ Wq, const float* __restrict__ Wkc,
    const float* __restrict__ Wvc, const float* __restrict__ Woc,
    const float* __restrict__ Wos, const float* __restrict__ Wvs,
    __half* __restrict__ Xh, __half* __restrict__ Wh,
    __half* __restrict__ Wos16, __half* __restrict__ WvsT16)
{
    if (blockIdx.x < MTOT) {
        size_t idx = (size_t)blockIdx.x * 256 + threadIdx.x;
        size_t r = idx >> 8;
        int c4 = (int)(idx & 255) * 4;
        const float* src = (r < NB) ? X1 : (r < 2 * NB) ? X2
                         : (r < 3 * NB) ? X3 : X4;
        float4 v = *(const float4*)&src[(r & (NB - 1)) * DD + c4];
        __half hf[4] = { __float2half(v.x), __float2half(v.y),
                         __float2half(v.z), __float2half(v.w) };
        *(uint2*)&Xh[r * DD + c4] = *(uint2*)hf;
    } else if (blockIdx.x < MTOT + 5120) {
        size_t idx = (size_t)(blockIdx.x - MTOT) * 256 + threadIdx.x;
        int sel = (int)(idx >> 18);             // 2^18 float4 per matrix
        size_t off = (idx & ((1u << 18) - 1)) * 4;
        const float* src = (sel == 0) ? Wq : (sel == 1) ? Wkc
                         : (sel == 2) ? Wvc : (sel == 3) ? Woc : Wos;
        __half* dst = (sel == 4) ? Wos16
                    : Wh + (size_t)((sel == 3) ? 4096 : sel * 1024) * DD;
        float4 v = *(const float4*)&src[off];
        __half h[4] = { __float2half(v.x), __float2half(v.y),
                        __float2half(v.z), __float2half(v.w) };
        *(uint2*)&dst[off] = *(uint2*)h;
    } else {
        __shared__ float tile[32][33];
        const int bb = blockIdx.x - (MTOT + 5120);
        const int i0 = (bb & 31) * 32;         // i tile (cols of Wvs)
        const int m0 = (bb >> 5) * 32;         // m tile (rows of Wvs)
        const int tx = threadIdx.x & 31, ty = threadIdx.x >> 5;   // 32 x 8
        #pragma unroll
        for (int r = 0; r < 4; r++)
            tile[ty * 4 + r][tx] = Wvs[(size_t)(m0 + ty * 4 + r) * DD + i0 + tx];
        __syncthreads();
        const int il = threadIdx.x >> 3;       // 0..31
        const int mq = (threadIdx.x & 7) * 4;  // 0,4,..,28
        __half h[4];
        #pragma unroll
        for (int r = 0; r < 4; r++)
            h[r] = __float2half(tile[mq + r][il]);
        *(uint2*)&WvsT16[(size_t)(i0 + il) * DD + m0 + mq] = *(uint2*)h;
    }
}

// --------------------------- bias kernel -----------------------------------
__device__ __forceinline__ float wsum(float v) {
    #pragma unroll
    for (int o = 16; o; o >>= 1) v += __shfl_xor_sync(0xffffffffu, v, o);
    return v;
}

// Merged: b1a[0..1023]=bq, [1024..3071]=0, [3072+o]=Wos[o,:]@bvs + bos[o].
__global__ __launch_bounds__(256) void bias_all_kernel(
    const float* __restrict__ bq,
    const float* __restrict__ Wos, const float* __restrict__ bvs,
    const float* __restrict__ bos, float* __restrict__ b1a)
{
    int idx = blockIdx.x * 256 + threadIdx.x;   // 128 blocks -> 32768 threads
    if (idx < DD)           b1a[idx] = bq[idx];
    else if (idx < 3 * DD)  b1a[idx] = 0.f;

    int o = blockIdx.x * 8 + (threadIdx.x >> 5);
    int lane = threadIdx.x & 31;
    float s = 0.f;
    for (int k = lane; k < DD; k += 32)
        s = fmaf(Wos[(size_t)o * DD + k], bvs[k], s);
    s = wsum(s);
    if (lane == 0) b1a[3 * DD + o] = s + bos[o];
}

// --------------------------- combine ---------------------------------------
// ctx_i = Vc_i + bv_c - sum_j a_ij Vc_j, fp16 in (C1h) / fp16 out (A2h).
__global__ __launch_bounds__(128) void combine_kernel(
    const __half* __restrict__ C1h,   // Q | Kc | Vc | S  (ld 4096)
    const float* __restrict__ bk, const float* __restrict__ bv,
    __half* __restrict__ A2h)
{
    const int b    = blockIdx.x;
    const int h    = threadIdx.x >> 5;
    const int lane = threadIdx.x & 31;
    const int base_d = h * HD + lane;

    float q[4][8], kc[4][8], vc[4][8];
    #pragma unroll
    for (int i = 0; i < 4; i++) {
        size_t row = (size_t)(i * NB + b) * N1A + base_d;
        #pragma unroll
        for (int e = 0; e < 8; e++) {
            q [i][e] = __half2float(C1h[row + e * 32]);
            kc[i][e] = __half2float(C1h[row + 1024 + e * 32]);
            vc[i][e] = __half2float(C1h[row + 2048 + e * 32]);
        }
    }
    float bke[8], bve[8];
    #pragma unroll
    for (int e = 0; e < 8; e++) {
        bke[e] = bk[base_d + e * 32];
        bve[e] = bv[base_d + e * 32];
    }

    float a[4][4];
    #pragma unroll
    for (int i = 0; i < 4; i++) {
        float s[4];
        #pragma unroll
        for (int j = 0; j < 4; j++) {
            float p = 0.f;
            #pragma unroll
            for (int e = 0; e < 8; e++)
                p = fmaf(q[i][e], kc[i][e] - kc[j][e] + bke[e], p);
            s[j] = wsum(p) * (1.f / 16.f);
        }
        float m = -1e30f;
        #pragma unroll
        for (int j = 0; j < 4; j++) if (j != i && s[j] > m) m = s[j];
        float den = 0.f;
        #pragma unroll
        for (int j = 0; j < 4; j++) {
            float ex = (j == i) ? 0.f : __expf(s[j] - m);
            a[i][j] = ex; den += ex;
        }
        float inv = 1.f / den;
        #pragma unroll
        for (int j = 0; j < 4; j++) a[i][j] *= inv;
    }

    #pragma unroll
    for (int i = 0; i < 4; i++) {
        __half* row = A2h + (size_t)(i * NB + b) * DD;
        #pragma unroll
        for (int e = 0; e < 8; e++) {
            float c = vc[i][e] + bve[e];
            #pragma unroll
            for (int j = 0; j < 4; j++)
                c = fmaf(-a[i][j], vc[j][e], c);
            row[base_d + e * 32] = __float2half(c);
        }
    }
}

// ---------------------------------------------------------------------------
extern "C" void kernel_launch(void* const* d_in, const int* in_sizes, int n_in,
                              void* d_out, int out_size)
{
    const float* X1   = (const float*)d_in[0];
    const float* X2   = (const float*)d_in[1];
    const float* X3   = (const float*)d_in[2];
    const float* X4   = (const float*)d_in[3];
    const float* Wq   = (const float*)d_in[4];
    const float* bq   = (const float*)d_in[5];
    const float* Wv_s = (const float*)d_in[8];
    const float* bv_s = (const float*)d_in[9];
    const float* Wo_s = (const float*)d_in[10];
    const float* bo_s = (const float*)d_in[11];
    const float* Wk_c = (const float*)d_in[12];
    const float* bk_c = (const float*)d_in[13];
    const float* Wv_c = (const float*)d_in[14];
    const float* bv_c = (const float*)d_in[15];
    const float* Wo_c = (const float*)d_in[16];
    const float* bo_c = (const float*)d_in[17];
    const float* Wc   = (const float*)d_in[18];
    const float* bc   = (const float*)d_in[19];

    float* out    = (float*)d_out;
    float* logits = out + (size_t)MTOT * DD;

    __half *gXh, *gWh, *gC1h, *gA2h, *gWos16, *gWvsT16;
    float *gPlog, *gb1a, *gzero;
    cudaGetSymbolAddress((void**)&gXh,     g_Xh);
    cudaGetSymbolAddress((void**)&gWh,     g_Wh);
    cudaGetSymbolAddress((void**)&gC1h,    g_C1h);
    cudaGetSymbolAddress((void**)&gA2h,    g_A2h);
    cudaGetSymbolAddress((void**)&gWos16,  g_Wos16);
    cudaGetSymbolAddress((void**)&gWvsT16, g_WvsT16);
    cudaGetSymbolAddress((void**)&gPlog,   g_plog);
    cudaGetSymbolAddress((void**)&gb1a,    g_b1a);
    cudaGetSymbolAddress((void**)&gzero,   g_zero);

    cudaFuncSetAttribute((const void*)gemm1_kernel,
                         cudaFuncAttributeMaxDynamicSharedMemorySize, GEMM_SMEM);
    cudaFuncSetAttribute((const void*)gemm2_kernel,
                         cudaFuncAttributeMaxDynamicSharedMemorySize, GEMM_SMEM);

    // prep: all fp16 casts (X, 5 weight matrices, Wv_s^T) in one launch
    cast_all_kernel<<<MTOT + 6144, 256>>>(
        X1, X2, X3, X4, Wq, Wk_c, Wv_c, Wo_c, Wo_s, Wv_s,
        gXh, gWh, gWos16, gWvsT16);

    // Weff = Wo_s@Wv_s (fp16 in, fp32 accum, fp16 out straight into Wh S block)
    gemm1_kernel<<<dim3(4, 8), 256, GEMM_SMEM>>>(
        (const uint16_t*)gWos16, (const uint16_t*)gWvsT16, gzero,
        gWh + (size_t)3072 * DD, DD, DD);

    bias_all_kernel<<<128, 256>>>(bq, Wo_s, bv_s, bo_s, gb1a);

    // GEMM1 (fp16 in/out): C1h[32768,4096] = Xh @ [Wq;Wkc;Wvc;Weff]^T + b1a
    gemm1_kernel<<<dim3(N1A / 256, MTOT / 128), 256, GEMM_SMEM>>>(
        (const uint16_t*)gXh, (const uint16_t*)gWh, gb1a, gC1h, N1A, DD);

    // attention combine -> ctx fp16 into A2h
    combine_kernel<<<NB, 128>>>(gC1h, bk_c, bv_c, gA2h);

    // GEMM2 (fp16 in, fp32 out): d = ctx @ Wo_c^T + bo_c + S, with fused
    // per-column-block logits partials (deterministic).
    gemm2_kernel<<<dim3(DD / 256, MTOT / 128), 256, GEMM_SMEM>>>(
        (const uint16_t*)gA2h, (const uint16_t*)(gWh + (size_t)4096 * DD),
        bo_c, gC1h + 3072, N1A, out, DD, DD, Wc, gPlog);

    // logits = sum of 4 column-block partials (fixed order) + bc
    reduce_logits_kernel<<<MTOT * 4 / 256, 256>>>(gPlog, bc, logits);
}